// round 3
// baseline (speedup 1.0000x reference)
#include <cuda_runtime.h>
#include <cuda_bf16.h>
#include <cstdint>

#define NN 100000
#define EO 600000
#define EL 1200000
#define HD 128
#define OD 64
#define SA 136   // smem row stride (bf16) -> conflict-free ldmatrix

// ---------------- scratch -----------------------------------------------
static __device__ float g_nodeA[(size_t)NN * HD];
static __device__ float g_nodeC[(size_t)NN * HD];
static __device__ float g_edgeB[(size_t)EO * HD];
static __device__ __nv_bfloat16 g_W1h[5][HD * HD], g_W1l[5][HD * HD];
static __device__ __nv_bfloat16 g_W2h[5][HD * HD], g_W2l[5][HD * HD];
static __device__ __nv_bfloat16 g_Woh[HD * OD], g_Wol[HD * OD];
static __device__ float g_bfb[5][HD];
// CSR scratch
static __device__ int g_deg[EO];
static __device__ int g_ex[EO];
static __device__ int g_bsum[1024];
static __device__ int g_rpN[NN + 1], g_adjN[EO], g_curN[NN];
static __device__ int g_rpE[EO + 1], g_adjE[EL], g_curE[EO];

// ---------------- PTX helpers --------------------------------------------
__device__ __forceinline__ void ldsm4(uint32_t* r, const void* p) {
    uint32_t a = (uint32_t)__cvta_generic_to_shared(p);
    asm volatile("ldmatrix.sync.aligned.m8n8.x4.shared.b16 {%0,%1,%2,%3}, [%4];"
                 : "=r"(r[0]), "=r"(r[1]), "=r"(r[2]), "=r"(r[3]) : "r"(a));
}
__device__ __forceinline__ void mma_bf16(float* d, const uint32_t* a,
                                         uint32_t b0, uint32_t b1) {
    asm volatile(
        "mma.sync.aligned.m16n8k16.row.col.f32.bf16.bf16.f32 "
        "{%0,%1,%2,%3}, {%4,%5,%6,%7}, {%8,%9}, {%0,%1,%2,%3};"
        : "+f"(d[0]), "+f"(d[1]), "+f"(d[2]), "+f"(d[3])
        : "r"(a[0]), "r"(a[1]), "r"(a[2]), "r"(a[3]), "r"(b0), "r"(b1));
}
__device__ __forceinline__ void split_store2(float x0, float x1,
                                             __nv_bfloat16* ph,
                                             __nv_bfloat16* pl) {
    __nv_bfloat16 h0 = __float2bfloat16(x0);
    __nv_bfloat16 h1 = __float2bfloat16(x1);
    __nv_bfloat16 l0 = __float2bfloat16(x0 - __bfloat162float(h0));
    __nv_bfloat16 l1 = __float2bfloat16(x1 - __bfloat162float(h1));
    *(__nv_bfloat162*)ph = __halves2bfloat162(h0, h1);
    *(__nv_bfloat162*)pl = __halves2bfloat162(l0, l1);
}

__device__ __forceinline__ void gemm_pass(
    const __nv_bfloat16* As_h, const __nv_bfloat16* As_l,
    const __nv_bfloat16* Wh, const __nv_bfloat16* Wl,
    int rowBase, int colBase, int lrow, int lkoff, float (&acc)[4][4][4]) {
#pragma unroll
    for (int mi = 0; mi < 4; ++mi)
#pragma unroll
        for (int ni = 0; ni < 4; ++ni)
#pragma unroll
            for (int q = 0; q < 4; ++q) acc[mi][ni][q] = 0.f;
#pragma unroll
    for (int ks = 0; ks < 8; ++ks) {
        const int k0 = ks * 16 + lkoff;
        uint32_t ah[4][4], al[4][4];
#pragma unroll
        for (int mi = 0; mi < 4; ++mi) {
            const int base = (rowBase + mi * 16 + lrow) * SA + k0;
            ldsm4(ah[mi], As_h + base);
            ldsm4(al[mi], As_l + base);
        }
        uint32_t bh[2][4], bl[2][4];
#pragma unroll
        for (int nj = 0; nj < 2; ++nj) {
            const int base = (colBase + nj * 16 + lrow) * SA + k0;
            ldsm4(bh[nj], Wh + base);
            ldsm4(bl[nj], Wl + base);
        }
#pragma unroll
        for (int mi = 0; mi < 4; ++mi)
#pragma unroll
            for (int ni = 0; ni < 4; ++ni) {
                const int nj = ni >> 1, hh = ni & 1;
                mma_bf16(acc[mi][ni], ah[mi], bh[nj][hh], bh[nj][hh + 2]);
                mma_bf16(acc[mi][ni], ah[mi], bl[nj][hh], bl[nj][hh + 2]);
                mma_bf16(acc[mi][ni], al[mi], bh[nj][hh], bh[nj][hh + 2]);
            }
    }
}

__device__ __forceinline__ void load_w_smem(const __nv_bfloat16* g,
                                            __nv_bfloat16* s, int tid) {
#pragma unroll
    for (int i = tid; i < 2048; i += 256) {
        int r = i >> 4, c = i & 15;
        *(uint4*)(s + r * SA + c * 8) = ((const uint4*)g)[i];
    }
}

// ---------------- fused GIN layer ----------------------------------------
// MODE: 0 = no aggregation (plain MLP), 1 = CSR gather (x + sum nbrs),
//       2 = PAIR gather on line graph (h = X[ep0]+X[ep1], + sum nbr h)
// HEAD: run a third GEMM vs Wo[128,64] and write [M,64] out instead of C.
template <int MODE, bool RELU2, bool HEAD>
__global__ __launch_bounds__(256, 1) void fused_gin(
    const float* __restrict__ X,
    const int* __restrict__ row_ptr, const int* __restrict__ adj,
    const int* __restrict__ ep,
    const __nv_bfloat16* __restrict__ W1h, const __nv_bfloat16* __restrict__ W1l,
    const __nv_bfloat16* __restrict__ W2h, const __nv_bfloat16* __restrict__ W2l,
    const __nv_bfloat16* __restrict__ Woh, const __nv_bfloat16* __restrict__ Wol,
    const float* __restrict__ b1, const float* __restrict__ b2,
    const float* __restrict__ b3, float* __restrict__ C, int M) {
    extern __shared__ char smem[];
    __nv_bfloat16* As_h = (__nv_bfloat16*)smem;
    __nv_bfloat16* As_l = As_h + 128 * SA;
    __nv_bfloat16* Wah = As_l + 128 * SA;
    __nv_bfloat16* Wal = Wah + 128 * SA;
    __nv_bfloat16* Wbh = Wal + 128 * SA;
    __nv_bfloat16* Wbl = Wbh + 128 * SA;

    const int tid = threadIdx.x;
    const int lane = tid & 31, wid = tid >> 5;
    const int m0 = blockIdx.x * 128;

    load_w_smem(W1h, Wah, tid);
    load_w_smem(W1l, Wal, tid);
    load_w_smem(W2h, Wbh, tid);
    load_w_smem(W2l, Wbl, tid);

    // ---- phase A: build A tile (gather + aggregate in f32, split bf16) ---
    for (int rr = 0; rr < 16; ++rr) {
        const int r = (wid << 4) + rr;
        const int row = m0 + r;
        float4 acc = make_float4(0.f, 0.f, 0.f, 0.f);
        if (row < M) {
            if (MODE == 2) {
                const int p0 = ep[2 * row], p1 = ep[2 * row + 1];
                float4 a = ((const float4*)(X + (size_t)p0 * HD))[lane];
                float4 b = ((const float4*)(X + (size_t)p1 * HD))[lane];
                acc.x = a.x + b.x; acc.y = a.y + b.y;
                acc.z = a.z + b.z; acc.w = a.w + b.w;
                const int s = row_ptr[row], e = row_ptr[row + 1];
                for (int j = s; j < e; ++j) {
                    const int nb = adj[j];
                    const int q0 = ep[2 * nb], q1 = ep[2 * nb + 1];
                    float4 u = ((const float4*)(X + (size_t)q0 * HD))[lane];
                    float4 w = ((const float4*)(X + (size_t)q1 * HD))[lane];
                    acc.x += u.x + w.x; acc.y += u.y + w.y;
                    acc.z += u.z + w.z; acc.w += u.w + w.w;
                }
            } else {
                acc = ((const float4*)(X + (size_t)row * HD))[lane];
                if (MODE == 1) {
                    const int s = row_ptr[row], e = row_ptr[row + 1];
                    for (int j = s; j < e; ++j) {
                        const int nb = adj[j];
                        float4 u = ((const float4*)(X + (size_t)nb * HD))[lane];
                        acc.x += u.x; acc.y += u.y; acc.z += u.z; acc.w += u.w;
                    }
                }
            }
        }
        __nv_bfloat16* ph = As_h + r * SA + lane * 4;
        __nv_bfloat16* pl = As_l + r * SA + lane * 4;
        split_store2(acc.x, acc.y, ph, pl);
        split_store2(acc.z, acc.w, ph + 2, pl + 2);
    }
    __syncthreads();

    const int rowBase = (wid >> 2) * 64, colBase = (wid & 3) * 32;
    const int lrow = lane & 15, lkoff = (lane >> 4) * 8;
    const int cq = (lane & 3) * 2, rq = lane >> 2;

    float acc[4][4][4];
    gemm_pass(As_h, As_l, Wah, Wal, rowBase, colBase, lrow, lkoff, acc);
    __syncthreads();   // As reads done; Wa reads done

    if (HEAD) {        // stage Wo into the now-dead Wa region
#pragma unroll
        for (int i = tid; i < 1024; i += 256) {
            int r = i >> 4, c = i & 15;
            *(uint4*)(Wah + r * SA + c * 8) = ((const uint4*)Woh)[i];
            *(uint4*)(Wal + r * SA + c * 8) = ((const uint4*)Wol)[i];
        }
    }
    // epilogue 1: h1 = relu(acc + b1) -> As
#pragma unroll
    for (int mi = 0; mi < 4; ++mi)
#pragma unroll
        for (int ni = 0; ni < 4; ++ni) {
            const int col = colBase + ni * 8 + cq;
            const float bb0 = b1[col], bb1 = b1[col + 1];
            const int r0 = rowBase + mi * 16 + rq, r1 = r0 + 8;
            float v00 = fmaxf(acc[mi][ni][0] + bb0, 0.f);
            float v01 = fmaxf(acc[mi][ni][1] + bb1, 0.f);
            float v10 = fmaxf(acc[mi][ni][2] + bb0, 0.f);
            float v11 = fmaxf(acc[mi][ni][3] + bb1, 0.f);
            split_store2(v00, v01, As_h + r0 * SA + col, As_l + r0 * SA + col);
            split_store2(v10, v11, As_h + r1 * SA + col, As_l + r1 * SA + col);
        }
    __syncthreads();

    gemm_pass(As_h, As_l, Wbh, Wbl, rowBase, colBase, lrow, lkoff, acc);

    if (!HEAD) {
#pragma unroll
        for (int mi = 0; mi < 4; ++mi)
#pragma unroll
            for (int ni = 0; ni < 4; ++ni) {
                const int col = colBase + ni * 8 + cq;
                const float bb0 = b2[col], bb1 = b2[col + 1];
                const int r0 = m0 + rowBase + mi * 16 + rq, r1 = r0 + 8;
                float v00 = acc[mi][ni][0] + bb0, v01 = acc[mi][ni][1] + bb1;
                float v10 = acc[mi][ni][2] + bb0, v11 = acc[mi][ni][3] + bb1;
                if (RELU2) {
                    v00 = fmaxf(v00, 0.f); v01 = fmaxf(v01, 0.f);
                    v10 = fmaxf(v10, 0.f); v11 = fmaxf(v11, 0.f);
                }
                if (r0 < M) *(float2*)(C + (size_t)r0 * HD + col) = make_float2(v00, v01);
                if (r1 < M) *(float2*)(C + (size_t)r1 * HD + col) = make_float2(v10, v11);
            }
        return;
    }

    // HEAD: h2 = relu(acc + b2) -> As, then pass 3 vs Wo, write [M,64]
    __syncthreads();   // As reads (pass2) done
#pragma unroll
    for (int mi = 0; mi < 4; ++mi)
#pragma unroll
        for (int ni = 0; ni < 4; ++ni) {
            const int col = colBase + ni * 8 + cq;
            const float bb0 = b2[col], bb1 = b2[col + 1];
            const int r0 = rowBase + mi * 16 + rq, r1 = r0 + 8;
            float v00 = fmaxf(acc[mi][ni][0] + bb0, 0.f);
            float v01 = fmaxf(acc[mi][ni][1] + bb1, 0.f);
            float v10 = fmaxf(acc[mi][ni][2] + bb0, 0.f);
            float v11 = fmaxf(acc[mi][ni][3] + bb1, 0.f);
            split_store2(v00, v01, As_h + r0 * SA + col, As_l + r0 * SA + col);
            split_store2(v10, v11, As_h + r1 * SA + col, As_l + r1 * SA + col);
        }
    __syncthreads();

    const int colB3 = (wid & 3) * 16;
    float acc3[4][2][4];
#pragma unroll
    for (int mi = 0; mi < 4; ++mi)
#pragma unroll
        for (int ni = 0; ni < 2; ++ni)
#pragma unroll
            for (int q = 0; q < 4; ++q) acc3[mi][ni][q] = 0.f;
#pragma unroll
    for (int ks = 0; ks < 8; ++ks) {
        const int k0 = ks * 16 + lkoff;
        uint32_t ah[4][4], al[4][4];
#pragma unroll
        for (int mi = 0; mi < 4; ++mi) {
            const int base = (rowBase + mi * 16 + lrow) * SA + k0;
            ldsm4(ah[mi], As_h + base);
            ldsm4(al[mi], As_l + base);
        }
        uint32_t bh[4], bl[4];
        {
            const int base = (colB3 + lrow) * SA + k0;
            ldsm4(bh, Wah + base);
            ldsm4(bl, Wal + base);
        }
#pragma unroll
        for (int mi = 0; mi < 4; ++mi)
#pragma unroll
            for (int ni = 0; ni < 2; ++ni) {
                mma_bf16(acc3[mi][ni], ah[mi], bh[ni], bh[ni + 2]);
                mma_bf16(acc3[mi][ni], ah[mi], bl[ni], bl[ni + 2]);
                mma_bf16(acc3[mi][ni], al[mi], bh[ni], bh[ni + 2]);
            }
    }
#pragma unroll
    for (int mi = 0; mi < 4; ++mi)
#pragma unroll
        for (int ni = 0; ni < 2; ++ni) {
            const int col = colB3 + ni * 8 + cq;
            const float bb0 = b3[col], bb1 = b3[col + 1];
            const int r0 = m0 + rowBase + mi * 16 + rq, r1 = r0 + 8;
            if (r0 < M)
                *(float2*)(C + (size_t)r0 * OD + col) =
                    make_float2(acc3[mi][ni][0] + bb0, acc3[mi][ni][1] + bb1);
            if (r1 < M)
                *(float2*)(C + (size_t)r1 * OD + col) =
                    make_float2(acc3[mi][ni][2] + bb0, acc3[mi][ni][3] + bb1);
        }
}

// ---------------- weight prep (single kernel) ------------------------------
struct PrepArgs {
    const float *W1[5], *b1[5], *g[5], *bb[5], *m[5], *v[5], *W2[5], *Wo;
    __nv_bfloat16 *W1h[5], *W1l[5], *W2h[5], *W2l[5], *Woh, *Wol;
    float* bf[5];
};

__global__ void prep_weights(PrepArgs a) {
    const int blk = blockIdx.x, tid = threadIdx.x;
    if (blk < 320) {                       // fold BN into W1 (5 jobs)
        const int j = blk >> 6;
        const int idx = ((blk & 63) << 8) + tid;
        const int k = idx >> 7, n = idx & 127;
        float s = a.g[j][n] * rsqrtf(a.v[j][n] + 1e-5f);
        float val = a.W1[j][idx] * s;
        __nv_bfloat16 h = __float2bfloat16(val);
        a.W1h[j][n * 128 + k] = h;
        a.W1l[j][n * 128 + k] = __float2bfloat16(val - __bfloat162float(h));
        if (idx < 128)
            a.bf[j][idx] = a.b1[j][idx] * s + a.bb[j][idx] - a.m[j][idx] * s;
    } else if (blk < 640) {                // convert W2 (5 jobs)
        const int j = (blk - 320) >> 6;
        const int idx = (((blk - 320) & 63) << 8) + tid;
        const int k = idx >> 7, n = idx & 127;
        float val = a.W2[j][idx];
        __nv_bfloat16 h = __float2bfloat16(val);
        a.W2h[j][n * 128 + k] = h;
        a.W2l[j][n * 128 + k] = __float2bfloat16(val - __bfloat162float(h));
    } else {                               // convert out_W [128,64]
        const int idx = ((blk - 640) << 8) + tid;  // 8192
        const int k = idx >> 6, n = idx & 63;
        float val = a.Wo[idx];
        __nv_bfloat16 h = __float2bfloat16(val);
        a.Woh[n * 128 + k] = h;
        a.Wol[n * 128 + k] = __float2bfloat16(val - __bfloat162float(h));
    }
}

// ---------------- CSR build -------------------------------------------------
__global__ void count_deg(const int* __restrict__ dst, int E, int* __restrict__ deg) {
    int e = blockIdx.x * 256 + threadIdx.x;
    if (e < E) atomicAdd(&deg[dst[e]], 1);
}

__global__ void scan1(const int* __restrict__ deg, int* __restrict__ ex,
                      int* __restrict__ bsum, int n) {
    __shared__ int wsum[32];
    const int t = threadIdx.x;
    const int base = blockIdx.x * 4096 + t * 4;
    int v[4], s = 0;
#pragma unroll
    for (int i = 0; i < 4; ++i) {
        int idx = base + i;
        v[i] = idx < n ? deg[idx] : 0;
        s += v[i];
    }
    const int lane = t & 31, w = t >> 5;
    int ps = s;
#pragma unroll
    for (int o = 1; o < 32; o <<= 1) {
        int y = __shfl_up_sync(~0u, ps, o);
        if (lane >= o) ps += y;
    }
    if (lane == 31) wsum[w] = ps;
    __syncthreads();
    if (w == 0) {
        int x = wsum[lane];
#pragma unroll
        for (int o = 1; o < 32; o <<= 1) {
            int y = __shfl_up_sync(~0u, x, o);
            if (lane >= o) x += y;
        }
        wsum[lane] = x;
    }
    __syncthreads();
    const int warpoff = w ? wsum[w - 1] : 0;
    int run = warpoff + ps - s;
#pragma unroll
    for (int i = 0; i < 4; ++i) {
        int idx = base + i;
        if (idx < n) ex[idx] = run;
        run += v[i];
    }
    if (t == 0) bsum[blockIdx.x] = wsum[31];
}

__global__ void scan2(int* __restrict__ bsum, int nb) {
    __shared__ int sm_[1024];
    const int t = threadIdx.x;
    int v = (t < nb) ? bsum[t] : 0;
    sm_[t] = v;
    __syncthreads();
    for (int o = 1; o < 1024; o <<= 1) {
        int y = (t >= o) ? sm_[t - o] : 0;
        __syncthreads();
        sm_[t] += y;
        __syncthreads();
    }
    if (t < nb) bsum[t] = sm_[t] - v;  // exclusive
}

__global__ void scan3(const int* __restrict__ ex, const int* __restrict__ boff,
                      int* __restrict__ rp, int* __restrict__ cur, int n, int E) {
    int i = blockIdx.x * 1024 + threadIdx.x;
    if (i < n) {
        int vv = ex[i] + boff[i >> 12];
        rp[i] = vv;
        cur[i] = vv;
    } else if (i == n) {
        rp[n] = E;
    }
}

__global__ void fill_csr(const int* __restrict__ src, const int* __restrict__ dst,
                         int E, int* __restrict__ cur, int* __restrict__ adj) {
    int e = blockIdx.x * 256 + threadIdx.x;
    if (e < E) {
        int p = atomicAdd(&cur[dst[e]], 1);
        adj[p] = src[e];
    }
}

// ----------------------------------------------------------------------------
extern "C" void kernel_launch(void* const* d_in, const int* in_sizes, int n_in,
                              void* d_out, int out_size) {
    const int*   edge_index = (const int*)d_in[0];
    const float* x_orig     = (const float*)d_in[1];
    const int*   ei_orig    = (const int*)d_in[2];
    const int*   edge_pairs = (const int*)d_in[3];
    const float* init_W1 = (const float*)d_in[4];
    const float* init_b1 = (const float*)d_in[5];
    const float* init_g  = (const float*)d_in[6];
    const float* init_bb = (const float*)d_in[7];
    const float* init_m  = (const float*)d_in[8];
    const float* init_v  = (const float*)d_in[9];
    const float* init_W2 = (const float*)d_in[10];
    const float* init_b2 = (const float*)d_in[11];
    const float* gin_W1  = (const float*)d_in[12];
    const float* gin_b1  = (const float*)d_in[13];
    const float* gin_g   = (const float*)d_in[14];
    const float* gin_bb  = (const float*)d_in[15];
    const float* gin_m   = (const float*)d_in[16];
    const float* gin_v   = (const float*)d_in[17];
    const float* gin_W2  = (const float*)d_in[18];
    const float* gin_b2  = (const float*)d_in[19];
    const float* mlp_W1  = (const float*)d_in[20];
    const float* mlp_b1  = (const float*)d_in[21];
    const float* mlp_g   = (const float*)d_in[22];
    const float* mlp_bb  = (const float*)d_in[23];
    const float* mlp_m   = (const float*)d_in[24];
    const float* mlp_v   = (const float*)d_in[25];
    const float* mlp_W2  = (const float*)d_in[26];
    const float* mlp_b2  = (const float*)d_in[27];
    const float* out_W   = (const float*)d_in[28];
    const float* out_b   = (const float*)d_in[29];
    float* out = (float*)d_out;

    float *nodeA, *nodeC, *edgeB;
    __nv_bfloat16 *W1h, *W1l, *W2h, *W2l, *Woh, *Wol;
    float* bfb;
    int *deg, *ex, *bsum, *rpN, *adjN, *curN, *rpE, *adjE, *curE;
    cudaGetSymbolAddress((void**)&nodeA, g_nodeA);
    cudaGetSymbolAddress((void**)&nodeC, g_nodeC);
    cudaGetSymbolAddress((void**)&edgeB, g_edgeB);
    cudaGetSymbolAddress((void**)&W1h, g_W1h);
    cudaGetSymbolAddress((void**)&W1l, g_W1l);
    cudaGetSymbolAddress((void**)&W2h, g_W2h);
    cudaGetSymbolAddress((void**)&W2l, g_W2l);
    cudaGetSymbolAddress((void**)&Woh, g_Woh);
    cudaGetSymbolAddress((void**)&Wol, g_Wol);
    cudaGetSymbolAddress((void**)&bfb, g_bfb);
    cudaGetSymbolAddress((void**)&deg, g_deg);
    cudaGetSymbolAddress((void**)&ex, g_ex);
    cudaGetSymbolAddress((void**)&bsum, g_bsum);
    cudaGetSymbolAddress((void**)&rpN, g_rpN);
    cudaGetSymbolAddress((void**)&adjN, g_adjN);
    cudaGetSymbolAddress((void**)&curN, g_curN);
    cudaGetSymbolAddress((void**)&rpE, g_rpE);
    cudaGetSymbolAddress((void**)&adjE, g_adjE);
    cudaGetSymbolAddress((void**)&curE, g_curE);

    // ---- weight prep (one kernel) -----------------------------------------
    PrepArgs pa;
    const float* W1s[5]  = {init_W1, init_W1 + HD * HD, mlp_W1, gin_W1, gin_W1 + HD * HD};
    const float* b1s[5]  = {init_b1, init_b1 + HD, mlp_b1, gin_b1, gin_b1 + HD};
    const float* gs[5]   = {init_g, init_g + HD, mlp_g, gin_g, gin_g + HD};
    const float* bbs[5]  = {init_bb, init_bb + HD, mlp_bb, gin_bb, gin_bb + HD};
    const float* ms[5]   = {init_m, init_m + HD, mlp_m, gin_m, gin_m + HD};
    const float* vs[5]   = {init_v, init_v + HD, mlp_v, gin_v, gin_v + HD};
    const float* W2s[5]  = {init_W2, init_W2 + HD * HD, mlp_W2, gin_W2, gin_W2 + HD * HD};
    for (int j = 0; j < 5; ++j) {
        pa.W1[j] = W1s[j]; pa.b1[j] = b1s[j]; pa.g[j] = gs[j]; pa.bb[j] = bbs[j];
        pa.m[j] = ms[j]; pa.v[j] = vs[j]; pa.W2[j] = W2s[j];
        pa.W1h[j] = W1h + (size_t)j * HD * HD; pa.W1l[j] = W1l + (size_t)j * HD * HD;
        pa.W2h[j] = W2h + (size_t)j * HD * HD; pa.W2l[j] = W2l + (size_t)j * HD * HD;
        pa.bf[j] = bfb + j * HD;
    }
    pa.Wo = out_W; pa.Woh = Woh; pa.Wol = Wol;
    prep_weights<<<672, 256>>>(pa);

    // ---- CSR build: node graph (dst = ei_orig[1]) --------------------------
    cudaMemsetAsync(deg, 0, NN * sizeof(int));
    count_deg<<<(EO + 255) / 256, 256>>>(ei_orig + EO, EO, deg);
    scan1<<<(NN + 4095) / 4096, 1024>>>(deg, ex, bsum, NN);
    scan2<<<1, 1024>>>(bsum, (NN + 4095) / 4096);
    scan3<<<(NN + 1024) / 1024, 1024>>>(ex, bsum, rpN, curN, NN, EO);
    fill_csr<<<(EO + 255) / 256, 256>>>(ei_orig, ei_orig + EO, EO, curN, adjN);

    // ---- CSR build: line graph (dst = edge_index[1]) ------------------------
    cudaMemsetAsync(deg, 0, EO * sizeof(int));
    count_deg<<<(EL + 255) / 256, 256>>>(edge_index + EL, EL, deg);
    scan1<<<(EO + 4095) / 4096, 1024>>>(deg, ex, bsum, EO);
    scan2<<<1, 1024>>>(bsum, (EO + 4095) / 4096);
    scan3<<<(EO + 1024) / 1024, 1024>>>(ex, bsum, rpE, curE, EO, EL);
    fill_csr<<<(EL + 255) / 256, 256>>>(edge_index, edge_index + EL, EL, curE, adjE);

    // ---- main pipeline -------------------------------------------------------
    const int SMEM_F = 6 * 128 * SA * 2;  // 208896 B
    cudaFuncSetAttribute(fused_gin<1, true, false>,
                         cudaFuncAttributeMaxDynamicSharedMemorySize, SMEM_F);
    cudaFuncSetAttribute(fused_gin<0, false, false>,
                         cudaFuncAttributeMaxDynamicSharedMemorySize, SMEM_F);
    cudaFuncSetAttribute(fused_gin<2, true, false>,
                         cudaFuncAttributeMaxDynamicSharedMemorySize, SMEM_F);
    cudaFuncSetAttribute(fused_gin<1, true, true>,
                         cudaFuncAttributeMaxDynamicSharedMemorySize, SMEM_F);

    const int gridN = (NN + 127) / 128;
    const int gridE = (EO + 127) / 128;
    const size_t WSZ = (size_t)HD * HD;

    // init layer 0: x_orig -> nodeA
    fused_gin<1, true, false><<<gridN, 256, SMEM_F>>>(
        x_orig, rpN, adjN, nullptr,
        W1h, W1l, W2h, W2l, nullptr, nullptr,
        bfb, init_b2, nullptr, nodeA, NN);
    // init layer 1: nodeA -> nodeC
    fused_gin<1, true, false><<<gridN, 256, SMEM_F>>>(
        nodeA, rpN, adjN, nullptr,
        W1h + WSZ, W1l + WSZ, W2h + WSZ, W2l + WSZ, nullptr, nullptr,
        bfb + HD, init_b2 + HD, nullptr, nodeC, NN);
    // mlp: nodeC -> nodeA
    fused_gin<0, false, false><<<gridN, 256, SMEM_F>>>(
        nodeC, nullptr, nullptr, nullptr,
        W1h + 2 * WSZ, W1l + 2 * WSZ, W2h + 2 * WSZ, W2l + 2 * WSZ, nullptr, nullptr,
        bfb + 2 * HD, mlp_b2, nullptr, nodeA, NN);
    // edge layer 0 (pair-lift fused): nodeA + ep -> edgeB
    fused_gin<2, true, false><<<gridE, 256, SMEM_F>>>(
        nodeA, rpE, adjE, edge_pairs,
        W1h + 3 * WSZ, W1l + 3 * WSZ, W2h + 3 * WSZ, W2l + 3 * WSZ, nullptr, nullptr,
        bfb + 3 * HD, gin_b2, nullptr, edgeB, EO);
    // edge layer 1 + head: edgeB -> out [EO,64]
    fused_gin<1, true, true><<<gridE, 256, SMEM_F>>>(
        edgeB, rpE, adjE, nullptr,
        W1h + 4 * WSZ, W1l + 4 * WSZ, W2h + 4 * WSZ, W2l + 4 * WSZ, Woh, Wol,
        bfb + 4 * HD, gin_b2 + HD, out_b, out, EO);
}

// round 4
// speedup vs baseline: 1.2726x; 1.2726x over previous
#include <cuda_runtime.h>
#include <cuda_bf16.h>
#include <cstdint>

#define NN 100000
#define EO 600000
#define EL 1200000
#define HD 128
#define OD 64
#define SA 136   // smem row stride (bf16) -> conflict-free ldmatrix

// ---------------- scratch (device globals) ---------------------------------
static __device__ float g_nodeA[(size_t)NN * HD];
static __device__ float g_nodeB[(size_t)NN * HD];
static __device__ float g_nodeC[(size_t)NN * HD];
static __device__ float g_nodeD[(size_t)NN * HD];
static __device__ float g_edgeA[(size_t)EO * HD];
static __device__ float g_edgeB[(size_t)EO * HD];
static __device__ float g_edgeC[(size_t)EO * HD];
static __device__ __nv_bfloat16 g_W1h[5][HD * HD], g_W1l[5][HD * HD];
static __device__ __nv_bfloat16 g_W2h[5][HD * HD], g_W2l[5][HD * HD];
static __device__ __nv_bfloat16 g_Woh[HD * OD], g_Wol[HD * OD];
static __device__ float g_bfb[5][HD];

// ---------------- PTX helpers ----------------------------------------------
__device__ __forceinline__ void ldsm4(uint32_t* r, const void* p) {
    uint32_t a = (uint32_t)__cvta_generic_to_shared(p);
    asm volatile("ldmatrix.sync.aligned.m8n8.x4.shared.b16 {%0,%1,%2,%3}, [%4];"
                 : "=r"(r[0]), "=r"(r[1]), "=r"(r[2]), "=r"(r[3]) : "r"(a));
}
__device__ __forceinline__ void mma_bf16(float* d, const uint32_t* a,
                                         uint32_t b0, uint32_t b1) {
    asm volatile(
        "mma.sync.aligned.m16n8k16.row.col.f32.bf16.bf16.f32 "
        "{%0,%1,%2,%3}, {%4,%5,%6,%7}, {%8,%9}, {%0,%1,%2,%3};"
        : "+f"(d[0]), "+f"(d[1]), "+f"(d[2]), "+f"(d[3])
        : "r"(a[0]), "r"(a[1]), "r"(a[2]), "r"(a[3]), "r"(b0), "r"(b1));
}
__device__ __forceinline__ void split_store2(float x0, float x1,
                                             __nv_bfloat16* ph,
                                             __nv_bfloat16* pl) {
    __nv_bfloat16 h0 = __float2bfloat16(x0);
    __nv_bfloat16 h1 = __float2bfloat16(x1);
    __nv_bfloat16 l0 = __float2bfloat16(x0 - __bfloat162float(h0));
    __nv_bfloat16 l1 = __float2bfloat16(x1 - __bfloat162float(h1));
    *(__nv_bfloat162*)ph = __halves2bfloat162(h0, h1);
    *(__nv_bfloat162*)pl = __halves2bfloat162(l0, l1);
}

// one 128x128 @ 128x128 pass; 16 warps, warp tile 32(M) x 32(N)
__device__ __forceinline__ void gemm_pass16(
    const __nv_bfloat16* As_h, const __nv_bfloat16* As_l,
    const __nv_bfloat16* Wh, const __nv_bfloat16* Wl,
    int rowBase, int colBase, int lrow, int lkoff, float (&acc)[2][4][4]) {
#pragma unroll
    for (int mi = 0; mi < 2; ++mi)
#pragma unroll
        for (int ni = 0; ni < 4; ++ni)
#pragma unroll
            for (int q = 0; q < 4; ++q) acc[mi][ni][q] = 0.f;
#pragma unroll
    for (int ks = 0; ks < 8; ++ks) {
        const int k0 = ks * 16 + lkoff;
        uint32_t ah[2][4], al[2][4];
#pragma unroll
        for (int mi = 0; mi < 2; ++mi) {
            const int base = (rowBase + mi * 16 + lrow) * SA + k0;
            ldsm4(ah[mi], As_h + base);
            ldsm4(al[mi], As_l + base);
        }
        uint32_t bh[2][4], bl[2][4];
#pragma unroll
        for (int nj = 0; nj < 2; ++nj) {
            const int base = (colBase + nj * 16 + lrow) * SA + k0;
            ldsm4(bh[nj], Wh + base);
            ldsm4(bl[nj], Wl + base);
        }
#pragma unroll
        for (int mi = 0; mi < 2; ++mi)
#pragma unroll
            for (int ni = 0; ni < 4; ++ni) {
                const int nj = ni >> 1, hh = ni & 1;
                mma_bf16(acc[mi][ni], ah[mi], bh[nj][hh], bh[nj][hh + 2]);
                mma_bf16(acc[mi][ni], ah[mi], bl[nj][hh], bl[nj][hh + 2]);
                mma_bf16(acc[mi][ni], al[mi], bh[nj][hh], bh[nj][hh + 2]);
            }
    }
}

__device__ __forceinline__ void load_w_smem(const __nv_bfloat16* g,
                                            __nv_bfloat16* s, int tid) {
#pragma unroll
    for (int i = tid; i < 2048; i += 512) {
        int r = i >> 4, c = i & 15;
        *(uint4*)(s + r * SA + c * 8) = ((const uint4*)g)[i];
    }
}

// ---------------- fused GIN layer (512 threads) ----------------------------
// DUAL: write C value to both C and C2 (C2 = next layer's agg accumulator).
// HEAD: third GEMM vs Wo[128,64], writes [M,64] to C instead.
template <bool RELU2, bool DUAL, bool HEAD>
__global__ __launch_bounds__(512, 1) void fused_gin(
    const float* __restrict__ A,
    const __nv_bfloat16* __restrict__ W1h, const __nv_bfloat16* __restrict__ W1l,
    const __nv_bfloat16* __restrict__ W2h, const __nv_bfloat16* __restrict__ W2l,
    const __nv_bfloat16* __restrict__ Woh, const __nv_bfloat16* __restrict__ Wol,
    const float* __restrict__ b1, const float* __restrict__ b2,
    const float* __restrict__ b3,
    float* __restrict__ C, float* __restrict__ C2, int M) {
    extern __shared__ char smem[];
    __nv_bfloat16* As_h = (__nv_bfloat16*)smem;
    __nv_bfloat16* As_l = As_h + 128 * SA;
    __nv_bfloat16* Wah = As_l + 128 * SA;
    __nv_bfloat16* Wal = Wah + 128 * SA;
    __nv_bfloat16* Wbh = Wal + 128 * SA;
    __nv_bfloat16* Wbl = Wbh + 128 * SA;

    const int tid = threadIdx.x;
    const int lane = tid & 31, wid = tid >> 5;
    const int m0 = blockIdx.x * 128;

    load_w_smem(W1h, Wah, tid);
    load_w_smem(W1l, Wal, tid);
    load_w_smem(W2h, Wbh, tid);
    load_w_smem(W2l, Wbl, tid);

    // A tile: 16 warps x 8 rows
#pragma unroll
    for (int rr = 0; rr < 8; ++rr) {
        const int r = (wid << 3) + rr;
        const int row = m0 + r;
        float4 v = make_float4(0.f, 0.f, 0.f, 0.f);
        if (row < M) v = ((const float4*)A)[(size_t)row * 32 + lane];
        __nv_bfloat16* ph = As_h + r * SA + lane * 4;
        __nv_bfloat16* pl = As_l + r * SA + lane * 4;
        split_store2(v.x, v.y, ph, pl);
        split_store2(v.z, v.w, ph + 2, pl + 2);
    }
    __syncthreads();

    const int rowBase = (wid >> 2) * 32, colBase = (wid & 3) * 32;
    const int lrow = lane & 15, lkoff = (lane >> 4) * 8;
    const int cq = (lane & 3) * 2, rq = lane >> 2;

    float acc[2][4][4];
    gemm_pass16(As_h, As_l, Wah, Wal, rowBase, colBase, lrow, lkoff, acc);
    __syncthreads();

    if (HEAD) {  // stage Wo into now-dead Wa region
#pragma unroll
        for (int i = tid; i < 1024; i += 512) {
            int r = i >> 4, c = i & 15;
            *(uint4*)(Wah + r * SA + c * 8) = ((const uint4*)Woh)[i];
            *(uint4*)(Wal + r * SA + c * 8) = ((const uint4*)Wol)[i];
        }
    }
    // epilogue 1: h1 = relu(acc + b1) -> As
#pragma unroll
    for (int mi = 0; mi < 2; ++mi)
#pragma unroll
        for (int ni = 0; ni < 4; ++ni) {
            const int col = colBase + ni * 8 + cq;
            const float bb0 = b1[col], bb1 = b1[col + 1];
            const int r0 = rowBase + mi * 16 + rq, r1 = r0 + 8;
            float v00 = fmaxf(acc[mi][ni][0] + bb0, 0.f);
            float v01 = fmaxf(acc[mi][ni][1] + bb1, 0.f);
            float v10 = fmaxf(acc[mi][ni][2] + bb0, 0.f);
            float v11 = fmaxf(acc[mi][ni][3] + bb1, 0.f);
            split_store2(v00, v01, As_h + r0 * SA + col, As_l + r0 * SA + col);
            split_store2(v10, v11, As_h + r1 * SA + col, As_l + r1 * SA + col);
        }
    __syncthreads();

    gemm_pass16(As_h, As_l, Wbh, Wbl, rowBase, colBase, lrow, lkoff, acc);

    if (!HEAD) {
#pragma unroll
        for (int mi = 0; mi < 2; ++mi)
#pragma unroll
            for (int ni = 0; ni < 4; ++ni) {
                const int col = colBase + ni * 8 + cq;
                const float bb0 = b2[col], bb1 = b2[col + 1];
                const int r0 = m0 + rowBase + mi * 16 + rq, r1 = r0 + 8;
                float v00 = acc[mi][ni][0] + bb0, v01 = acc[mi][ni][1] + bb1;
                float v10 = acc[mi][ni][2] + bb0, v11 = acc[mi][ni][3] + bb1;
                if (RELU2) {
                    v00 = fmaxf(v00, 0.f); v01 = fmaxf(v01, 0.f);
                    v10 = fmaxf(v10, 0.f); v11 = fmaxf(v11, 0.f);
                }
                if (r0 < M) {
                    *(float2*)(C + (size_t)r0 * HD + col) = make_float2(v00, v01);
                    if (DUAL)
                        *(float2*)(C2 + (size_t)r0 * HD + col) = make_float2(v00, v01);
                }
                if (r1 < M) {
                    *(float2*)(C + (size_t)r1 * HD + col) = make_float2(v10, v11);
                    if (DUAL)
                        *(float2*)(C2 + (size_t)r1 * HD + col) = make_float2(v10, v11);
                }
            }
        return;
    }

    // HEAD: h2 = relu(acc + b2) -> As, pass 3 vs Wo, write [M,64]
    __syncthreads();
#pragma unroll
    for (int mi = 0; mi < 2; ++mi)
#pragma unroll
        for (int ni = 0; ni < 4; ++ni) {
            const int col = colBase + ni * 8 + cq;
            const float bb0 = b2[col], bb1 = b2[col + 1];
            const int r0 = rowBase + mi * 16 + rq, r1 = r0 + 8;
            float v00 = fmaxf(acc[mi][ni][0] + bb0, 0.f);
            float v01 = fmaxf(acc[mi][ni][1] + bb1, 0.f);
            float v10 = fmaxf(acc[mi][ni][2] + bb0, 0.f);
            float v11 = fmaxf(acc[mi][ni][3] + bb1, 0.f);
            split_store2(v00, v01, As_h + r0 * SA + col, As_l + r0 * SA + col);
            split_store2(v10, v11, As_h + r1 * SA + col, As_l + r1 * SA + col);
        }
    __syncthreads();

    const int colB3 = (wid & 3) * 16;
    float acc3[2][2][4];
#pragma unroll
    for (int mi = 0; mi < 2; ++mi)
#pragma unroll
        for (int ni = 0; ni < 2; ++ni)
#pragma unroll
            for (int q = 0; q < 4; ++q) acc3[mi][ni][q] = 0.f;
#pragma unroll
    for (int ks = 0; ks < 8; ++ks) {
        const int k0 = ks * 16 + lkoff;
        uint32_t ah[2][4], al[2][4];
#pragma unroll
        for (int mi = 0; mi < 2; ++mi) {
            const int base = (rowBase + mi * 16 + lrow) * SA + k0;
            ldsm4(ah[mi], As_h + base);
            ldsm4(al[mi], As_l + base);
        }
        uint32_t bh[4], bl[4];
        {
            const int base = (colB3 + lrow) * SA + k0;
            ldsm4(bh, Wah + base);
            ldsm4(bl, Wal + base);
        }
#pragma unroll
        for (int mi = 0; mi < 2; ++mi)
#pragma unroll
            for (int ni = 0; ni < 2; ++ni) {
                mma_bf16(acc3[mi][ni], ah[mi], bh[ni], bh[ni + 2]);
                mma_bf16(acc3[mi][ni], ah[mi], bl[ni], bl[ni + 2]);
                mma_bf16(acc3[mi][ni], al[mi], bh[ni], bh[ni + 2]);
            }
    }
#pragma unroll
    for (int mi = 0; mi < 2; ++mi)
#pragma unroll
        for (int ni = 0; ni < 2; ++ni) {
            const int col = colB3 + ni * 8 + cq;
            const float bb0 = b3[col], bb1 = b3[col + 1];
            const int r0 = m0 + rowBase + mi * 16 + rq, r1 = r0 + 8;
            if (r0 < M)
                *(float2*)(C + (size_t)r0 * OD + col) =
                    make_float2(acc3[mi][ni][0] + bb0, acc3[mi][ni][1] + bb1);
            if (r1 < M)
                *(float2*)(C + (size_t)r1 * OD + col) =
                    make_float2(acc3[mi][ni][2] + bb0, acc3[mi][ni][3] + bb1);
        }
}

// ---------------- weight prep ----------------------------------------------
struct PrepArgs {
    const float *W1[5], *b1[5], *g[5], *bb[5], *m[5], *v[5], *W2[5], *Wo;
    __nv_bfloat16 *W1h[5], *W1l[5], *W2h[5], *W2l[5], *Woh, *Wol;
    float* bf[5];
};

__global__ void prep_weights(PrepArgs a) {
    const int blk = blockIdx.x, tid = threadIdx.x;
    if (blk < 320) {
        const int j = blk >> 6;
        const int idx = ((blk & 63) << 8) + tid;
        const int k = idx >> 7, n = idx & 127;
        float s = a.g[j][n] * rsqrtf(a.v[j][n] + 1e-5f);
        float val = a.W1[j][idx] * s;
        __nv_bfloat16 h = __float2bfloat16(val);
        a.W1h[j][n * 128 + k] = h;
        a.W1l[j][n * 128 + k] = __float2bfloat16(val - __bfloat162float(h));
        if (idx < 128)
            a.bf[j][idx] = a.b1[j][idx] * s + a.bb[j][idx] - a.m[j][idx] * s;
    } else if (blk < 640) {
        const int j = (blk - 320) >> 6;
        const int idx = (((blk - 320) & 63) << 8) + tid;
        const int k = idx >> 7, n = idx & 127;
        float val = a.W2[j][idx];
        __nv_bfloat16 h = __float2bfloat16(val);
        a.W2h[j][n * 128 + k] = h;
        a.W2l[j][n * 128 + k] = __float2bfloat16(val - __bfloat162float(h));
    } else {
        const int idx = ((blk - 640) << 8) + tid;  // 8192
        const int k = idx >> 6, n = idx & 63;
        float val = a.Wo[idx];
        __nv_bfloat16 h = __float2bfloat16(val);
        a.Woh[n * 128 + k] = h;
        a.Wol[n * 128 + k] = __float2bfloat16(val - __bfloat162float(h));
    }
}

// ---------------- graph kernels ---------------------------------------------
__global__ void copy4_kernel(const float4* __restrict__ s,
                             float4* __restrict__ d, int n) {
    int i = blockIdx.x * 256 + threadIdx.x;
    if (i < n) d[i] = s[i];
}

__global__ void scatter_add4_kernel(const int* __restrict__ srcs,
                                    const int* __restrict__ dsts,
                                    const float* __restrict__ x,
                                    float* __restrict__ agg, int E) {
    unsigned t = blockIdx.x * 256u + threadIdx.x;
    unsigned e = t >> 5, lane = t & 31u;
    if (e >= (unsigned)E) return;
    int s = srcs[e], d = dsts[e];
    float4 v = ((const float4*)(x + (size_t)s * HD))[lane];
    float* dp = agg + (size_t)d * HD + lane * 4;
    asm volatile("red.global.add.v4.f32 [%0], {%1,%2,%3,%4};" ::"l"(dp),
                 "f"(v.x), "f"(v.y), "f"(v.z), "f"(v.w)
                 : "memory");
}

// h = y[ep0] + y[ep1], written to BOTH h and hagg
__global__ void pair_gather2_kernel(const int* __restrict__ ep,
                                    const float* __restrict__ y,
                                    float* __restrict__ h,
                                    float* __restrict__ hagg, int E) {
    unsigned t = blockIdx.x * 256u + threadIdx.x;
    unsigned e = t >> 5, lane = t & 31u;
    if (e >= (unsigned)E) return;
    int i0 = ep[2 * e], i1 = ep[2 * e + 1];
    float4 a = ((const float4*)(y + (size_t)i0 * HD))[lane];
    float4 b = ((const float4*)(y + (size_t)i1 * HD))[lane];
    a.x += b.x; a.y += b.y; a.z += b.z; a.w += b.w;
    ((float4*)(h + (size_t)e * HD))[lane] = a;
    ((float4*)(hagg + (size_t)e * HD))[lane] = a;
}

// -----------------------------------------------------------------------------
extern "C" void kernel_launch(void* const* d_in, const int* in_sizes, int n_in,
                              void* d_out, int out_size) {
    const int*   edge_index = (const int*)d_in[0];
    const float* x_orig     = (const float*)d_in[1];
    const int*   ei_orig    = (const int*)d_in[2];
    const int*   edge_pairs = (const int*)d_in[3];
    const float* init_W1 = (const float*)d_in[4];
    const float* init_b1 = (const float*)d_in[5];
    const float* init_g  = (const float*)d_in[6];
    const float* init_bb = (const float*)d_in[7];
    const float* init_m  = (const float*)d_in[8];
    const float* init_v  = (const float*)d_in[9];
    const float* init_W2 = (const float*)d_in[10];
    const float* init_b2 = (const float*)d_in[11];
    const float* gin_W1  = (const float*)d_in[12];
    const float* gin_b1  = (const float*)d_in[13];
    const float* gin_g   = (const float*)d_in[14];
    const float* gin_bb  = (const float*)d_in[15];
    const float* gin_m   = (const float*)d_in[16];
    const float* gin_v   = (const float*)d_in[17];
    const float* gin_W2  = (const float*)d_in[18];
    const float* gin_b2  = (const float*)d_in[19];
    const float* mlp_W1  = (const float*)d_in[20];
    const float* mlp_b1  = (const float*)d_in[21];
    const float* mlp_g   = (const float*)d_in[22];
    const float* mlp_bb  = (const float*)d_in[23];
    const float* mlp_m   = (const float*)d_in[24];
    const float* mlp_v   = (const float*)d_in[25];
    const float* mlp_W2  = (const float*)d_in[26];
    const float* mlp_b2  = (const float*)d_in[27];
    const float* out_W   = (const float*)d_in[28];
    const float* out_b   = (const float*)d_in[29];
    float* out = (float*)d_out;

    float *nodeA, *nodeB, *nodeC, *nodeD, *edgeA, *edgeB, *edgeC, *bfb;
    __nv_bfloat16 *W1h, *W1l, *W2h, *W2l, *Woh, *Wol;
    cudaGetSymbolAddress((void**)&nodeA, g_nodeA);
    cudaGetSymbolAddress((void**)&nodeB, g_nodeB);
    cudaGetSymbolAddress((void**)&nodeC, g_nodeC);
    cudaGetSymbolAddress((void**)&nodeD, g_nodeD);
    cudaGetSymbolAddress((void**)&edgeA, g_edgeA);
    cudaGetSymbolAddress((void**)&edgeB, g_edgeB);
    cudaGetSymbolAddress((void**)&edgeC, g_edgeC);
    cudaGetSymbolAddress((void**)&bfb, g_bfb);
    cudaGetSymbolAddress((void**)&W1h, g_W1h);
    cudaGetSymbolAddress((void**)&W1l, g_W1l);
    cudaGetSymbolAddress((void**)&W2h, g_W2h);
    cudaGetSymbolAddress((void**)&W2l, g_W2l);
    cudaGetSymbolAddress((void**)&Woh, g_Woh);
    cudaGetSymbolAddress((void**)&Wol, g_Wol);

    // weight prep
    PrepArgs pa;
    const float* W1s[5]  = {init_W1, init_W1 + HD * HD, mlp_W1, gin_W1, gin_W1 + HD * HD};
    const float* b1s[5]  = {init_b1, init_b1 + HD, mlp_b1, gin_b1, gin_b1 + HD};
    const float* gs[5]   = {init_g, init_g + HD, mlp_g, gin_g, gin_g + HD};
    const float* bbs[5]  = {init_bb, init_bb + HD, mlp_bb, gin_bb, gin_bb + HD};
    const float* ms[5]   = {init_m, init_m + HD, mlp_m, gin_m, gin_m + HD};
    const float* vs[5]   = {init_v, init_v + HD, mlp_v, gin_v, gin_v + HD};
    const float* W2s[5]  = {init_W2, init_W2 + HD * HD, mlp_W2, gin_W2, gin_W2 + HD * HD};
    for (int j = 0; j < 5; ++j) {
        pa.W1[j] = W1s[j]; pa.b1[j] = b1s[j]; pa.g[j] = gs[j]; pa.bb[j] = bbs[j];
        pa.m[j] = ms[j]; pa.v[j] = vs[j]; pa.W2[j] = W2s[j];
        pa.W1h[j] = W1h + (size_t)j * HD * HD; pa.W1l[j] = W1l + (size_t)j * HD * HD;
        pa.W2h[j] = W2h + (size_t)j * HD * HD; pa.W2l[j] = W2l + (size_t)j * HD * HD;
        pa.bf[j] = bfb + j * HD;
    }
    pa.Wo = out_W; pa.Woh = Woh; pa.Wol = Wol;
    prep_weights<<<672, 256>>>(pa);

    const int SMEM_F = 6 * 128 * SA * 2;  // 208896 B
    cudaFuncSetAttribute(fused_gin<true, true, false>,
                         cudaFuncAttributeMaxDynamicSharedMemorySize, SMEM_F);
    cudaFuncSetAttribute(fused_gin<true, false, false>,
                         cudaFuncAttributeMaxDynamicSharedMemorySize, SMEM_F);
    cudaFuncSetAttribute(fused_gin<false, false, false>,
                         cudaFuncAttributeMaxDynamicSharedMemorySize, SMEM_F);
    cudaFuncSetAttribute(fused_gin<true, true, true>,
                         cudaFuncAttributeMaxDynamicSharedMemorySize, SMEM_F);

    const int gridN = (NN + 127) / 128;
    const int gridE = (EO + 127) / 128;
    const int cpN = (NN * 32 + 255) / 256;
    const int scO = ((unsigned)EO * 32u + 255u) / 256u;
    const int scL = ((unsigned)EL * 32u + 255u) / 256u;
    const size_t WSZ = (size_t)HD * HD;

    // ---- node layer 0: agg(x) in nodeB -> GEMM -> nodeA + nodeC(agg init) --
    copy4_kernel<<<cpN, 256>>>((const float4*)x_orig, (float4*)nodeB, NN * 32);
    scatter_add4_kernel<<<scO, 256>>>(ei_orig, ei_orig + EO, x_orig, nodeB, EO);
    fused_gin<true, true, false><<<gridN, 512, SMEM_F>>>(
        nodeB, W1h, W1l, W2h, W2l, nullptr, nullptr,
        bfb, init_b2, nullptr, nodeA, nodeC, NN);

    // ---- node layer 1: scatter into nodeC -> GEMM -> nodeD -----------------
    scatter_add4_kernel<<<scO, 256>>>(ei_orig, ei_orig + EO, nodeA, nodeC, EO);
    fused_gin<true, false, false><<<gridN, 512, SMEM_F>>>(
        nodeC, W1h + WSZ, W1l + WSZ, W2h + WSZ, W2l + WSZ, nullptr, nullptr,
        bfb + HD, init_b2 + HD, nullptr, nodeD, nullptr, NN);

    // ---- node MLP: nodeD -> nodeA -------------------------------------------
    fused_gin<false, false, false><<<gridN, 512, SMEM_F>>>(
        nodeD, W1h + 2 * WSZ, W1l + 2 * WSZ, W2h + 2 * WSZ, W2l + 2 * WSZ,
        nullptr, nullptr, bfb + 2 * HD, mlp_b2, nullptr, nodeA, nullptr, NN);

    // ---- pair lift: h -> edgeA (source) + edgeB (agg accumulator) -----------
    pair_gather2_kernel<<<scO, 256>>>(edge_pairs, nodeA, edgeA, edgeB, EO);

    // ---- edge layer 0: scatter into edgeB -> GEMM -> edgeA + edgeC(agg) -----
    scatter_add4_kernel<<<scL, 256>>>(edge_index, edge_index + EL, edgeA, edgeB, EL);
    fused_gin<true, true, false><<<gridE, 512, SMEM_F>>>(
        edgeB, W1h + 3 * WSZ, W1l + 3 * WSZ, W2h + 3 * WSZ, W2l + 3 * WSZ,
        nullptr, nullptr, bfb + 3 * HD, gin_b2, nullptr, edgeA, edgeC, EO);

    // ---- edge layer 1 + head: scatter into edgeC -> GEMM+head -> out --------
    scatter_add4_kernel<<<scL, 256>>>(edge_index, edge_index + EL, edgeA, edgeC, EL);
    fused_gin<true, true, true><<<gridE, 512, SMEM_F>>>(
        edgeC, W1h + 4 * WSZ, W1l + 4 * WSZ, W2h + 4 * WSZ, W2l + 4 * WSZ,
        Woh, Wol, bfb + 4 * HD, gin_b2 + HD, out_b, out, nullptr, EO);
}

// round 6
// speedup vs baseline: 1.4307x; 1.1242x over previous
#include <cuda_runtime.h>
#include <cuda_bf16.h>
#include <cstdint>

#define NN 100000
#define EO 600000
#define EL 1200000
#define HD 128
#define OD 64
#define SA 136   // smem row stride (bf16) -> conflict-spread ldmatrix

// ---------------- scratch (device globals) ---------------------------------
static __device__ float g_nodeA[(size_t)NN * HD];
static __device__ float g_nodeB[(size_t)NN * HD];
static __device__ float g_nodeC[(size_t)NN * HD];
static __device__ float g_nodeD[(size_t)NN * HD];
static __device__ float g_edgeA[(size_t)EO * HD];
static __device__ float g_edgeB[(size_t)EO * HD];
static __device__ float g_edgeC[(size_t)EO * HD];
static __device__ __nv_bfloat16 g_W1h[5][HD * HD], g_W1l[5][HD * HD];
static __device__ __nv_bfloat16 g_W2h[5][HD * HD], g_W2l[5][HD * HD];
static __device__ uint32_t g_Wofh[4096], g_Wofl[4096];  // Wo in frag order
static __device__ float g_bfb[5][HD];

// ---------------- PTX helpers ----------------------------------------------
__device__ __forceinline__ void ldsm4(uint32_t* r, const void* p) {
    uint32_t a = (uint32_t)__cvta_generic_to_shared(p);
    asm volatile("ldmatrix.sync.aligned.m8n8.x4.shared.b16 {%0,%1,%2,%3}, [%4];"
                 : "=r"(r[0]), "=r"(r[1]), "=r"(r[2]), "=r"(r[3]) : "r"(a));
}
__device__ __forceinline__ void mma_bf16(float* d, const uint32_t* a,
                                         uint32_t b0, uint32_t b1) {
    asm volatile(
        "mma.sync.aligned.m16n8k16.row.col.f32.bf16.bf16.f32 "
        "{%0,%1,%2,%3}, {%4,%5,%6,%7}, {%8,%9}, {%0,%1,%2,%3};"
        : "+f"(d[0]), "+f"(d[1]), "+f"(d[2]), "+f"(d[3])
        : "r"(a[0]), "r"(a[1]), "r"(a[2]), "r"(a[3]), "r"(b0), "r"(b1));
}
__device__ __forceinline__ void split_store2(float x0, float x1,
                                             __nv_bfloat16* ph,
                                             __nv_bfloat16* pl) {
    __nv_bfloat16 h0 = __float2bfloat16(x0);
    __nv_bfloat16 h1 = __float2bfloat16(x1);
    __nv_bfloat16 l0 = __float2bfloat16(x0 - __bfloat162float(h0));
    __nv_bfloat16 l1 = __float2bfloat16(x1 - __bfloat162float(h1));
    *(__nv_bfloat162*)ph = __halves2bfloat162(h0, h1);
    *(__nv_bfloat162*)pl = __halves2bfloat162(l0, l1);
}
__device__ __forceinline__ uint32_t pack_hi(float a, float b) {
    __nv_bfloat162 t = __halves2bfloat162(__float2bfloat16(a), __float2bfloat16(b));
    return *(uint32_t*)&t;
}
__device__ __forceinline__ uint32_t pack_lo(float a, float b) {
    float ra = a - __bfloat162float(__float2bfloat16(a));
    float rb = b - __bfloat162float(__float2bfloat16(b));
    __nv_bfloat162 t = __halves2bfloat162(__float2bfloat16(ra), __float2bfloat16(rb));
    return *(uint32_t*)&t;
}
#define BARH(id) asm volatile("bar.sync %0, 256;" :: "r"(id) : "memory")

// one 64x128 @ 128x128 pass from smem; 8 warps/half, warp tile 32x32
__device__ __forceinline__ void gemm_pass(
    const __nv_bfloat16* As_h, const __nv_bfloat16* As_l,
    const __nv_bfloat16* Wh, const __nv_bfloat16* Wl,
    int rowBase, int colBase, int lrow, int lkoff, float (&acc)[2][4][4]) {
#pragma unroll
    for (int mi = 0; mi < 2; ++mi)
#pragma unroll
        for (int ni = 0; ni < 4; ++ni)
#pragma unroll
            for (int q = 0; q < 4; ++q) acc[mi][ni][q] = 0.f;
#pragma unroll
    for (int ks = 0; ks < 8; ++ks) {
        const int k0 = ks * 16 + lkoff;
        uint32_t ah[2][4], al[2][4];
#pragma unroll
        for (int mi = 0; mi < 2; ++mi) {
            const int base = (rowBase + mi * 16 + lrow) * SA + k0;
            ldsm4(ah[mi], As_h + base);
            ldsm4(al[mi], As_l + base);
        }
        uint32_t bh[2][4], bl[2][4];
#pragma unroll
        for (int nj = 0; nj < 2; ++nj) {
            const int base = (colBase + nj * 16 + lrow) * SA + k0;
            ldsm4(bh[nj], Wh + base);
            ldsm4(bl[nj], Wl + base);
        }
#pragma unroll
        for (int mi = 0; mi < 2; ++mi)
#pragma unroll
            for (int ni = 0; ni < 4; ++ni) {
                const int nj = ni >> 1, hh = ni & 1;
                mma_bf16(acc[mi][ni], ah[mi], bh[nj][hh], bh[nj][hh + 2]);
                mma_bf16(acc[mi][ni], ah[mi], bl[nj][hh], bl[nj][hh + 2]);
                mma_bf16(acc[mi][ni], al[mi], bh[nj][hh], bh[nj][hh + 2]);
            }
    }
}

// ---------------- fused GIN layer: persistent, two independent halves ------
// half = tile pipeline of 8 warps with private 64-row A smem, shared W smem.
// DUAL: also write result to C2 (next layer's agg accumulator).
// HEAD: third GEMM vs Wo (fragments from gmem), writes [M,64].
template <bool RELU2, bool DUAL, bool HEAD>
__global__ __launch_bounds__(512, 1) void fused_gin(
    const float* __restrict__ A,
    const __nv_bfloat16* __restrict__ W1hI, const __nv_bfloat16* __restrict__ W1lI,
    const __nv_bfloat16* __restrict__ W2hI, const __nv_bfloat16* __restrict__ W2lI,
    const uint4* __restrict__ WoFh, const uint4* __restrict__ WoFl,
    const float* __restrict__ b1, const float* __restrict__ b2,
    const float* __restrict__ b3,
    float* __restrict__ C, float* __restrict__ C2, int M, int nTiles) {
    extern __shared__ char smem[];
    const int tid = threadIdx.x, lane = tid & 31, wid = tid >> 5;
    const int half = wid >> 3, wl = wid & 7;

    __nv_bfloat16* As_h = (__nv_bfloat16*)(smem + half * 2 * 17408);
    __nv_bfloat16* As_l = (__nv_bfloat16*)(smem + half * 2 * 17408 + 17408);
    __nv_bfloat16* Wah = (__nv_bfloat16*)(smem + 69632);
    __nv_bfloat16* Wal = (__nv_bfloat16*)(smem + 104448);
    __nv_bfloat16* Wbh = (__nv_bfloat16*)(smem + 139264);
    __nv_bfloat16* Wbl = (__nv_bfloat16*)(smem + 174080);

    // stage W once per CTA (all 512 threads)
    {
        const uint4* s1 = (const uint4*)W1hI;
        const uint4* s2 = (const uint4*)W1lI;
        const uint4* s3 = (const uint4*)W2hI;
        const uint4* s4 = (const uint4*)W2lI;
        for (int i = tid; i < 2048; i += 512) {
            int r = i >> 4, c = i & 15;
            *(uint4*)(Wah + r * SA + c * 8) = s1[i];
            *(uint4*)(Wal + r * SA + c * 8) = s2[i];
            *(uint4*)(Wbh + r * SA + c * 8) = s3[i];
            *(uint4*)(Wbl + r * SA + c * 8) = s4[i];
        }
    }
    __syncthreads();

    const int barid = 1 + half;
    const int rowBase = (wl >> 2) * 32, colBase = (wl & 3) * 32;
    const int lrow = lane & 15, lkoff = (lane >> 4) * 8;
    const int cq = (lane & 3) * 2, rq = lane >> 2;
    const int cc = wl & 3;

    for (int tile = blockIdx.x * 2 + half; tile < nTiles; tile += gridDim.x * 2) {
        const int m0 = tile * 64;
        BARH(barid);   // previous iteration's As readers done

        // ---- A tile build: 8 warps x 8 rows ------------------------------
#pragma unroll
        for (int rr = 0; rr < 8; ++rr) {
            const int r = wl * 8 + rr;
            const int row = m0 + r;
            float4 v = make_float4(0.f, 0.f, 0.f, 0.f);
            if (row < M) v = ((const float4*)A)[(size_t)row * 32 + lane];
            __nv_bfloat16* ph = As_h + r * SA + lane * 4;
            __nv_bfloat16* pl = As_l + r * SA + lane * 4;
            split_store2(v.x, v.y, ph, pl);
            split_store2(v.z, v.w, ph + 2, pl + 2);
        }
        BARH(barid);

        float acc[2][4][4];
        gemm_pass(As_h, As_l, Wah, Wal, rowBase, colBase, lrow, lkoff, acc);
        BARH(barid);   // all As reads done before overwrite

        // epilogue 1: h1 = relu(acc + b1) -> As
#pragma unroll
        for (int mi = 0; mi < 2; ++mi)
#pragma unroll
            for (int ni = 0; ni < 4; ++ni) {
                const int col = colBase + ni * 8 + cq;
                const float bb0 = b1[col], bb1 = b1[col + 1];
                const int r0 = rowBase + mi * 16 + rq, r1 = r0 + 8;
                float v00 = fmaxf(acc[mi][ni][0] + bb0, 0.f);
                float v01 = fmaxf(acc[mi][ni][1] + bb1, 0.f);
                float v10 = fmaxf(acc[mi][ni][2] + bb0, 0.f);
                float v11 = fmaxf(acc[mi][ni][3] + bb1, 0.f);
                split_store2(v00, v01, As_h + r0 * SA + col, As_l + r0 * SA + col);
                split_store2(v10, v11, As_h + r1 * SA + col, As_l + r1 * SA + col);
            }
        BARH(barid);

        gemm_pass(As_h, As_l, Wbh, Wbl, rowBase, colBase, lrow, lkoff, acc);

        if (!HEAD) {
#pragma unroll
            for (int mi = 0; mi < 2; ++mi)
#pragma unroll
                for (int ni = 0; ni < 4; ++ni) {
                    const int col = colBase + ni * 8 + cq;
                    const float bb0 = b2[col], bb1 = b2[col + 1];
                    const int r0 = m0 + rowBase + mi * 16 + rq, r1 = r0 + 8;
                    float v00 = acc[mi][ni][0] + bb0, v01 = acc[mi][ni][1] + bb1;
                    float v10 = acc[mi][ni][2] + bb0, v11 = acc[mi][ni][3] + bb1;
                    if (RELU2) {
                        v00 = fmaxf(v00, 0.f); v01 = fmaxf(v01, 0.f);
                        v10 = fmaxf(v10, 0.f); v11 = fmaxf(v11, 0.f);
                    }
                    if (r0 < M) {
                        *(float2*)(C + (size_t)r0 * HD + col) = make_float2(v00, v01);
                        if (DUAL)
                            *(float2*)(C2 + (size_t)r0 * HD + col) = make_float2(v00, v01);
                    }
                    if (r1 < M) {
                        *(float2*)(C + (size_t)r1 * HD + col) = make_float2(v10, v11);
                        if (DUAL)
                            *(float2*)(C2 + (size_t)r1 * HD + col) = make_float2(v10, v11);
                    }
                }
        } else {
            BARH(barid);   // pass2 As reads done
            // h2 = relu(acc + b2) -> As
#pragma unroll
            for (int mi = 0; mi < 2; ++mi)
#pragma unroll
                for (int ni = 0; ni < 4; ++ni) {
                    const int col = colBase + ni * 8 + cq;
                    const float bb0 = b2[col], bb1 = b2[col + 1];
                    const int r0 = rowBase + mi * 16 + rq, r1 = r0 + 8;
                    float v00 = fmaxf(acc[mi][ni][0] + bb0, 0.f);
                    float v01 = fmaxf(acc[mi][ni][1] + bb1, 0.f);
                    float v10 = fmaxf(acc[mi][ni][2] + bb0, 0.f);
                    float v11 = fmaxf(acc[mi][ni][3] + bb1, 0.f);
                    split_store2(v00, v01, As_h + r0 * SA + col, As_l + r0 * SA + col);
                    split_store2(v10, v11, As_h + r1 * SA + col, As_l + r1 * SA + col);
                }
            BARH(barid);

            // pass 3: h2 @ Wo, B fragments straight from gmem (L2-resident)
            float acc3[2][2][4];
#pragma unroll
            for (int mi = 0; mi < 2; ++mi)
#pragma unroll
                for (int ni = 0; ni < 2; ++ni)
#pragma unroll
                    for (int q = 0; q < 4; ++q) acc3[mi][ni][q] = 0.f;
#pragma unroll
            for (int ks = 0; ks < 8; ++ks) {
                const int k0 = ks * 16 + lkoff;
                uint32_t ah[2][4], al[2][4];
#pragma unroll
                for (int mi = 0; mi < 2; ++mi) {
                    const int base = (rowBase + mi * 16 + lrow) * SA + k0;
                    ldsm4(ah[mi], As_h + base);
                    ldsm4(al[mi], As_l + base);
                }
                const uint4 bh = WoFh[(cc * 8 + ks) * 32 + lane];
                const uint4 bl = WoFl[(cc * 8 + ks) * 32 + lane];
#pragma unroll
                for (int mi = 0; mi < 2; ++mi) {
                    mma_bf16(acc3[mi][0], ah[mi], bh.x, bh.z);
                    mma_bf16(acc3[mi][0], ah[mi], bl.x, bl.z);
                    mma_bf16(acc3[mi][0], al[mi], bh.x, bh.z);
                    mma_bf16(acc3[mi][1], ah[mi], bh.y, bh.w);
                    mma_bf16(acc3[mi][1], ah[mi], bl.y, bl.w);
                    mma_bf16(acc3[mi][1], al[mi], bh.y, bh.w);
                }
            }
#pragma unroll
            for (int mi = 0; mi < 2; ++mi)
#pragma unroll
                for (int ni = 0; ni < 2; ++ni) {
                    const int col = cc * 16 + ni * 8 + cq;
                    const float bb0 = b3[col], bb1 = b3[col + 1];
                    const int r0 = m0 + rowBase + mi * 16 + rq, r1 = r0 + 8;
                    if (r0 < M)
                        *(float2*)(C + (size_t)r0 * OD + col) =
                            make_float2(acc3[mi][ni][0] + bb0, acc3[mi][ni][1] + bb1);
                    if (r1 < M)
                        *(float2*)(C + (size_t)r1 * OD + col) =
                            make_float2(acc3[mi][ni][2] + bb0, acc3[mi][ni][3] + bb1);
                }
        }
    }
}

// ---------------- weight prep ------------------------------------------------
struct PrepArgs {
    const float *W1[5], *b1[5], *g[5], *bb[5], *m[5], *v[5], *W2[5], *Wo;
    __nv_bfloat16 *W1h[5], *W1l[5], *W2h[5], *W2l[5];
    uint32_t *Wofh, *Wofl;
    float* bf[5];
};

__global__ void prep_weights(PrepArgs a) {
    const int blk = blockIdx.x, tid = threadIdx.x;
    if (blk < 320) {                        // BN-fold W1 (5 jobs)
        const int j = blk >> 6;
        const int idx = ((blk & 63) << 8) + tid;
        const int k = idx >> 7, n = idx & 127;
        float s = a.g[j][n] * rsqrtf(a.v[j][n] + 1e-5f);
        float val = a.W1[j][idx] * s;
        __nv_bfloat16 h = __float2bfloat16(val);
        a.W1h[j][n * 128 + k] = h;
        a.W1l[j][n * 128 + k] = __float2bfloat16(val - __bfloat162float(h));
        if (idx < 128)
            a.bf[j][idx] = a.b1[j][idx] * s + a.bb[j][idx] - a.m[j][idx] * s;
    } else if (blk < 640) {                 // W2 (5 jobs)
        const int j = (blk - 320) >> 6;
        const int idx = (((blk - 320) & 63) << 8) + tid;
        const int k = idx >> 7, n = idx & 127;
        float val = a.W2[j][idx];
        __nv_bfloat16 h = __float2bfloat16(val);
        a.W2h[j][n * 128 + k] = h;
        a.W2l[j][n * 128 + k] = __float2bfloat16(val - __bfloat162float(h));
    } else {                                // Wo -> ldmatrix fragment order
        const int idx = ((blk - 640) << 8) + tid;  // 0..4095
        const int j = idx & 3, L = (idx >> 2) & 31;
        const int ks = (idx >> 7) & 7, cc = idx >> 10;
        const int n = cc * 16 + (j & 1) * 8 + (L >> 2);
        const int k = ks * 16 + ((j >> 1)) * 8 + (L & 3) * 2;
        float v0 = a.Wo[k * OD + n];
        float v1 = a.Wo[(k + 1) * OD + n];
        a.Wofh[((cc * 8 + ks) * 32 + L) * 4 + j] = pack_hi(v0, v1);
        a.Wofl[((cc * 8 + ks) * 32 + L) * 4 + j] = pack_lo(v0, v1);
    }
}

// ---------------- graph kernels -----------------------------------------------
__global__ void copy4_kernel(const float4* __restrict__ s,
                             float4* __restrict__ d, int n) {
    int i = blockIdx.x * 256 + threadIdx.x;
    if (i < n) d[i] = s[i];
}

__global__ void scatter_add4_kernel(const int* __restrict__ srcs,
                                    const int* __restrict__ dsts,
                                    const float* __restrict__ x,
                                    float* __restrict__ agg, int E) {
    unsigned t = blockIdx.x * 256u + threadIdx.x;
    unsigned e = t >> 5, lane = t & 31u;
    if (e >= (unsigned)E) return;
    int s = srcs[e], d = dsts[e];
    float4 v = ((const float4*)(x + (size_t)s * HD))[lane];
    float* dp = agg + (size_t)d * HD + lane * 4;
    asm volatile("red.global.add.v4.f32 [%0], {%1,%2,%3,%4};" ::"l"(dp),
                 "f"(v.x), "f"(v.y), "f"(v.z), "f"(v.w)
                 : "memory");
}

__global__ void pair_gather2_kernel(const int* __restrict__ ep,
                                    const float* __restrict__ y,
                                    float* __restrict__ h,
                                    float* __restrict__ hagg, int E) {
    unsigned t = blockIdx.x * 256u + threadIdx.x;
    unsigned e = t >> 5, lane = t & 31u;
    if (e >= (unsigned)E) return;
    int i0 = ep[2 * e], i1 = ep[2 * e + 1];
    float4 a = ((const float4*)(y + (size_t)i0 * HD))[lane];
    float4 b = ((const float4*)(y + (size_t)i1 * HD))[lane];
    a.x += b.x; a.y += b.y; a.z += b.z; a.w += b.w;
    ((float4*)(h + (size_t)e * HD))[lane] = a;
    ((float4*)(hagg + (size_t)e * HD))[lane] = a;
}

// --------------------------------------------------------------------------------
extern "C" void kernel_launch(void* const* d_in, const int* in_sizes, int n_in,
                              void* d_out, int out_size) {
    const int*   edge_index = (const int*)d_in[0];
    const float* x_orig     = (const float*)d_in[1];
    const int*   ei_orig    = (const int*)d_in[2];
    const int*   edge_pairs = (const int*)d_in[3];
    const float* init_W1 = (const float*)d_in[4];
    const float* init_b1 = (const float*)d_in[5];
    const float* init_g  = (const float*)d_in[6];
    const float* init_bb = (const float*)d_in[7];
    const float* init_m  = (const float*)d_in[8];
    const float* init_v  = (const float*)d_in[9];
    const float* init_W2 = (const float*)d_in[10];
    const float* init_b2 = (const float*)d_in[11];
    const float* gin_W1  = (const float*)d_in[12];
    const float* gin_b1  = (const float*)d_in[13];
    const float* gin_g   = (const float*)d_in[14];
    const float* gin_bb  = (const float*)d_in[15];
    const float* gin_m   = (const float*)d_in[16];
    const float* gin_v   = (const float*)d_in[17];
    const float* gin_W2  = (const float*)d_in[18];
    const float* gin_b2  = (const float*)d_in[19];
    const float* mlp_W1  = (const float*)d_in[20];
    const float* mlp_b1  = (const float*)d_in[21];
    const float* mlp_g   = (const float*)d_in[22];
    const float* mlp_bb  = (const float*)d_in[23];
    const float* mlp_m   = (const float*)d_in[24];
    const float* mlp_v   = (const float*)d_in[25];
    const float* mlp_W2  = (const float*)d_in[26];
    const float* mlp_b2  = (const float*)d_in[27];
    const float* out_W   = (const float*)d_in[28];
    const float* out_b   = (const float*)d_in[29];
    float* out = (float*)d_out;

    float *nodeA, *nodeB, *nodeC, *nodeD, *edgeA, *edgeB, *edgeC, *bfb;
    __nv_bfloat16 *W1h, *W1l, *W2h, *W2l;
    uint32_t *Wofh, *Wofl;
    cudaGetSymbolAddress((void**)&nodeA, g_nodeA);
    cudaGetSymbolAddress((void**)&nodeB, g_nodeB);
    cudaGetSymbolAddress((void**)&nodeC, g_nodeC);
    cudaGetSymbolAddress((void**)&nodeD, g_nodeD);
    cudaGetSymbolAddress((void**)&edgeA, g_edgeA);
    cudaGetSymbolAddress((void**)&edgeB, g_edgeB);
    cudaGetSymbolAddress((void**)&edgeC, g_edgeC);
    cudaGetSymbolAddress((void**)&bfb, g_bfb);
    cudaGetSymbolAddress((void**)&W1h, g_W1h);
    cudaGetSymbolAddress((void**)&W1l, g_W1l);
    cudaGetSymbolAddress((void**)&W2h, g_W2h);
    cudaGetSymbolAddress((void**)&W2l, g_W2l);
    cudaGetSymbolAddress((void**)&Wofh, g_Wofh);
    cudaGetSymbolAddress((void**)&Wofl, g_Wofl);

    // weight prep
    PrepArgs pa;
    const float* W1s[5]  = {init_W1, init_W1 + HD * HD, mlp_W1, gin_W1, gin_W1 + HD * HD};
    const float* b1s[5]  = {init_b1, init_b1 + HD, mlp_b1, gin_b1, gin_b1 + HD};
    const float* gs[5]   = {init_g, init_g + HD, mlp_g, gin_g, gin_g + HD};
    const float* bbs[5]  = {init_bb, init_bb + HD, mlp_bb, gin_bb, gin_bb + HD};
    const float* ms[5]   = {init_m, init_m + HD, mlp_m, gin_m, gin_m + HD};
    const float* vs[5]   = {init_v, init_v + HD, mlp_v, gin_v, gin_v + HD};
    const float* W2s[5]  = {init_W2, init_W2 + HD * HD, mlp_W2, gin_W2, gin_W2 + HD * HD};
    for (int j = 0; j < 5; ++j) {
        pa.W1[j] = W1s[j]; pa.b1[j] = b1s[j]; pa.g[j] = gs[j]; pa.bb[j] = bbs[j];
        pa.m[j] = ms[j]; pa.v[j] = vs[j]; pa.W2[j] = W2s[j];
        pa.W1h[j] = W1h + (size_t)j * HD * HD; pa.W1l[j] = W1l + (size_t)j * HD * HD;
        pa.W2h[j] = W2h + (size_t)j * HD * HD; pa.W2l[j] = W2l + (size_t)j * HD * HD;
        pa.bf[j] = bfb + j * HD;
    }
    pa.Wo = out_W; pa.Wofh = Wofh; pa.Wofl = Wofl;
    prep_weights<<<656, 256>>>(pa);

    const int SMEM_F = 208896;
    cudaFuncSetAttribute(fused_gin<true, true, false>,
                         cudaFuncAttributeMaxDynamicSharedMemorySize, SMEM_F);
    cudaFuncSetAttribute(fused_gin<true, false, false>,
                         cudaFuncAttributeMaxDynamicSharedMemorySize, SMEM_F);
    cudaFuncSetAttribute(fused_gin<false, false, false>,
                         cudaFuncAttributeMaxDynamicSharedMemorySize, SMEM_F);
    cudaFuncSetAttribute(fused_gin<true, false, true>,
                         cudaFuncAttributeMaxDynamicSharedMemorySize, SMEM_F);

    const int GRID = 148;                   // persistent, 1 CTA/SM
    const int tilesN = (NN + 63) / 64;      // 1563
    const int tilesE = (EO + 63) / 64;      // 9375
    const int cpN = (NN * 32 + 255) / 256;
    const int scO = ((unsigned)EO * 32u + 255u) / 256u;
    const int scL = ((unsigned)EL * 32u + 255u) / 256u;
    const size_t WSZ = (size_t)HD * HD;

    // ---- node layer 0 -------------------------------------------------------
    copy4_kernel<<<cpN, 256>>>((const float4*)x_orig, (float4*)nodeB, NN * 32);
    scatter_add4_kernel<<<scO, 256>>>(ei_orig, ei_orig + EO, x_orig, nodeB, EO);
    fused_gin<true, true, false><<<GRID, 512, SMEM_F>>>(
        nodeB, W1h, W1l, W2h, W2l, nullptr, nullptr,
        bfb, init_b2, nullptr, nodeA, nodeC, NN, tilesN);

    // ---- node layer 1 -------------------------------------------------------
    scatter_add4_kernel<<<scO, 256>>>(ei_orig, ei_orig + EO, nodeA, nodeC, EO);
    fused_gin<true, false, false><<<GRID, 512, SMEM_F>>>(
        nodeC, W1h + WSZ, W1l + WSZ, W2h + WSZ, W2l + WSZ, nullptr, nullptr,
        bfb + HD, init_b2 + HD, nullptr, nodeD, nullptr, NN, tilesN);

    // ---- node MLP -------------------------------------------------------------
    fused_gin<false, false, false><<<GRID, 512, SMEM_F>>>(
        nodeD, W1h + 2 * WSZ, W1l + 2 * WSZ, W2h + 2 * WSZ, W2l + 2 * WSZ,
        nullptr, nullptr, bfb + 2 * HD, mlp_b2, nullptr, nodeA, nullptr, NN, tilesN);

    // ---- pair lift -------------------------------------------------------------
    pair_gather2_kernel<<<scO, 256>>>(edge_pairs, nodeA, edgeA, edgeB, EO);

    // ---- edge layer 0 -----------------------------------------------------------
    scatter_add4_kernel<<<scL, 256>>>(edge_index, edge_index + EL, edgeA, edgeB, EL);
    fused_gin<true, true, false><<<GRID, 512, SMEM_F>>>(
        edgeB, W1h + 3 * WSZ, W1l + 3 * WSZ, W2h + 3 * WSZ, W2l + 3 * WSZ,
        nullptr, nullptr, bfb + 3 * HD, gin_b2, nullptr, edgeA, edgeC, EO, tilesE);

    // ---- edge layer 1 + head ------------------------------------------------------
    scatter_add4_kernel<<<scL, 256>>>(edge_index, edge_index + EL, edgeA, edgeC, EL);
    fused_gin<true, false, true><<<GRID, 512, SMEM_F>>>(
        edgeC, W1h + 4 * WSZ, W1l + 4 * WSZ, W2h + 4 * WSZ, W2l + 4 * WSZ,
        (const uint4*)Wofh, (const uint4*)Wofl,
        bfb + 4 * HD, gin_b2 + HD, out_b, out, nullptr, EO, tilesE);
}

// round 7
// speedup vs baseline: 1.4368x; 1.0043x over previous
#include <cuda_runtime.h>
#include <cuda_bf16.h>
#include <cstdint>

#define NN 100000
#define EO 600000
#define EL 1200000
#define HD 128
#define OD 64
#define SA 136   // smem row stride (bf16) -> conflict-spread ldmatrix/stmatrix

// ---------------- scratch (device globals) ---------------------------------
static __device__ float g_nodeA[(size_t)NN * HD];
static __device__ float g_nodeB[(size_t)NN * HD];
static __device__ float g_nodeC[(size_t)NN * HD];
static __device__ float g_nodeD[(size_t)NN * HD];
static __device__ float g_edgeA[(size_t)EO * HD];
static __device__ float g_edgeB[(size_t)EO * HD];
static __device__ float g_edgeC[(size_t)EO * HD];
static __device__ __nv_bfloat16 g_W1h[5][HD * HD], g_W1l[5][HD * HD];
static __device__ __nv_bfloat16 g_W2h[5][HD * HD], g_W2l[5][HD * HD];
static __device__ uint32_t g_Wofh[4096], g_Wofl[4096];  // Wo in frag order
static __device__ float g_bfb[5][HD];

// ---------------- PTX helpers ----------------------------------------------
__device__ __forceinline__ void ldsm4(uint32_t* r, const void* p) {
    uint32_t a = (uint32_t)__cvta_generic_to_shared(p);
    asm volatile("ldmatrix.sync.aligned.m8n8.x4.shared.b16 {%0,%1,%2,%3}, [%4];"
                 : "=r"(r[0]), "=r"(r[1]), "=r"(r[2]), "=r"(r[3]) : "r"(a));
}
__device__ __forceinline__ void stsm4(void* p, uint32_t r0, uint32_t r1,
                                      uint32_t r2, uint32_t r3) {
    uint32_t a = (uint32_t)__cvta_generic_to_shared(p);
    asm volatile("stmatrix.sync.aligned.m8n8.x4.shared.b16 [%0], {%1,%2,%3,%4};"
                 :: "r"(a), "r"(r0), "r"(r1), "r"(r2), "r"(r3) : "memory");
}
__device__ __forceinline__ void mma_bf16(float* d, const uint32_t* a,
                                         uint32_t b0, uint32_t b1) {
    asm volatile(
        "mma.sync.aligned.m16n8k16.row.col.f32.bf16.bf16.f32 "
        "{%0,%1,%2,%3}, {%4,%5,%6,%7}, {%8,%9}, {%0,%1,%2,%3};"
        : "+f"(d[0]), "+f"(d[1]), "+f"(d[2]), "+f"(d[3])
        : "r"(a[0]), "r"(a[1]), "r"(a[2]), "r"(a[3]), "r"(b0), "r"(b1));
}
__device__ __forceinline__ uint32_t pack_hi(float a, float b) {
    __nv_bfloat162 t = __halves2bfloat162(__float2bfloat16(a), __float2bfloat16(b));
    return *(uint32_t*)&t;
}
__device__ __forceinline__ uint32_t pack_lo(float a, float b) {
    float ra = a - __bfloat162float(__float2bfloat16(a));
    float rb = b - __bfloat162float(__float2bfloat16(b));
    __nv_bfloat162 t = __halves2bfloat162(__float2bfloat16(ra), __float2bfloat16(rb));
    return *(uint32_t*)&t;
}
// split a float4 into hi/lo bf16x2 pairs, one 8B store each
__device__ __forceinline__ void split_store4(float4 v, __nv_bfloat16* ph,
                                             __nv_bfloat16* pl) {
    *(uint2*)ph = make_uint2(pack_hi(v.x, v.y), pack_hi(v.z, v.w));
    *(uint2*)pl = make_uint2(pack_lo(v.x, v.y), pack_lo(v.z, v.w));
}
#define BARH(id) asm volatile("bar.sync %0, 256;" :: "r"(id) : "memory")

// one 64x128 @ 128x128 pass from smem; 8 warps/half, warp tile 32x32
__device__ __forceinline__ void gemm_pass(
    const __nv_bfloat16* As_h, const __nv_bfloat16* As_l,
    const __nv_bfloat16* Wh, const __nv_bfloat16* Wl,
    int rowBase, int colBase, int lrow, int lkoff, float (&acc)[2][4][4]) {
#pragma unroll
    for (int mi = 0; mi < 2; ++mi)
#pragma unroll
        for (int ni = 0; ni < 4; ++ni)
#pragma unroll
            for (int q = 0; q < 4; ++q) acc[mi][ni][q] = 0.f;
#pragma unroll
    for (int ks = 0; ks < 8; ++ks) {
        const int k0 = ks * 16 + lkoff;
        uint32_t ah[2][4], al[2][4];
#pragma unroll
        for (int mi = 0; mi < 2; ++mi) {
            const int base = (rowBase + mi * 16 + lrow) * SA + k0;
            ldsm4(ah[mi], As_h + base);
            ldsm4(al[mi], As_l + base);
        }
        uint32_t bh[2][4], bl[2][4];
#pragma unroll
        for (int nj = 0; nj < 2; ++nj) {
            const int base = (colBase + nj * 16 + lrow) * SA + k0;
            ldsm4(bh[nj], Wh + base);
            ldsm4(bl[nj], Wl + base);
        }
#pragma unroll
        for (int mi = 0; mi < 2; ++mi)
#pragma unroll
            for (int ni = 0; ni < 4; ++ni) {
                const int nj = ni >> 1, hh = ni & 1;
                mma_bf16(acc[mi][ni], ah[mi], bh[nj][hh], bh[nj][hh + 2]);
                mma_bf16(acc[mi][ni], ah[mi], bl[nj][hh], bl[nj][hh + 2]);
                mma_bf16(acc[mi][ni], al[mi], bh[nj][hh], bh[nj][hh + 2]);
            }
    }
}

// bias+relu then stmatrix both splits back into As (used for h1 and h2)
__device__ __forceinline__ void epi_to_smem(
    const float (&acc)[2][4][4], const float (&br)[4][2],
    __nv_bfloat16* As_h, __nv_bfloat16* As_l,
    int rowBase, int colBase, int lane) {
    const int srow = (lane & 7) + ((lane >> 3) & 1) * 8;
    const int scol = (lane >> 4) * 8;
#pragma unroll
    for (int mi = 0; mi < 2; ++mi) {
#pragma unroll
        for (int ng = 0; ng < 2; ++ng) {
            float v[2][4];
#pragma unroll
            for (int q = 0; q < 2; ++q) {
                const int ni = ng * 2 + q;
                v[q][0] = fmaxf(acc[mi][ni][0] + br[ni][0], 0.f);
                v[q][1] = fmaxf(acc[mi][ni][1] + br[ni][1], 0.f);
                v[q][2] = fmaxf(acc[mi][ni][2] + br[ni][0], 0.f);
                v[q][3] = fmaxf(acc[mi][ni][3] + br[ni][1], 0.f);
            }
            const int off = (rowBase + mi * 16 + srow) * SA + colBase + ng * 16 + scol;
            stsm4(As_h + off, pack_hi(v[0][0], v[0][1]), pack_hi(v[0][2], v[0][3]),
                  pack_hi(v[1][0], v[1][1]), pack_hi(v[1][2], v[1][3]));
            stsm4(As_l + off, pack_lo(v[0][0], v[0][1]), pack_lo(v[0][2], v[0][3]),
                  pack_lo(v[1][0], v[1][1]), pack_lo(v[1][2], v[1][3]));
        }
    }
}

// ---------------- fused GIN layer: persistent, two independent halves ------
template <bool RELU2, bool DUAL, bool HEAD>
__global__ __launch_bounds__(512, 1) void fused_gin(
    const float* __restrict__ A,
    const __nv_bfloat16* __restrict__ W1hI, const __nv_bfloat16* __restrict__ W1lI,
    const __nv_bfloat16* __restrict__ W2hI, const __nv_bfloat16* __restrict__ W2lI,
    const uint4* __restrict__ WoFh, const uint4* __restrict__ WoFl,
    const float* __restrict__ b1, const float* __restrict__ b2,
    const float* __restrict__ b3,
    float* __restrict__ C, float* __restrict__ C2, int M, int nTiles) {
    extern __shared__ char smem[];
    const int tid = threadIdx.x, lane = tid & 31, wid = tid >> 5;
    const int half = wid >> 3, wl = wid & 7;

    __nv_bfloat16* As_h = (__nv_bfloat16*)(smem + half * 2 * 17408);
    __nv_bfloat16* As_l = (__nv_bfloat16*)(smem + half * 2 * 17408 + 17408);
    __nv_bfloat16* Wah = (__nv_bfloat16*)(smem + 69632);
    __nv_bfloat16* Wal = (__nv_bfloat16*)(smem + 104448);
    __nv_bfloat16* Wbh = (__nv_bfloat16*)(smem + 139264);
    __nv_bfloat16* Wbl = (__nv_bfloat16*)(smem + 174080);

    // stage W once per CTA
    {
        const uint4* s1 = (const uint4*)W1hI;
        const uint4* s2 = (const uint4*)W1lI;
        const uint4* s3 = (const uint4*)W2hI;
        const uint4* s4 = (const uint4*)W2lI;
        for (int i = tid; i < 2048; i += 512) {
            int r = i >> 4, c = i & 15;
            *(uint4*)(Wah + r * SA + c * 8) = s1[i];
            *(uint4*)(Wal + r * SA + c * 8) = s2[i];
            *(uint4*)(Wbh + r * SA + c * 8) = s3[i];
            *(uint4*)(Wbl + r * SA + c * 8) = s4[i];
        }
    }
    __syncthreads();

    const int barid = 1 + half;
    const int rowBase = (wl >> 2) * 32, colBase = (wl & 3) * 32;
    const int lrow = lane & 15, lkoff = (lane >> 4) * 8;
    const int cq = (lane & 3) * 2, rq = lane >> 2;
    const int cc = wl & 3;

    // hoist biases into registers (persistent kernel)
    float b1r[4][2], b2r[4][2], b3r[2][2];
#pragma unroll
    for (int ni = 0; ni < 4; ++ni) {
        const int col = colBase + ni * 8 + cq;
        b1r[ni][0] = b1[col]; b1r[ni][1] = b1[col + 1];
        b2r[ni][0] = b2[col]; b2r[ni][1] = b2[col + 1];
    }
    if (HEAD) {
#pragma unroll
        for (int ni = 0; ni < 2; ++ni) {
            const int col = cc * 16 + ni * 8 + cq;
            b3r[ni][0] = b3[col]; b3r[ni][1] = b3[col + 1];
        }
    }

    for (int tile = blockIdx.x * 2 + half; tile < nTiles; tile += gridDim.x * 2) {
        const int m0 = tile * 64;
        BARH(barid);   // previous iteration's As readers done

        // ---- A tile build: 8 warps x 8 rows, 8B split stores --------------
#pragma unroll
        for (int rr = 0; rr < 8; ++rr) {
            const int r = wl * 8 + rr;
            const int row = m0 + r;
            float4 v = make_float4(0.f, 0.f, 0.f, 0.f);
            if (row < M) v = ((const float4*)A)[(size_t)row * 32 + lane];
            split_store4(v, As_h + r * SA + lane * 4, As_l + r * SA + lane * 4);
        }
        BARH(barid);

        float acc[2][4][4];
        gemm_pass(As_h, As_l, Wah, Wal, rowBase, colBase, lrow, lkoff, acc);
        BARH(barid);   // all As reads done before overwrite

        epi_to_smem(acc, b1r, As_h, As_l, rowBase, colBase, lane);
        BARH(barid);

        gemm_pass(As_h, As_l, Wbh, Wbl, rowBase, colBase, lrow, lkoff, acc);

        if (!HEAD) {
#pragma unroll
            for (int mi = 0; mi < 2; ++mi)
#pragma unroll
                for (int ni = 0; ni < 4; ++ni) {
                    const int col = colBase + ni * 8 + cq;
                    const int r0 = m0 + rowBase + mi * 16 + rq, r1 = r0 + 8;
                    float v00 = acc[mi][ni][0] + b2r[ni][0];
                    float v01 = acc[mi][ni][1] + b2r[ni][1];
                    float v10 = acc[mi][ni][2] + b2r[ni][0];
                    float v11 = acc[mi][ni][3] + b2r[ni][1];
                    if (RELU2) {
                        v00 = fmaxf(v00, 0.f); v01 = fmaxf(v01, 0.f);
                        v10 = fmaxf(v10, 0.f); v11 = fmaxf(v11, 0.f);
                    }
                    if (r0 < M) {
                        *(float2*)(C + (size_t)r0 * HD + col) = make_float2(v00, v01);
                        if (DUAL)
                            *(float2*)(C2 + (size_t)r0 * HD + col) = make_float2(v00, v01);
                    }
                    if (r1 < M) {
                        *(float2*)(C + (size_t)r1 * HD + col) = make_float2(v10, v11);
                        if (DUAL)
                            *(float2*)(C2 + (size_t)r1 * HD + col) = make_float2(v10, v11);
                    }
                }
        } else {
            BARH(barid);   // pass2 As reads done
            epi_to_smem(acc, b2r, As_h, As_l, rowBase, colBase, lane);
            BARH(barid);

            // pass 3: h2 @ Wo, B fragments straight from gmem (L2-resident)
            float acc3[2][2][4];
#pragma unroll
            for (int mi = 0; mi < 2; ++mi)
#pragma unroll
                for (int ni = 0; ni < 2; ++ni)
#pragma unroll
                    for (int q = 0; q < 4; ++q) acc3[mi][ni][q] = 0.f;
#pragma unroll
            for (int ks = 0; ks < 8; ++ks) {
                const int k0 = ks * 16 + lkoff;
                uint32_t ah[2][4], al[2][4];
#pragma unroll
                for (int mi = 0; mi < 2; ++mi) {
                    const int base = (rowBase + mi * 16 + lrow) * SA + k0;
                    ldsm4(ah[mi], As_h + base);
                    ldsm4(al[mi], As_l + base);
                }
                const uint4 bh = WoFh[(cc * 8 + ks) * 32 + lane];
                const uint4 bl = WoFl[(cc * 8 + ks) * 32 + lane];
#pragma unroll
                for (int mi = 0; mi < 2; ++mi) {
                    mma_bf16(acc3[mi][0], ah[mi], bh.x, bh.z);
                    mma_bf16(acc3[mi][0], ah[mi], bl.x, bl.z);
                    mma_bf16(acc3[mi][0], al[mi], bh.x, bh.z);
                    mma_bf16(acc3[mi][1], ah[mi], bh.y, bh.w);
                    mma_bf16(acc3[mi][1], ah[mi], bl.y, bl.w);
                    mma_bf16(acc3[mi][1], al[mi], bh.y, bh.w);
                }
            }
#pragma unroll
            for (int mi = 0; mi < 2; ++mi)
#pragma unroll
                for (int ni = 0; ni < 2; ++ni) {
                    const int col = cc * 16 + ni * 8 + cq;
                    const int r0 = m0 + rowBase + mi * 16 + rq, r1 = r0 + 8;
                    if (r0 < M)
                        *(float2*)(C + (size_t)r0 * OD + col) = make_float2(
                            acc3[mi][ni][0] + b3r[ni][0], acc3[mi][ni][1] + b3r[ni][1]);
                    if (r1 < M)
                        *(float2*)(C + (size_t)r1 * OD + col) = make_float2(
                            acc3[mi][ni][2] + b3r[ni][0], acc3[mi][ni][3] + b3r[ni][1]);
                }
        }
    }
}

// ---------------- weight prep ------------------------------------------------
struct PrepArgs {
    const float *W1[5], *b1[5], *g[5], *bb[5], *m[5], *v[5], *W2[5], *Wo;
    __nv_bfloat16 *W1h[5], *W1l[5], *W2h[5], *W2l[5];
    uint32_t *Wofh, *Wofl;
    float* bf[5];
};

__global__ void prep_weights(PrepArgs a) {
    const int blk = blockIdx.x, tid = threadIdx.x;
    if (blk < 320) {                        // BN-fold W1 (5 jobs)
        const int j = blk >> 6;
        const int idx = ((blk & 63) << 8) + tid;
        const int k = idx >> 7, n = idx & 127;
        float s = a.g[j][n] * rsqrtf(a.v[j][n] + 1e-5f);
        float val = a.W1[j][idx] * s;
        __nv_bfloat16 h = __float2bfloat16(val);
        a.W1h[j][n * 128 + k] = h;
        a.W1l[j][n * 128 + k] = __float2bfloat16(val - __bfloat162float(h));
        if (idx < 128)
            a.bf[j][idx] = a.b1[j][idx] * s + a.bb[j][idx] - a.m[j][idx] * s;
    } else if (blk < 640) {                 // W2 (5 jobs)
        const int j = (blk - 320) >> 6;
        const int idx = (((blk - 320) & 63) << 8) + tid;
        const int k = idx >> 7, n = idx & 127;
        float val = a.W2[j][idx];
        __nv_bfloat16 h = __float2bfloat16(val);
        a.W2h[j][n * 128 + k] = h;
        a.W2l[j][n * 128 + k] = __float2bfloat16(val - __bfloat162float(h));
    } else {                                // Wo -> ldmatrix fragment order
        const int idx = ((blk - 640) << 8) + tid;  // 0..4095
        const int j = idx & 3, L = (idx >> 2) & 31;
        const int ks = (idx >> 7) & 7, cc = idx >> 10;
        const int n = cc * 16 + (j & 1) * 8 + (L >> 2);
        const int k = ks * 16 + ((j >> 1)) * 8 + (L & 3) * 2;
        float v0 = a.Wo[k * OD + n];
        float v1 = a.Wo[(k + 1) * OD + n];
        a.Wofh[((cc * 8 + ks) * 32 + L) * 4 + j] = pack_hi(v0, v1);
        a.Wofl[((cc * 8 + ks) * 32 + L) * 4 + j] = pack_lo(v0, v1);
    }
}

// ---------------- graph kernels -----------------------------------------------
__global__ void copy4_kernel(const float4* __restrict__ s,
                             float4* __restrict__ d, int n) {
    int i = blockIdx.x * 256 + threadIdx.x;
    if (i < n) d[i] = s[i];
}

__global__ void scatter_add4_kernel(const int* __restrict__ srcs,
                                    const int* __restrict__ dsts,
                                    const float* __restrict__ x,
                                    float* __restrict__ agg, int E) {
    unsigned t = blockIdx.x * 256u + threadIdx.x;
    unsigned e = t >> 5, lane = t & 31u;
    if (e >= (unsigned)E) return;
    int s = srcs[e], d = dsts[e];
    float4 v = ((const float4*)(x + (size_t)s * HD))[lane];
    float* dp = agg + (size_t)d * HD + lane * 4;
    asm volatile("red.global.add.v4.f32 [%0], {%1,%2,%3,%4};" ::"l"(dp),
                 "f"(v.x), "f"(v.y), "f"(v.z), "f"(v.w)
                 : "memory");
}

__global__ void pair_gather2_kernel(const int* __restrict__ ep,
                                    const float* __restrict__ y,
                                    float* __restrict__ h,
                                    float* __restrict__ hagg, int E) {
    unsigned t = blockIdx.x * 256u + threadIdx.x;
    unsigned e = t >> 5, lane = t & 31u;
    if (e >= (unsigned)E) return;
    int i0 = ep[2 * e], i1 = ep[2 * e + 1];
    float4 a = ((const float4*)(y + (size_t)i0 * HD))[lane];
    float4 b = ((const float4*)(y + (size_t)i1 * HD))[lane];
    a.x += b.x; a.y += b.y; a.z += b.z; a.w += b.w;
    ((float4*)(h + (size_t)e * HD))[lane] = a;
    ((float4*)(hagg + (size_t)e * HD))[lane] = a;
}

// --------------------------------------------------------------------------------
extern "C" void kernel_launch(void* const* d_in, const int* in_sizes, int n_in,
                              void* d_out, int out_size) {
    const int*   edge_index = (const int*)d_in[0];
    const float* x_orig     = (const float*)d_in[1];
    const int*   ei_orig    = (const int*)d_in[2];
    const int*   edge_pairs = (const int*)d_in[3];
    const float* init_W1 = (const float*)d_in[4];
    const float* init_b1 = (const float*)d_in[5];
    const float* init_g  = (const float*)d_in[6];
    const float* init_bb = (const float*)d_in[7];
    const float* init_m  = (const float*)d_in[8];
    const float* init_v  = (const float*)d_in[9];
    const float* init_W2 = (const float*)d_in[10];
    const float* init_b2 = (const float*)d_in[11];
    const float* gin_W1  = (const float*)d_in[12];
    const float* gin_b1  = (const float*)d_in[13];
    const float* gin_g   = (const float*)d_in[14];
    const float* gin_bb  = (const float*)d_in[15];
    const float* gin_m   = (const float*)d_in[16];
    const float* gin_v   = (const float*)d_in[17];
    const float* gin_W2  = (const float*)d_in[18];
    const float* gin_b2  = (const float*)d_in[19];
    const float* mlp_W1  = (const float*)d_in[20];
    const float* mlp_b1  = (const float*)d_in[21];
    const float* mlp_g   = (const float*)d_in[22];
    const float* mlp_bb  = (const float*)d_in[23];
    const float* mlp_m   = (const float*)d_in[24];
    const float* mlp_v   = (const float*)d_in[25];
    const float* mlp_W2  = (const float*)d_in[26];
    const float* mlp_b2  = (const float*)d_in[27];
    const float* out_W   = (const float*)d_in[28];
    const float* out_b   = (const float*)d_in[29];
    float* out = (float*)d_out;

    float *nodeA, *nodeB, *nodeC, *nodeD, *edgeA, *edgeB, *edgeC, *bfb;
    __nv_bfloat16 *W1h, *W1l, *W2h, *W2l;
    uint32_t *Wofh, *Wofl;
    cudaGetSymbolAddress((void**)&nodeA, g_nodeA);
    cudaGetSymbolAddress((void**)&nodeB, g_nodeB);
    cudaGetSymbolAddress((void**)&nodeC, g_nodeC);
    cudaGetSymbolAddress((void**)&nodeD, g_nodeD);
    cudaGetSymbolAddress((void**)&edgeA, g_edgeA);
    cudaGetSymbolAddress((void**)&edgeB, g_edgeB);
    cudaGetSymbolAddress((void**)&edgeC, g_edgeC);
    cudaGetSymbolAddress((void**)&bfb, g_bfb);
    cudaGetSymbolAddress((void**)&W1h, g_W1h);
    cudaGetSymbolAddress((void**)&W1l, g_W1l);
    cudaGetSymbolAddress((void**)&W2h, g_W2h);
    cudaGetSymbolAddress((void**)&W2l, g_W2l);
    cudaGetSymbolAddress((void**)&Wofh, g_Wofh);
    cudaGetSymbolAddress((void**)&Wofl, g_Wofl);

    // weight prep
    PrepArgs pa;
    const float* W1s[5]  = {init_W1, init_W1 + HD * HD, mlp_W1, gin_W1, gin_W1 + HD * HD};
    const float* b1s[5]  = {init_b1, init_b1 + HD, mlp_b1, gin_b1, gin_b1 + HD};
    const float* gs[5]   = {init_g, init_g + HD, mlp_g, gin_g, gin_g + HD};
    const float* bbs[5]  = {init_bb, init_bb + HD, mlp_bb, gin_bb, gin_bb + HD};
    const float* ms[5]   = {init_m, init_m + HD, mlp_m, gin_m, gin_m + HD};
    const float* vs[5]   = {init_v, init_v + HD, mlp_v, gin_v, gin_v + HD};
    const float* W2s[5]  = {init_W2, init_W2 + HD * HD, mlp_W2, gin_W2, gin_W2 + HD * HD};
    for (int j = 0; j < 5; ++j) {
        pa.W1[j] = W1s[j]; pa.b1[j] = b1s[j]; pa.g[j] = gs[j]; pa.bb[j] = bbs[j];
        pa.m[j] = ms[j]; pa.v[j] = vs[j]; pa.W2[j] = W2s[j];
        pa.W1h[j] = W1h + (size_t)j * HD * HD; pa.W1l[j] = W1l + (size_t)j * HD * HD;
        pa.W2h[j] = W2h + (size_t)j * HD * HD; pa.W2l[j] = W2l + (size_t)j * HD * HD;
        pa.bf[j] = bfb + j * HD;
    }
    pa.Wo = out_W; pa.Wofh = Wofh; pa.Wofl = Wofl;
    prep_weights<<<656, 256>>>(pa);

    const int SMEM_F = 208896;
    cudaFuncSetAttribute(fused_gin<true, true, false>,
                         cudaFuncAttributeMaxDynamicSharedMemorySize, SMEM_F);
    cudaFuncSetAttribute(fused_gin<true, false, false>,
                         cudaFuncAttributeMaxDynamicSharedMemorySize, SMEM_F);
    cudaFuncSetAttribute(fused_gin<false, false, false>,
                         cudaFuncAttributeMaxDynamicSharedMemorySize, SMEM_F);
    cudaFuncSetAttribute(fused_gin<true, false, true>,
                         cudaFuncAttributeMaxDynamicSharedMemorySize, SMEM_F);

    const int GRID = 148;                   // persistent, 1 CTA/SM
    const int tilesN = (NN + 63) / 64;      // 1563
    const int tilesE = (EO + 63) / 64;      // 9375
    const int cpN = (NN * 32 + 255) / 256;
    const int scO = ((unsigned)EO * 32u + 255u) / 256u;
    const int scL = ((unsigned)EL * 32u + 255u) / 256u;
    const size_t WSZ = (size_t)HD * HD;

    // ---- node layer 0 -------------------------------------------------------
    copy4_kernel<<<cpN, 256>>>((const float4*)x_orig, (float4*)nodeB, NN * 32);
    scatter_add4_kernel<<<scO, 256>>>(ei_orig, ei_orig + EO, x_orig, nodeB, EO);
    fused_gin<true, true, false><<<GRID, 512, SMEM_F>>>(
        nodeB, W1h, W1l, W2h, W2l, nullptr, nullptr,
        bfb, init_b2, nullptr, nodeA, nodeC, NN, tilesN);

    // ---- node layer 1 -------------------------------------------------------
    scatter_add4_kernel<<<scO, 256>>>(ei_orig, ei_orig + EO, nodeA, nodeC, EO);
    fused_gin<true, false, false><<<GRID, 512, SMEM_F>>>(
        nodeC, W1h + WSZ, W1l + WSZ, W2h + WSZ, W2l + WSZ, nullptr, nullptr,
        bfb + HD, init_b2 + HD, nullptr, nodeD, nullptr, NN, tilesN);

    // ---- node MLP -------------------------------------------------------------
    fused_gin<false, false, false><<<GRID, 512, SMEM_F>>>(
        nodeD, W1h + 2 * WSZ, W1l + 2 * WSZ, W2h + 2 * WSZ, W2l + 2 * WSZ,
        nullptr, nullptr, bfb + 2 * HD, mlp_b2, nullptr, nodeA, nullptr, NN, tilesN);

    // ---- pair lift -------------------------------------------------------------
    pair_gather2_kernel<<<scO, 256>>>(edge_pairs, nodeA, edgeA, edgeB, EO);

    // ---- edge layer 0 -----------------------------------------------------------
    scatter_add4_kernel<<<scL, 256>>>(edge_index, edge_index + EL, edgeA, edgeB, EL);
    fused_gin<true, true, false><<<GRID, 512, SMEM_F>>>(
        edgeB, W1h + 3 * WSZ, W1l + 3 * WSZ, W2h + 3 * WSZ, W2l + 3 * WSZ,
        nullptr, nullptr, bfb + 3 * HD, gin_b2, nullptr, edgeA, edgeC, EO, tilesE);

    // ---- edge layer 1 + head ------------------------------------------------------
    scatter_add4_kernel<<<scL, 256>>>(edge_index, edge_index + EL, edgeA, edgeC, EL);
    fused_gin<true, false, true><<<GRID, 512, SMEM_F>>>(
        edgeC, W1h + 4 * WSZ, W1l + 4 * WSZ, W2h + 4 * WSZ, W2l + 4 * WSZ,
        (const uint4*)Wofh, (const uint4*)Wofl,
        bfb + 4 * HD, gin_b2 + HD, out_b, out, nullptr, EO, tilesE);
}

// round 8
// speedup vs baseline: 1.5775x; 1.0979x over previous
#include <cuda_runtime.h>
#include <cuda_bf16.h>
#include <cstdint>

#define NN 100000
#define EO 600000
#define EL 1200000
#define HD 128
#define OD 64
#define SA 136   // smem row stride (bf16) -> conflict-spread ldmatrix/stmatrix

// ---------------- scratch (device globals) ---------------------------------
static __device__ float g_nodeA[(size_t)NN * HD];
static __device__ float g_nodeB[(size_t)NN * HD];
static __device__ float g_nodeC[(size_t)NN * HD];
static __device__ float g_nodeD[(size_t)NN * HD];
static __device__ float g_edgeA[(size_t)EO * HD];
static __device__ float g_edgeB[(size_t)EO * HD];
static __device__ float g_edgeC[(size_t)EO * HD];
static __device__ __nv_bfloat16 g_W1h[5][HD * HD], g_W1l[5][HD * HD];
static __device__ __nv_bfloat16 g_W2h[5][HD * HD], g_W2l[5][HD * HD];
static __device__ uint32_t g_Wofh[4096], g_Wofl[4096];   // Wo frags (N=64)
static __device__ uint32_t g_F1h[8192], g_F1l[8192];     // mlp W1 frags (N=128)
static __device__ uint32_t g_F2h[8192], g_F2l[8192];     // mlp W2 frags
static __device__ float g_bfb[5][HD];
// CSR scratch
static __device__ int g_deg[EO], g_ex[EO], g_bsum[1024];
static __device__ int g_rpN[NN + 1], g_adjN[EO], g_curN[NN];
static __device__ int g_rpE[EO + 1], g_adjE[EL], g_curE[EO];

// ---------------- PTX helpers ----------------------------------------------
__device__ __forceinline__ void ldsm4(uint32_t* r, const void* p) {
    uint32_t a = (uint32_t)__cvta_generic_to_shared(p);
    asm volatile("ldmatrix.sync.aligned.m8n8.x4.shared.b16 {%0,%1,%2,%3}, [%4];"
                 : "=r"(r[0]), "=r"(r[1]), "=r"(r[2]), "=r"(r[3]) : "r"(a));
}
__device__ __forceinline__ void stsm4(void* p, uint32_t r0, uint32_t r1,
                                      uint32_t r2, uint32_t r3) {
    uint32_t a = (uint32_t)__cvta_generic_to_shared(p);
    asm volatile("stmatrix.sync.aligned.m8n8.x4.shared.b16 [%0], {%1,%2,%3,%4};"
                 :: "r"(a), "r"(r0), "r"(r1), "r"(r2), "r"(r3) : "memory");
}
__device__ __forceinline__ void mma_bf16(float* d, const uint32_t* a,
                                         uint32_t b0, uint32_t b1) {
    asm volatile(
        "mma.sync.aligned.m16n8k16.row.col.f32.bf16.bf16.f32 "
        "{%0,%1,%2,%3}, {%4,%5,%6,%7}, {%8,%9}, {%0,%1,%2,%3};"
        : "+f"(d[0]), "+f"(d[1]), "+f"(d[2]), "+f"(d[3])
        : "r"(a[0]), "r"(a[1]), "r"(a[2]), "r"(a[3]), "r"(b0), "r"(b1));
}
__device__ __forceinline__ uint32_t pack_hi(float a, float b) {
    __nv_bfloat162 t = __halves2bfloat162(__float2bfloat16(a), __float2bfloat16(b));
    return *(uint32_t*)&t;
}
__device__ __forceinline__ uint32_t pack_lo(float a, float b) {
    float ra = a - __bfloat162float(__float2bfloat16(a));
    float rb = b - __bfloat162float(__float2bfloat16(b));
    __nv_bfloat162 t = __halves2bfloat162(__float2bfloat16(ra), __float2bfloat16(rb));
    return *(uint32_t*)&t;
}
__device__ __forceinline__ void split_store4(float4 v, __nv_bfloat16* ph,
                                             __nv_bfloat16* pl) {
    *(uint2*)ph = make_uint2(pack_hi(v.x, v.y), pack_hi(v.z, v.w));
    *(uint2*)pl = make_uint2(pack_lo(v.x, v.y), pack_lo(v.z, v.w));
}
#define BARH(id) asm volatile("bar.sync %0, 256;" :: "r"(id) : "memory")

// ---------------- GEMM passes ------------------------------------------------
__device__ __forceinline__ void gemm_pass(
    const __nv_bfloat16* As_h, const __nv_bfloat16* As_l,
    const __nv_bfloat16* Wh, const __nv_bfloat16* Wl,
    int rowBase, int colBase, int lrow, int lkoff, float (&acc)[2][4][4]) {
#pragma unroll
    for (int mi = 0; mi < 2; ++mi)
#pragma unroll
        for (int ni = 0; ni < 4; ++ni)
#pragma unroll
            for (int q = 0; q < 4; ++q) acc[mi][ni][q] = 0.f;
#pragma unroll
    for (int ks = 0; ks < 8; ++ks) {
        const int k0 = ks * 16 + lkoff;
        uint32_t ah[2][4], al[2][4];
#pragma unroll
        for (int mi = 0; mi < 2; ++mi) {
            const int base = (rowBase + mi * 16 + lrow) * SA + k0;
            ldsm4(ah[mi], As_h + base);
            ldsm4(al[mi], As_l + base);
        }
        uint32_t bh[2][4], bl[2][4];
#pragma unroll
        for (int nj = 0; nj < 2; ++nj) {
            const int base = (colBase + nj * 16 + lrow) * SA + k0;
            ldsm4(bh[nj], Wh + base);
            ldsm4(bl[nj], Wl + base);
        }
#pragma unroll
        for (int mi = 0; mi < 2; ++mi)
#pragma unroll
            for (int ni = 0; ni < 4; ++ni) {
                const int nj = ni >> 1, hh = ni & 1;
                mma_bf16(acc[mi][ni], ah[mi], bh[nj][hh], bh[nj][hh + 2]);
                mma_bf16(acc[mi][ni], ah[mi], bl[nj][hh], bl[nj][hh + 2]);
                mma_bf16(acc[mi][ni], al[mi], bh[nj][hh], bh[nj][hh + 2]);
            }
    }
}

// B fragments from gmem (N=128 per CTA; warp covers cols cc*32..cc*32+31)
__device__ __forceinline__ void gemm_pass_frag(
    const __nv_bfloat16* As_h, const __nv_bfloat16* As_l,
    const uint4* __restrict__ Fh, const uint4* __restrict__ Fl,
    int rowBase, int cc, int lrow, int lkoff, int lane, float (&acc)[2][4][4]) {
#pragma unroll
    for (int mi = 0; mi < 2; ++mi)
#pragma unroll
        for (int ni = 0; ni < 4; ++ni)
#pragma unroll
            for (int q = 0; q < 4; ++q) acc[mi][ni][q] = 0.f;
#pragma unroll
    for (int ks = 0; ks < 8; ++ks) {
        const int k0 = ks * 16 + lkoff;
        uint32_t ah[2][4], al[2][4];
#pragma unroll
        for (int mi = 0; mi < 2; ++mi) {
            const int base = (rowBase + mi * 16 + lrow) * SA + k0;
            ldsm4(ah[mi], As_h + base);
            ldsm4(al[mi], As_l + base);
        }
#pragma unroll
        for (int nj = 0; nj < 2; ++nj) {
            const uint4 bh = Fh[((cc * 2 + nj) * 8 + ks) * 32 + lane];
            const uint4 bl = Fl[((cc * 2 + nj) * 8 + ks) * 32 + lane];
#pragma unroll
            for (int mi = 0; mi < 2; ++mi) {
                const int n0 = nj * 2;
                mma_bf16(acc[mi][n0], ah[mi], bh.x, bh.z);
                mma_bf16(acc[mi][n0], ah[mi], bl.x, bl.z);
                mma_bf16(acc[mi][n0], al[mi], bh.x, bh.z);
                mma_bf16(acc[mi][n0 + 1], ah[mi], bh.y, bh.w);
                mma_bf16(acc[mi][n0 + 1], ah[mi], bl.y, bl.w);
                mma_bf16(acc[mi][n0 + 1], al[mi], bh.y, bh.w);
            }
        }
    }
}

// bias+relu then stmatrix both splits back into As
__device__ __forceinline__ void epi_to_smem(
    const float (&acc)[2][4][4], const float (&br)[4][2],
    __nv_bfloat16* As_h, __nv_bfloat16* As_l,
    int rowBase, int colBase, int lane) {
    const int srow = (lane & 7) + ((lane >> 3) & 1) * 8;
    const int scol = (lane >> 4) * 8;
#pragma unroll
    for (int mi = 0; mi < 2; ++mi) {
#pragma unroll
        for (int ng = 0; ng < 2; ++ng) {
            float v[2][4];
#pragma unroll
            for (int q = 0; q < 2; ++q) {
                const int ni = ng * 2 + q;
                v[q][0] = fmaxf(acc[mi][ni][0] + br[ni][0], 0.f);
                v[q][1] = fmaxf(acc[mi][ni][1] + br[ni][1], 0.f);
                v[q][2] = fmaxf(acc[mi][ni][2] + br[ni][0], 0.f);
                v[q][3] = fmaxf(acc[mi][ni][3] + br[ni][1], 0.f);
            }
            const int off = (rowBase + mi * 16 + srow) * SA + colBase + ng * 16 + scol;
            stsm4(As_h + off, pack_hi(v[0][0], v[0][1]), pack_hi(v[0][2], v[0][3]),
                  pack_hi(v[1][0], v[1][1]), pack_hi(v[1][2], v[1][3]));
            stsm4(As_l + off, pack_lo(v[0][0], v[0][1]), pack_lo(v[0][2], v[0][3]),
                  pack_lo(v[1][0], v[1][1]), pack_lo(v[1][2], v[1][3]));
        }
    }
}

// gmem write: acc + bias (+relu) -> C [M,HD]
template <bool RELU>
__device__ __forceinline__ void write_out128(
    const float (&acc)[2][4][4], const float (&br)[4][2],
    float* __restrict__ C, int m0, int rowBase, int colBase,
    int cq, int rq, int M) {
#pragma unroll
    for (int mi = 0; mi < 2; ++mi)
#pragma unroll
        for (int ni = 0; ni < 4; ++ni) {
            const int col = colBase + ni * 8 + cq;
            const int r0 = m0 + rowBase + mi * 16 + rq, r1 = r0 + 8;
            float v00 = acc[mi][ni][0] + br[ni][0];
            float v01 = acc[mi][ni][1] + br[ni][1];
            float v10 = acc[mi][ni][2] + br[ni][0];
            float v11 = acc[mi][ni][3] + br[ni][1];
            if (RELU) {
                v00 = fmaxf(v00, 0.f); v01 = fmaxf(v01, 0.f);
                v10 = fmaxf(v10, 0.f); v11 = fmaxf(v11, 0.f);
            }
            if (r0 < M) *(float2*)(C + (size_t)r0 * HD + col) = make_float2(v00, v01);
            if (r1 < M) *(float2*)(C + (size_t)r1 * HD + col) = make_float2(v10, v11);
        }
}

// ---------------- fused GIN layer (2 passes, optional head pass) -----------
template <bool HEAD>
__global__ __launch_bounds__(512, 1) void fused_gin(
    const float* __restrict__ A,
    const __nv_bfloat16* __restrict__ W1hI, const __nv_bfloat16* __restrict__ W1lI,
    const __nv_bfloat16* __restrict__ W2hI, const __nv_bfloat16* __restrict__ W2lI,
    const uint4* __restrict__ WoFh, const uint4* __restrict__ WoFl,
    const float* __restrict__ b1, const float* __restrict__ b2,
    const float* __restrict__ b3,
    float* __restrict__ C, int M, int nTiles) {
    extern __shared__ char smem[];
    const int tid = threadIdx.x, lane = tid & 31, wid = tid >> 5;
    const int half = wid >> 3, wl = wid & 7;

    __nv_bfloat16* As_h = (__nv_bfloat16*)(smem + half * 2 * 17408);
    __nv_bfloat16* As_l = (__nv_bfloat16*)(smem + half * 2 * 17408 + 17408);
    __nv_bfloat16* Wah = (__nv_bfloat16*)(smem + 69632);
    __nv_bfloat16* Wal = (__nv_bfloat16*)(smem + 104448);
    __nv_bfloat16* Wbh = (__nv_bfloat16*)(smem + 139264);
    __nv_bfloat16* Wbl = (__nv_bfloat16*)(smem + 174080);

    {
        const uint4* s1 = (const uint4*)W1hI;
        const uint4* s2 = (const uint4*)W1lI;
        const uint4* s3 = (const uint4*)W2hI;
        const uint4* s4 = (const uint4*)W2lI;
        for (int i = tid; i < 2048; i += 512) {
            int r = i >> 4, c = i & 15;
            *(uint4*)(Wah + r * SA + c * 8) = s1[i];
            *(uint4*)(Wal + r * SA + c * 8) = s2[i];
            *(uint4*)(Wbh + r * SA + c * 8) = s3[i];
            *(uint4*)(Wbl + r * SA + c * 8) = s4[i];
        }
    }
    __syncthreads();

    const int barid = 1 + half;
    const int rowBase = (wl >> 2) * 32, colBase = (wl & 3) * 32;
    const int lrow = lane & 15, lkoff = (lane >> 4) * 8;
    const int cq = (lane & 3) * 2, rq = lane >> 2;
    const int cc = wl & 3;

    float b1r[4][2], b2r[4][2], b3r[2][2];
#pragma unroll
    for (int ni = 0; ni < 4; ++ni) {
        const int col = colBase + ni * 8 + cq;
        b1r[ni][0] = b1[col]; b1r[ni][1] = b1[col + 1];
        b2r[ni][0] = b2[col]; b2r[ni][1] = b2[col + 1];
    }
    if (HEAD) {
#pragma unroll
        for (int ni = 0; ni < 2; ++ni) {
            const int col = cc * 16 + ni * 8 + cq;
            b3r[ni][0] = b3[col]; b3r[ni][1] = b3[col + 1];
        }
    }

    for (int tile = blockIdx.x * 2 + half; tile < nTiles; tile += gridDim.x * 2) {
        const int m0 = tile * 64;
        BARH(barid);
#pragma unroll
        for (int rr = 0; rr < 8; ++rr) {
            const int r = wl * 8 + rr;
            const int row = m0 + r;
            float4 v = make_float4(0.f, 0.f, 0.f, 0.f);
            if (row < M) v = ((const float4*)A)[(size_t)row * 32 + lane];
            split_store4(v, As_h + r * SA + lane * 4, As_l + r * SA + lane * 4);
        }
        BARH(barid);

        float acc[2][4][4];
        gemm_pass(As_h, As_l, Wah, Wal, rowBase, colBase, lrow, lkoff, acc);
        BARH(barid);
        epi_to_smem(acc, b1r, As_h, As_l, rowBase, colBase, lane);
        BARH(barid);
        gemm_pass(As_h, As_l, Wbh, Wbl, rowBase, colBase, lrow, lkoff, acc);

        if (!HEAD) {
            write_out128<true>(acc, b2r, C, m0, rowBase, colBase, cq, rq, M);
        } else {
            BARH(barid);
            epi_to_smem(acc, b2r, As_h, As_l, rowBase, colBase, lane);
            BARH(barid);
            float acc3[2][2][4];
#pragma unroll
            for (int mi = 0; mi < 2; ++mi)
#pragma unroll
                for (int ni = 0; ni < 2; ++ni)
#pragma unroll
                    for (int q = 0; q < 4; ++q) acc3[mi][ni][q] = 0.f;
#pragma unroll
            for (int ks = 0; ks < 8; ++ks) {
                const int k0 = ks * 16 + lkoff;
                uint32_t ah[2][4], al[2][4];
#pragma unroll
                for (int mi = 0; mi < 2; ++mi) {
                    const int base = (rowBase + mi * 16 + lrow) * SA + k0;
                    ldsm4(ah[mi], As_h + base);
                    ldsm4(al[mi], As_l + base);
                }
                const uint4 bh = WoFh[(cc * 8 + ks) * 32 + lane];
                const uint4 bl = WoFl[(cc * 8 + ks) * 32 + lane];
#pragma unroll
                for (int mi = 0; mi < 2; ++mi) {
                    mma_bf16(acc3[mi][0], ah[mi], bh.x, bh.z);
                    mma_bf16(acc3[mi][0], ah[mi], bl.x, bl.z);
                    mma_bf16(acc3[mi][0], al[mi], bh.x, bh.z);
                    mma_bf16(acc3[mi][1], ah[mi], bh.y, bh.w);
                    mma_bf16(acc3[mi][1], ah[mi], bl.y, bl.w);
                    mma_bf16(acc3[mi][1], al[mi], bh.y, bh.w);
                }
            }
#pragma unroll
            for (int mi = 0; mi < 2; ++mi)
#pragma unroll
                for (int ni = 0; ni < 2; ++ni) {
                    const int col = cc * 16 + ni * 8 + cq;
                    const int r0 = m0 + rowBase + mi * 16 + rq, r1 = r0 + 8;
                    if (r0 < M)
                        *(float2*)(C + (size_t)r0 * OD + col) = make_float2(
                            acc3[mi][ni][0] + b3r[ni][0], acc3[mi][ni][1] + b3r[ni][1]);
                    if (r1 < M)
                        *(float2*)(C + (size_t)r1 * OD + col) = make_float2(
                            acc3[mi][ni][2] + b3r[ni][0], acc3[mi][ni][3] + b3r[ni][1]);
                }
        }
    }
}

// ---------------- fused node layer 1 + MLP (4 passes) ----------------------
__global__ __launch_bounds__(512, 1) void fused_gin_mlp(
    const float* __restrict__ A,
    const __nv_bfloat16* __restrict__ W1hI, const __nv_bfloat16* __restrict__ W1lI,
    const __nv_bfloat16* __restrict__ W2hI, const __nv_bfloat16* __restrict__ W2lI,
    const uint4* __restrict__ F1h, const uint4* __restrict__ F1l,
    const uint4* __restrict__ F2h, const uint4* __restrict__ F2l,
    const float* __restrict__ b1, const float* __restrict__ b2,
    const float* __restrict__ b3, const float* __restrict__ b4,
    float* __restrict__ C, int M, int nTiles) {
    extern __shared__ char smem[];
    const int tid = threadIdx.x, lane = tid & 31, wid = tid >> 5;
    const int half = wid >> 3, wl = wid & 7;

    __nv_bfloat16* As_h = (__nv_bfloat16*)(smem + half * 2 * 17408);
    __nv_bfloat16* As_l = (__nv_bfloat16*)(smem + half * 2 * 17408 + 17408);
    __nv_bfloat16* Wah = (__nv_bfloat16*)(smem + 69632);
    __nv_bfloat16* Wal = (__nv_bfloat16*)(smem + 104448);
    __nv_bfloat16* Wbh = (__nv_bfloat16*)(smem + 139264);
    __nv_bfloat16* Wbl = (__nv_bfloat16*)(smem + 174080);

    {
        const uint4* s1 = (const uint4*)W1hI;
        const uint4* s2 = (const uint4*)W1lI;
        const uint4* s3 = (const uint4*)W2hI;
        const uint4* s4 = (const uint4*)W2lI;
        for (int i = tid; i < 2048; i += 512) {
            int r = i >> 4, c = i & 15;
            *(uint4*)(Wah + r * SA + c * 8) = s1[i];
            *(uint4*)(Wal + r * SA + c * 8) = s2[i];
            *(uint4*)(Wbh + r * SA + c * 8) = s3[i];
            *(uint4*)(Wbl + r * SA + c * 8) = s4[i];
        }
    }
    __syncthreads();

    const int barid = 1 + half;
    const int rowBase = (wl >> 2) * 32, colBase = (wl & 3) * 32;
    const int lrow = lane & 15, lkoff = (lane >> 4) * 8;
    const int cq = (lane & 3) * 2, rq = lane >> 2;
    const int cc = wl & 3;

    float b1r[4][2], b2r[4][2], b3r[4][2], b4r[4][2];
#pragma unroll
    for (int ni = 0; ni < 4; ++ni) {
        const int col = colBase + ni * 8 + cq;
        b1r[ni][0] = b1[col]; b1r[ni][1] = b1[col + 1];
        b2r[ni][0] = b2[col]; b2r[ni][1] = b2[col + 1];
        b3r[ni][0] = b3[col]; b3r[ni][1] = b3[col + 1];
        b4r[ni][0] = b4[col]; b4r[ni][1] = b4[col + 1];
    }

    for (int tile = blockIdx.x * 2 + half; tile < nTiles; tile += gridDim.x * 2) {
        const int m0 = tile * 64;
        BARH(barid);
#pragma unroll
        for (int rr = 0; rr < 8; ++rr) {
            const int r = wl * 8 + rr;
            const int row = m0 + r;
            float4 v = make_float4(0.f, 0.f, 0.f, 0.f);
            if (row < M) v = ((const float4*)A)[(size_t)row * 32 + lane];
            split_store4(v, As_h + r * SA + lane * 4, As_l + r * SA + lane * 4);
        }
        BARH(barid);

        float acc[2][4][4];
        gemm_pass(As_h, As_l, Wah, Wal, rowBase, colBase, lrow, lkoff, acc);
        BARH(barid);
        epi_to_smem(acc, b1r, As_h, As_l, rowBase, colBase, lane);
        BARH(barid);
        gemm_pass(As_h, As_l, Wbh, Wbl, rowBase, colBase, lrow, lkoff, acc);
        BARH(barid);
        epi_to_smem(acc, b2r, As_h, As_l, rowBase, colBase, lane);  // layer out (relu)
        BARH(barid);
        gemm_pass_frag(As_h, As_l, F1h, F1l, rowBase, cc, lrow, lkoff, lane, acc);
        BARH(barid);
        epi_to_smem(acc, b3r, As_h, As_l, rowBase, colBase, lane);  // mlp hidden (relu)
        BARH(barid);
        gemm_pass_frag(As_h, As_l, F2h, F2l, rowBase, cc, lrow, lkoff, lane, acc);
        write_out128<false>(acc, b4r, C, m0, rowBase, colBase, cq, rq, M);
    }
}

// ---------------- weight prep ------------------------------------------------
struct PrepArgs {
    const float *W1[5], *b1[5], *g[5], *bb[5], *m[5], *v[5], *W2[5], *Wo;
    __nv_bfloat16 *W1h[5], *W1l[5], *W2h[5], *W2l[5];
    uint32_t *Wofh, *Wofl;
    float* bf[5];
};

__global__ void prep_weights(PrepArgs a) {
    const int blk = blockIdx.x, tid = threadIdx.x;
    if (blk < 320) {
        const int j = blk >> 6;
        const int idx = ((blk & 63) << 8) + tid;
        const int k = idx >> 7, n = idx & 127;
        float s = a.g[j][n] * rsqrtf(a.v[j][n] + 1e-5f);
        float val = a.W1[j][idx] * s;
        __nv_bfloat16 h = __float2bfloat16(val);
        a.W1h[j][n * 128 + k] = h;
        a.W1l[j][n * 128 + k] = __float2bfloat16(val - __bfloat162float(h));
        if (idx < 128)
            a.bf[j][idx] = a.b1[j][idx] * s + a.bb[j][idx] - a.m[j][idx] * s;
    } else if (blk < 640) {
        const int j = (blk - 320) >> 6;
        const int idx = (((blk - 320) & 63) << 8) + tid;
        const int k = idx >> 7, n = idx & 127;
        float val = a.W2[j][idx];
        __nv_bfloat16 h = __float2bfloat16(val);
        a.W2h[j][n * 128 + k] = h;
        a.W2l[j][n * 128 + k] = __float2bfloat16(val - __bfloat162float(h));
    } else {
        const int idx = ((blk - 640) << 8) + tid;  // 0..4095 (Wo frags)
        const int j = idx & 3, L = (idx >> 2) & 31;
        const int ks = (idx >> 7) & 7, cc = idx >> 10;
        const int n = cc * 16 + (j & 1) * 8 + (L >> 2);
        const int k = ks * 16 + ((j >> 1)) * 8 + (L & 3) * 2;
        float v0 = a.Wo[k * OD + n];
        float v1 = a.Wo[(k + 1) * OD + n];
        a.Wofh[((cc * 8 + ks) * 32 + L) * 4 + j] = pack_hi(v0, v1);
        a.Wofl[((cc * 8 + ks) * 32 + L) * 4 + j] = pack_lo(v0, v1);
    }
}

// convert mlp W images (j=2, n-major [n*128+k]) into N=128 frag arrays
__global__ void frag_mlp(const __nv_bfloat16* __restrict__ i1h,
                         const __nv_bfloat16* __restrict__ i1l,
                         const __nv_bfloat16* __restrict__ i2h,
                         const __nv_bfloat16* __restrict__ i2l,
                         uint32_t* __restrict__ F1h, uint32_t* __restrict__ F1l,
                         uint32_t* __restrict__ F2h, uint32_t* __restrict__ F2l) {
    const int i = blockIdx.x * 256 + threadIdx.x;   // 0..32767
    const int m = i >> 13, e = i & 8191;
    const int j = e & 3, L = (e >> 2) & 31;
    const int ks = (e >> 7) & 7, g = e >> 10;       // g = cc*2+nj, 0..7
    const int n = g * 16 + (j & 1) * 8 + (L >> 2);
    const int k = ks * 16 + (j >> 1) * 8 + (L & 3) * 2;
    const __nv_bfloat16* src;
    uint32_t* dst;
    switch (m) {
        case 0: src = i1h; dst = F1h; break;
        case 1: src = i1l; dst = F1l; break;
        case 2: src = i2h; dst = F2h; break;
        default: src = i2l; dst = F2l; break;
    }
    dst[e] = *(const uint32_t*)(src + n * 128 + k);
}

// ---------------- CSR build ----------------------------------------------------
__global__ void count_deg(const int* __restrict__ dst, int E, int* __restrict__ deg) {
    int e = blockIdx.x * 256 + threadIdx.x;
    if (e < E) atomicAdd(&deg[dst[e]], 1);
}

__global__ void scan1(const int* __restrict__ deg, int* __restrict__ ex,
                      int* __restrict__ bsum, int n) {
    __shared__ int wsum[32];
    const int t = threadIdx.x;
    const int base = blockIdx.x * 4096 + t * 4;
    int v[4], s = 0;
#pragma unroll
    for (int i = 0; i < 4; ++i) {
        int idx = base + i;
        v[i] = idx < n ? deg[idx] : 0;
        s += v[i];
    }
    const int lane = t & 31, w = t >> 5;
    int ps = s;
#pragma unroll
    for (int o = 1; o < 32; o <<= 1) {
        int y = __shfl_up_sync(~0u, ps, o);
        if (lane >= o) ps += y;
    }
    if (lane == 31) wsum[w] = ps;
    __syncthreads();
    if (w == 0) {
        int x = wsum[lane];
#pragma unroll
        for (int o = 1; o < 32; o <<= 1) {
            int y = __shfl_up_sync(~0u, x, o);
            if (lane >= o) x += y;
        }
        wsum[lane] = x;
    }
    __syncthreads();
    const int warpoff = w ? wsum[w - 1] : 0;
    int run = warpoff + ps - s;
#pragma unroll
    for (int i = 0; i < 4; ++i) {
        int idx = base + i;
        if (idx < n) ex[idx] = run;
        run += v[i];
    }
    if (t == 0) bsum[blockIdx.x] = wsum[31];
}

__global__ void scan2(int* __restrict__ bsum, int nb) {
    __shared__ int sm_[1024];
    const int t = threadIdx.x;
    int v = (t < nb) ? bsum[t] : 0;
    sm_[t] = v;
    __syncthreads();
    for (int o = 1; o < 1024; o <<= 1) {
        int y = (t >= o) ? sm_[t - o] : 0;
        __syncthreads();
        sm_[t] += y;
        __syncthreads();
    }
    if (t < nb) bsum[t] = sm_[t] - v;
}

__global__ void scan3(const int* __restrict__ ex, const int* __restrict__ boff,
                      int* __restrict__ rp, int* __restrict__ cur, int n, int E) {
    int i = blockIdx.x * 1024 + threadIdx.x;
    if (i < n) {
        int vv = ex[i] + boff[i >> 12];
        rp[i] = vv;
        cur[i] = vv;
    } else if (i == n) {
        rp[n] = E;
    }
}

__global__ void fill_csr(const int* __restrict__ src, const int* __restrict__ dst,
                         int E, int* __restrict__ cur, int* __restrict__ adj) {
    int e = blockIdx.x * 256 + threadIdx.x;
    if (e < E) {
        int p = atomicAdd(&cur[dst[e]], 1);
        adj[p] = src[e];
    }
}

// ---------------- gather aggregation: agg[r] = x[r] + sum x[nbr] ---------------
__global__ void gather_agg(const float* __restrict__ x,
                           const int* __restrict__ rp,
                           const int* __restrict__ adj,
                           float* __restrict__ agg, int n) {
    unsigned t = blockIdx.x * 256u + threadIdx.x;
    unsigned r = t >> 5, lane = t & 31u;
    if (r >= (unsigned)n) return;
    const int s = rp[r], e = rp[r + 1];
    float4 acc = ((const float4*)(x + (size_t)r * HD))[lane];
    const int cnt = e - s;
    int nb_l = ((int)lane < cnt) ? adj[s + lane] : 0;
    const int lim = cnt < 32 ? cnt : 32;
    for (int j = 0; j < lim; ++j) {
        const int nb = __shfl_sync(~0u, nb_l, j);
        float4 u = ((const float4*)(x + (size_t)nb * HD))[lane];
        acc.x += u.x; acc.y += u.y; acc.z += u.z; acc.w += u.w;
    }
    for (int j = s + 32; j < e; ++j) {  // rare high-degree tail
        const int nb = adj[j];
        float4 u = ((const float4*)(x + (size_t)nb * HD))[lane];
        acc.x += u.x; acc.y += u.y; acc.z += u.z; acc.w += u.w;
    }
    ((float4*)(agg + (size_t)r * HD))[lane] = acc;
}

// ---------------- pair lift: h = y[ep0] + y[ep1] --------------------------------
__global__ void pair_gather_kernel(const int* __restrict__ ep,
                                   const float* __restrict__ y,
                                   float* __restrict__ h, int E) {
    unsigned t = blockIdx.x * 256u + threadIdx.x;
    unsigned e = t >> 5, lane = t & 31u;
    if (e >= (unsigned)E) return;
    int i0 = ep[2 * e], i1 = ep[2 * e + 1];
    float4 a = ((const float4*)(y + (size_t)i0 * HD))[lane];
    float4 b = ((const float4*)(y + (size_t)i1 * HD))[lane];
    a.x += b.x; a.y += b.y; a.z += b.z; a.w += b.w;
    ((float4*)(h + (size_t)e * HD))[lane] = a;
}

// ----------------------------------------------------------------------------------
extern "C" void kernel_launch(void* const* d_in, const int* in_sizes, int n_in,
                              void* d_out, int out_size) {
    const int*   edge_index = (const int*)d_in[0];
    const float* x_orig     = (const float*)d_in[1];
    const int*   ei_orig    = (const int*)d_in[2];
    const int*   edge_pairs = (const int*)d_in[3];
    const float* init_W1 = (const float*)d_in[4];
    const float* init_b1 = (const float*)d_in[5];
    const float* init_g  = (const float*)d_in[6];
    const float* init_bb = (const float*)d_in[7];
    const float* init_m  = (const float*)d_in[8];
    const float* init_v  = (const float*)d_in[9];
    const float* init_W2 = (const float*)d_in[10];
    const float* init_b2 = (const float*)d_in[11];
    const float* gin_W1  = (const float*)d_in[12];
    const float* gin_b1  = (const float*)d_in[13];
    const float* gin_g   = (const float*)d_in[14];
    const float* gin_bb  = (const float*)d_in[15];
    const float* gin_m   = (const float*)d_in[16];
    const float* gin_v   = (const float*)d_in[17];
    const float* gin_W2  = (const float*)d_in[18];
    const float* gin_b2  = (const float*)d_in[19];
    const float* mlp_W1  = (const float*)d_in[20];
    const float* mlp_b1  = (const float*)d_in[21];
    const float* mlp_g   = (const float*)d_in[22];
    const float* mlp_bb  = (const float*)d_in[23];
    const float* mlp_m   = (const float*)d_in[24];
    const float* mlp_v   = (const float*)d_in[25];
    const float* mlp_W2  = (const float*)d_in[26];
    const float* mlp_b2  = (const float*)d_in[27];
    const float* out_W   = (const float*)d_in[28];
    const float* out_b   = (const float*)d_in[29];
    float* out = (float*)d_out;

    float *nodeA, *nodeB, *nodeC, *nodeD, *edgeA, *edgeB, *edgeC, *bfb;
    __nv_bfloat16 *W1h, *W1l, *W2h, *W2l;
    uint32_t *Wofh, *Wofl, *F1h, *F1l, *F2h, *F2l;
    int *deg, *ex, *bsum, *rpN, *adjN, *curN, *rpE, *adjE, *curE;
    cudaGetSymbolAddress((void**)&nodeA, g_nodeA);
    cudaGetSymbolAddress((void**)&nodeB, g_nodeB);
    cudaGetSymbolAddress((void**)&nodeC, g_nodeC);
    cudaGetSymbolAddress((void**)&nodeD, g_nodeD);
    cudaGetSymbolAddress((void**)&edgeA, g_edgeA);
    cudaGetSymbolAddress((void**)&edgeB, g_edgeB);
    cudaGetSymbolAddress((void**)&edgeC, g_edgeC);
    cudaGetSymbolAddress((void**)&bfb, g_bfb);
    cudaGetSymbolAddress((void**)&W1h, g_W1h);
    cudaGetSymbolAddress((void**)&W1l, g_W1l);
    cudaGetSymbolAddress((void**)&W2h, g_W2h);
    cudaGetSymbolAddress((void**)&W2l, g_W2l);
    cudaGetSymbolAddress((void**)&Wofh, g_Wofh);
    cudaGetSymbolAddress((void**)&Wofl, g_Wofl);
    cudaGetSymbolAddress((void**)&F1h, g_F1h);
    cudaGetSymbolAddress((void**)&F1l, g_F1l);
    cudaGetSymbolAddress((void**)&F2h, g_F2h);
    cudaGetSymbolAddress((void**)&F2l, g_F2l);
    cudaGetSymbolAddress((void**)&deg, g_deg);
    cudaGetSymbolAddress((void**)&ex, g_ex);
    cudaGetSymbolAddress((void**)&bsum, g_bsum);
    cudaGetSymbolAddress((void**)&rpN, g_rpN);
    cudaGetSymbolAddress((void**)&adjN, g_adjN);
    cudaGetSymbolAddress((void**)&curN, g_curN);
    cudaGetSymbolAddress((void**)&rpE, g_rpE);
    cudaGetSymbolAddress((void**)&adjE, g_adjE);
    cudaGetSymbolAddress((void**)&curE, g_curE);

    // ---- weight prep --------------------------------------------------------
    PrepArgs pa;
    const float* W1s[5]  = {init_W1, init_W1 + HD * HD, mlp_W1, gin_W1, gin_W1 + HD * HD};
    const float* b1s[5]  = {init_b1, init_b1 + HD, mlp_b1, gin_b1, gin_b1 + HD};
    const float* gs[5]   = {init_g, init_g + HD, mlp_g, gin_g, gin_g + HD};
    const float* bbs[5]  = {init_bb, init_bb + HD, mlp_bb, gin_bb, gin_bb + HD};
    const float* ms[5]   = {init_m, init_m + HD, mlp_m, gin_m, gin_m + HD};
    const float* vs[5]   = {init_v, init_v + HD, mlp_v, gin_v, gin_v + HD};
    const float* W2s[5]  = {init_W2, init_W2 + HD * HD, mlp_W2, gin_W2, gin_W2 + HD * HD};
    for (int j = 0; j < 5; ++j) {
        pa.W1[j] = W1s[j]; pa.b1[j] = b1s[j]; pa.g[j] = gs[j]; pa.bb[j] = bbs[j];
        pa.m[j] = ms[j]; pa.v[j] = vs[j]; pa.W2[j] = W2s[j];
        pa.W1h[j] = W1h + (size_t)j * HD * HD; pa.W1l[j] = W1l + (size_t)j * HD * HD;
        pa.W2h[j] = W2h + (size_t)j * HD * HD; pa.W2l[j] = W2l + (size_t)j * HD * HD;
        pa.bf[j] = bfb + j * HD;
    }
    pa.Wo = out_W; pa.Wofh = Wofh; pa.Wofl = Wofl;
    prep_weights<<<656, 256>>>(pa);
    frag_mlp<<<128, 256>>>(W1h + 2 * HD * HD, W1l + 2 * HD * HD,
                           W2h + 2 * HD * HD, W2l + 2 * HD * HD,
                           F1h, F1l, F2h, F2l);

    // ---- CSR build: node graph (dst = ei_orig[1]) ----------------------------
    cudaMemsetAsync(deg, 0, NN * sizeof(int));
    count_deg<<<(EO + 255) / 256, 256>>>(ei_orig + EO, EO, deg);
    scan1<<<(NN + 4095) / 4096, 1024>>>(deg, ex, bsum, NN);
    scan2<<<1, 1024>>>(bsum, (NN + 4095) / 4096);
    scan3<<<(NN + 1024) / 1024 + 1, 1024>>>(ex, bsum, rpN, curN, NN, EO);
    fill_csr<<<(EO + 255) / 256, 256>>>(ei_orig, ei_orig + EO, EO, curN, adjN);

    // ---- CSR build: line graph (dst = edge_index[1]) --------------------------
    cudaMemsetAsync(deg, 0, EO * sizeof(int));
    count_deg<<<(EL + 255) / 256, 256>>>(edge_index + EL, EL, deg);
    scan1<<<(EO + 4095) / 4096, 1024>>>(deg, ex, bsum, EO);
    scan2<<<1, 1024>>>(bsum, (EO + 4095) / 4096);
    scan3<<<(EO + 1024) / 1024 + 1, 1024>>>(ex, bsum, rpE, curE, EO, EL);
    fill_csr<<<(EL + 255) / 256, 256>>>(edge_index, edge_index + EL, EL, curE, adjE);

    // ---- main pipeline ----------------------------------------------------------
    const int SMEM_F = 208896;
    cudaFuncSetAttribute(fused_gin<false>,
                         cudaFuncAttributeMaxDynamicSharedMemorySize, SMEM_F);
    cudaFuncSetAttribute(fused_gin<true>,
                         cudaFuncAttributeMaxDynamicSharedMemorySize, SMEM_F);
    cudaFuncSetAttribute(fused_gin_mlp,
                         cudaFuncAttributeMaxDynamicSharedMemorySize, SMEM_F);

    const int GRID = 148;
    const int tilesN = (NN + 63) / 64;
    const int tilesE = (EO + 63) / 64;
    const int gaN = ((unsigned)NN * 32u + 255u) / 256u;
    const int gaE = ((unsigned)EO * 32u + 255u) / 256u;
    const size_t WSZ = (size_t)HD * HD;

    // node layer 0: agg(x_orig) -> nodeB; GEMM -> nodeA
    gather_agg<<<gaN, 256>>>(x_orig, rpN, adjN, nodeB, NN);
    fused_gin<false><<<GRID, 512, SMEM_F>>>(
        nodeB, W1h, W1l, W2h, W2l, nullptr, nullptr,
        bfb, init_b2, nullptr, nodeA, NN, tilesN);

    // node layer 1 + MLP: agg(nodeA) -> nodeC; 4-pass GEMM -> nodeD
    gather_agg<<<gaN, 256>>>(nodeA, rpN, adjN, nodeC, NN);
    fused_gin_mlp<<<GRID, 512, SMEM_F>>>(
        nodeC, W1h + WSZ, W1l + WSZ, W2h + WSZ, W2l + WSZ,
        (const uint4*)F1h, (const uint4*)F1l, (const uint4*)F2h, (const uint4*)F2l,
        bfb + HD, init_b2 + HD, bfb + 2 * HD, mlp_b2, nodeD, NN, tilesN);

    // pair lift: nodeD -> edgeA
    pair_gather_kernel<<<gaE, 256>>>(edge_pairs, nodeD, edgeA, EO);

    // edge layer 0: agg(edgeA) -> edgeB; GEMM -> edgeC
    gather_agg<<<gaE, 256>>>(edgeA, rpE, adjE, edgeB, EO);
    fused_gin<false><<<GRID, 512, SMEM_F>>>(
        edgeB, W1h + 3 * WSZ, W1l + 3 * WSZ, W2h + 3 * WSZ, W2l + 3 * WSZ,
        nullptr, nullptr, bfb + 3 * HD, gin_b2, nullptr, edgeC, EO, tilesE);

    // edge layer 1 + head: agg(edgeC) -> edgeA; GEMM+head -> out
    gather_agg<<<gaE, 256>>>(edgeC, rpE, adjE, edgeA, EO);
    fused_gin<true><<<GRID, 512, SMEM_F>>>(
        edgeA, W1h + 4 * WSZ, W1l + 4 * WSZ, W2h + 4 * WSZ, W2l + 4 * WSZ,
        (const uint4*)Wofh, (const uint4*)Wofl,
        bfb + 4 * HD, gin_b2 + HD, out_b, out, EO, tilesE);
}

// round 9
// speedup vs baseline: 1.6709x; 1.0592x over previous
#include <cuda_runtime.h>
#include <cuda_bf16.h>
#include <cstdint>

#define NN 100000
#define EO 600000
#define EL 1200000
#define HD 128
#define OD 64
#define SA 136   // smem row stride (bf16) -> conflict-spread ldmatrix/stmatrix

// ---------------- scratch (device globals) ---------------------------------
static __device__ float g_nodeA[(size_t)NN * HD];
static __device__ float g_nodeB[(size_t)NN * HD];
static __device__ float g_nodeC[(size_t)NN * HD];
static __device__ float g_nodeD[(size_t)NN * HD];
static __device__ float g_edgeA[(size_t)EO * HD];
static __device__ float g_edgeB[(size_t)EO * HD];
static __device__ float g_edgeC[(size_t)EO * HD];
static __device__ __nv_bfloat16 g_W1h[5][HD * HD], g_W1l[5][HD * HD];
static __device__ __nv_bfloat16 g_W2h[5][HD * HD], g_W2l[5][HD * HD];
static __device__ uint32_t g_Wofh[4096], g_Wofl[4096];   // Wo frags (N=64)
static __device__ uint32_t g_F1h[8192], g_F1l[8192];     // mlp W1 frags (N=128)
static __device__ uint32_t g_F2h[8192], g_F2l[8192];     // mlp W2 frags
static __device__ float g_bfb[5][HD];
// CSR scratch
static __device__ int g_deg[EO], g_ex[EO], g_bsum[1024];
static __device__ int g_rpN[NN + 1], g_adjN[EO], g_curN[NN];
static __device__ int g_rpE[EO + 1], g_adjE[EL], g_curE[EO];

// ---------------- PTX helpers ----------------------------------------------
__device__ __forceinline__ void ldsm4(uint32_t* r, const void* p) {
    uint32_t a = (uint32_t)__cvta_generic_to_shared(p);
    asm volatile("ldmatrix.sync.aligned.m8n8.x4.shared.b16 {%0,%1,%2,%3}, [%4];"
                 : "=r"(r[0]), "=r"(r[1]), "=r"(r[2]), "=r"(r[3]) : "r"(a));
}
__device__ __forceinline__ void stsm4(void* p, uint32_t r0, uint32_t r1,
                                      uint32_t r2, uint32_t r3) {
    uint32_t a = (uint32_t)__cvta_generic_to_shared(p);
    asm volatile("stmatrix.sync.aligned.m8n8.x4.shared.b16 [%0], {%1,%2,%3,%4};"
                 :: "r"(a), "r"(r0), "r"(r1), "r"(r2), "r"(r3) : "memory");
}
__device__ __forceinline__ void mma_bf16(float* d, const uint32_t* a,
                                         uint32_t b0, uint32_t b1) {
    asm volatile(
        "mma.sync.aligned.m16n8k16.row.col.f32.bf16.bf16.f32 "
        "{%0,%1,%2,%3}, {%4,%5,%6,%7}, {%8,%9}, {%0,%1,%2,%3};"
        : "+f"(d[0]), "+f"(d[1]), "+f"(d[2]), "+f"(d[3])
        : "r"(a[0]), "r"(a[1]), "r"(a[2]), "r"(a[3]), "r"(b0), "r"(b1));
}
__device__ __forceinline__ uint32_t pack_hi(float a, float b) {
    __nv_bfloat162 t = __halves2bfloat162(__float2bfloat16(a), __float2bfloat16(b));
    return *(uint32_t*)&t;
}
__device__ __forceinline__ uint32_t pack_lo(float a, float b) {
    float ra = a - __bfloat162float(__float2bfloat16(a));
    float rb = b - __bfloat162float(__float2bfloat16(b));
    __nv_bfloat162 t = __halves2bfloat162(__float2bfloat16(ra), __float2bfloat16(rb));
    return *(uint32_t*)&t;
}
__device__ __forceinline__ void split_store4(float4 v, __nv_bfloat16* ph,
                                             __nv_bfloat16* pl) {
    *(uint2*)ph = make_uint2(pack_hi(v.x, v.y), pack_hi(v.z, v.w));
    *(uint2*)pl = make_uint2(pack_lo(v.x, v.y), pack_lo(v.z, v.w));
}
#define BARH(id) asm volatile("bar.sync %0, 256;" :: "r"(id) : "memory")

// ---------------- GEMM passes ------------------------------------------------
__device__ __forceinline__ void gemm_pass(
    const __nv_bfloat16* As_h, const __nv_bfloat16* As_l,
    const __nv_bfloat16* Wh, const __nv_bfloat16* Wl,
    int rowBase, int colBase, int lrow, int lkoff, float (&acc)[2][4][4]) {
#pragma unroll
    for (int mi = 0; mi < 2; ++mi)
#pragma unroll
        for (int ni = 0; ni < 4; ++ni)
#pragma unroll
            for (int q = 0; q < 4; ++q) acc[mi][ni][q] = 0.f;
#pragma unroll
    for (int ks = 0; ks < 8; ++ks) {
        const int k0 = ks * 16 + lkoff;
        uint32_t ah[2][4], al[2][4];
#pragma unroll
        for (int mi = 0; mi < 2; ++mi) {
            const int base = (rowBase + mi * 16 + lrow) * SA + k0;
            ldsm4(ah[mi], As_h + base);
            ldsm4(al[mi], As_l + base);
        }
        uint32_t bh[2][4], bl[2][4];
#pragma unroll
        for (int nj = 0; nj < 2; ++nj) {
            const int base = (colBase + nj * 16 + lrow) * SA + k0;
            ldsm4(bh[nj], Wh + base);
            ldsm4(bl[nj], Wl + base);
        }
#pragma unroll
        for (int mi = 0; mi < 2; ++mi)
#pragma unroll
            for (int ni = 0; ni < 4; ++ni) {
                const int nj = ni >> 1, hh = ni & 1;
                mma_bf16(acc[mi][ni], ah[mi], bh[nj][hh], bh[nj][hh + 2]);
                mma_bf16(acc[mi][ni], ah[mi], bl[nj][hh], bl[nj][hh + 2]);
                mma_bf16(acc[mi][ni], al[mi], bh[nj][hh], bh[nj][hh + 2]);
            }
    }
}

// B fragments from gmem (N=128 per CTA; warp covers cols cc*32..cc*32+31)
__device__ __forceinline__ void gemm_pass_frag(
    const __nv_bfloat16* As_h, const __nv_bfloat16* As_l,
    const uint4* __restrict__ Fh, const uint4* __restrict__ Fl,
    int rowBase, int cc, int lrow, int lkoff, int lane, float (&acc)[2][4][4]) {
#pragma unroll
    for (int mi = 0; mi < 2; ++mi)
#pragma unroll
        for (int ni = 0; ni < 4; ++ni)
#pragma unroll
            for (int q = 0; q < 4; ++q) acc[mi][ni][q] = 0.f;
#pragma unroll
    for (int ks = 0; ks < 8; ++ks) {
        const int k0 = ks * 16 + lkoff;
        uint32_t ah[2][4], al[2][4];
#pragma unroll
        for (int mi = 0; mi < 2; ++mi) {
            const int base = (rowBase + mi * 16 + lrow) * SA + k0;
            ldsm4(ah[mi], As_h + base);
            ldsm4(al[mi], As_l + base);
        }
#pragma unroll
        for (int nj = 0; nj < 2; ++nj) {
            const uint4 bh = Fh[((cc * 2 + nj) * 8 + ks) * 32 + lane];
            const uint4 bl = Fl[((cc * 2 + nj) * 8 + ks) * 32 + lane];
#pragma unroll
            for (int mi = 0; mi < 2; ++mi) {
                const int n0 = nj * 2;
                mma_bf16(acc[mi][n0], ah[mi], bh.x, bh.z);
                mma_bf16(acc[mi][n0], ah[mi], bl.x, bl.z);
                mma_bf16(acc[mi][n0], al[mi], bh.x, bh.z);
                mma_bf16(acc[mi][n0 + 1], ah[mi], bh.y, bh.w);
                mma_bf16(acc[mi][n0 + 1], ah[mi], bl.y, bl.w);
                mma_bf16(acc[mi][n0 + 1], al[mi], bh.y, bh.w);
            }
        }
    }
}

// bias+relu then stmatrix both splits back into As
__device__ __forceinline__ void epi_to_smem(
    const float (&acc)[2][4][4], const float (&br)[4][2],
    __nv_bfloat16* As_h, __nv_bfloat16* As_l,
    int rowBase, int colBase, int lane) {
    const int srow = (lane & 7) + ((lane >> 3) & 1) * 8;
    const int scol = (lane >> 4) * 8;
#pragma unroll
    for (int mi = 0; mi < 2; ++mi) {
#pragma unroll
        for (int ng = 0; ng < 2; ++ng) {
            float v[2][4];
#pragma unroll
            for (int q = 0; q < 2; ++q) {
                const int ni = ng * 2 + q;
                v[q][0] = fmaxf(acc[mi][ni][0] + br[ni][0], 0.f);
                v[q][1] = fmaxf(acc[mi][ni][1] + br[ni][1], 0.f);
                v[q][2] = fmaxf(acc[mi][ni][2] + br[ni][0], 0.f);
                v[q][3] = fmaxf(acc[mi][ni][3] + br[ni][1], 0.f);
            }
            const int off = (rowBase + mi * 16 + srow) * SA + colBase + ng * 16 + scol;
            stsm4(As_h + off, pack_hi(v[0][0], v[0][1]), pack_hi(v[0][2], v[0][3]),
                  pack_hi(v[1][0], v[1][1]), pack_hi(v[1][2], v[1][3]));
            stsm4(As_l + off, pack_lo(v[0][0], v[0][1]), pack_lo(v[0][2], v[0][3]),
                  pack_lo(v[1][0], v[1][1]), pack_lo(v[1][2], v[1][3]));
        }
    }
}

// gmem write: acc + bias (+relu) -> C [M,HD]
template <bool RELU>
__device__ __forceinline__ void write_out128(
    const float (&acc)[2][4][4], const float (&br)[4][2],
    float* __restrict__ C, int m0, int rowBase, int colBase,
    int cq, int rq, int M) {
#pragma unroll
    for (int mi = 0; mi < 2; ++mi)
#pragma unroll
        for (int ni = 0; ni < 4; ++ni) {
            const int col = colBase + ni * 8 + cq;
            const int r0 = m0 + rowBase + mi * 16 + rq, r1 = r0 + 8;
            float v00 = acc[mi][ni][0] + br[ni][0];
            float v01 = acc[mi][ni][1] + br[ni][1];
            float v10 = acc[mi][ni][2] + br[ni][0];
            float v11 = acc[mi][ni][3] + br[ni][1];
            if (RELU) {
                v00 = fmaxf(v00, 0.f); v01 = fmaxf(v01, 0.f);
                v10 = fmaxf(v10, 0.f); v11 = fmaxf(v11, 0.f);
            }
            if (r0 < M) *(float2*)(C + (size_t)r0 * HD + col) = make_float2(v00, v01);
            if (r1 < M) *(float2*)(C + (size_t)r1 * HD + col) = make_float2(v10, v11);
        }
}

// ---------------- fused GIN layer (2 passes, optional head pass) -----------
template <bool HEAD>
__global__ __launch_bounds__(512, 1) void fused_gin(
    const float* __restrict__ A,
    const __nv_bfloat16* __restrict__ W1hI, const __nv_bfloat16* __restrict__ W1lI,
    const __nv_bfloat16* __restrict__ W2hI, const __nv_bfloat16* __restrict__ W2lI,
    const uint4* __restrict__ WoFh, const uint4* __restrict__ WoFl,
    const float* __restrict__ b1, const float* __restrict__ b2,
    const float* __restrict__ b3,
    float* __restrict__ C, int M, int nTiles) {
    extern __shared__ char smem[];
    const int tid = threadIdx.x, lane = tid & 31, wid = tid >> 5;
    const int half = wid >> 3, wl = wid & 7;

    __nv_bfloat16* As_h = (__nv_bfloat16*)(smem + half * 2 * 17408);
    __nv_bfloat16* As_l = (__nv_bfloat16*)(smem + half * 2 * 17408 + 17408);
    __nv_bfloat16* Wah = (__nv_bfloat16*)(smem + 69632);
    __nv_bfloat16* Wal = (__nv_bfloat16*)(smem + 104448);
    __nv_bfloat16* Wbh = (__nv_bfloat16*)(smem + 139264);
    __nv_bfloat16* Wbl = (__nv_bfloat16*)(smem + 174080);

    {
        const uint4* s1 = (const uint4*)W1hI;
        const uint4* s2 = (const uint4*)W1lI;
        const uint4* s3 = (const uint4*)W2hI;
        const uint4* s4 = (const uint4*)W2lI;
        for (int i = tid; i < 2048; i += 512) {
            int r = i >> 4, c = i & 15;
            *(uint4*)(Wah + r * SA + c * 8) = s1[i];
            *(uint4*)(Wal + r * SA + c * 8) = s2[i];
            *(uint4*)(Wbh + r * SA + c * 8) = s3[i];
            *(uint4*)(Wbl + r * SA + c * 8) = s4[i];
        }
    }
    __syncthreads();

    const int barid = 1 + half;
    const int rowBase = (wl >> 2) * 32, colBase = (wl & 3) * 32;
    const int lrow = lane & 15, lkoff = (lane >> 4) * 8;
    const int cq = (lane & 3) * 2, rq = lane >> 2;
    const int cc = wl & 3;

    float b1r[4][2], b2r[4][2], b3r[2][2];
#pragma unroll
    for (int ni = 0; ni < 4; ++ni) {
        const int col = colBase + ni * 8 + cq;
        b1r[ni][0] = b1[col]; b1r[ni][1] = b1[col + 1];
        b2r[ni][0] = b2[col]; b2r[ni][1] = b2[col + 1];
    }
    if (HEAD) {
#pragma unroll
        for (int ni = 0; ni < 2; ++ni) {
            const int col = cc * 16 + ni * 8 + cq;
            b3r[ni][0] = b3[col]; b3r[ni][1] = b3[col + 1];
        }
    }

    for (int tile = blockIdx.x * 2 + half; tile < nTiles; tile += gridDim.x * 2) {
        const int m0 = tile * 64;
        BARH(barid);
#pragma unroll
        for (int rr = 0; rr < 8; ++rr) {
            const int r = wl * 8 + rr;
            const int row = m0 + r;
            float4 v = make_float4(0.f, 0.f, 0.f, 0.f);
            if (row < M) v = ((const float4*)A)[(size_t)row * 32 + lane];
            split_store4(v, As_h + r * SA + lane * 4, As_l + r * SA + lane * 4);
        }
        BARH(barid);

        float acc[2][4][4];
        gemm_pass(As_h, As_l, Wah, Wal, rowBase, colBase, lrow, lkoff, acc);
        BARH(barid);
        epi_to_smem(acc, b1r, As_h, As_l, rowBase, colBase, lane);
        BARH(barid);
        gemm_pass(As_h, As_l, Wbh, Wbl, rowBase, colBase, lrow, lkoff, acc);

        if (!HEAD) {
            write_out128<true>(acc, b2r, C, m0, rowBase, colBase, cq, rq, M);
        } else {
            BARH(barid);
            epi_to_smem(acc, b2r, As_h, As_l, rowBase, colBase, lane);
            BARH(barid);
            float acc3[2][2][4];
#pragma unroll
            for (int mi = 0; mi < 2; ++mi)
#pragma unroll
                for (int ni = 0; ni < 2; ++ni)
#pragma unroll
                    for (int q = 0; q < 4; ++q) acc3[mi][ni][q] = 0.f;
#pragma unroll
            for (int ks = 0; ks < 8; ++ks) {
                const int k0 = ks * 16 + lkoff;
                uint32_t ah[2][4], al[2][4];
#pragma unroll
                for (int mi = 0; mi < 2; ++mi) {
                    const int base = (rowBase + mi * 16 + lrow) * SA + k0;
                    ldsm4(ah[mi], As_h + base);
                    ldsm4(al[mi], As_l + base);
                }
                const uint4 bh = WoFh[(cc * 8 + ks) * 32 + lane];
                const uint4 bl = WoFl[(cc * 8 + ks) * 32 + lane];
#pragma unroll
                for (int mi = 0; mi < 2; ++mi) {
                    mma_bf16(acc3[mi][0], ah[mi], bh.x, bh.z);
                    mma_bf16(acc3[mi][0], ah[mi], bl.x, bl.z);
                    mma_bf16(acc3[mi][0], al[mi], bh.x, bh.z);
                    mma_bf16(acc3[mi][1], ah[mi], bh.y, bh.w);
                    mma_bf16(acc3[mi][1], ah[mi], bl.y, bl.w);
                    mma_bf16(acc3[mi][1], al[mi], bh.y, bh.w);
                }
            }
#pragma unroll
            for (int mi = 0; mi < 2; ++mi)
#pragma unroll
                for (int ni = 0; ni < 2; ++ni) {
                    const int col = cc * 16 + ni * 8 + cq;
                    const int r0 = m0 + rowBase + mi * 16 + rq, r1 = r0 + 8;
                    if (r0 < M)
                        *(float2*)(C + (size_t)r0 * OD + col) = make_float2(
                            acc3[mi][ni][0] + b3r[ni][0], acc3[mi][ni][1] + b3r[ni][1]);
                    if (r1 < M)
                        *(float2*)(C + (size_t)r1 * OD + col) = make_float2(
                            acc3[mi][ni][2] + b3r[ni][0], acc3[mi][ni][3] + b3r[ni][1]);
                }
        }
    }
}

// ---------------- fused node layer 1 + MLP (4 passes) ----------------------
__global__ __launch_bounds__(512, 1) void fused_gin_mlp(
    const float* __restrict__ A,
    const __nv_bfloat16* __restrict__ W1hI, const __nv_bfloat16* __restrict__ W1lI,
    const __nv_bfloat16* __restrict__ W2hI, const __nv_bfloat16* __restrict__ W2lI,
    const uint4* __restrict__ F1h, const uint4* __restrict__ F1l,
    const uint4* __restrict__ F2h, const uint4* __restrict__ F2l,
    const float* __restrict__ b1, const float* __restrict__ b2,
    const float* __restrict__ b3, const float* __restrict__ b4,
    float* __restrict__ C, int M, int nTiles) {
    extern __shared__ char smem[];
    const int tid = threadIdx.x, lane = tid & 31, wid = tid >> 5;
    const int half = wid >> 3, wl = wid & 7;

    __nv_bfloat16* As_h = (__nv_bfloat16*)(smem + half * 2 * 17408);
    __nv_bfloat16* As_l = (__nv_bfloat16*)(smem + half * 2 * 17408 + 17408);
    __nv_bfloat16* Wah = (__nv_bfloat16*)(smem + 69632);
    __nv_bfloat16* Wal = (__nv_bfloat16*)(smem + 104448);
    __nv_bfloat16* Wbh = (__nv_bfloat16*)(smem + 139264);
    __nv_bfloat16* Wbl = (__nv_bfloat16*)(smem + 174080);

    {
        const uint4* s1 = (const uint4*)W1hI;
        const uint4* s2 = (const uint4*)W1lI;
        const uint4* s3 = (const uint4*)W2hI;
        const uint4* s4 = (const uint4*)W2lI;
        for (int i = tid; i < 2048; i += 512) {
            int r = i >> 4, c = i & 15;
            *(uint4*)(Wah + r * SA + c * 8) = s1[i];
            *(uint4*)(Wal + r * SA + c * 8) = s2[i];
            *(uint4*)(Wbh + r * SA + c * 8) = s3[i];
            *(uint4*)(Wbl + r * SA + c * 8) = s4[i];
        }
    }
    __syncthreads();

    const int barid = 1 + half;
    const int rowBase = (wl >> 2) * 32, colBase = (wl & 3) * 32;
    const int lrow = lane & 15, lkoff = (lane >> 4) * 8;
    const int cq = (lane & 3) * 2, rq = lane >> 2;
    const int cc = wl & 3;

    float b1r[4][2], b2r[4][2], b3r[4][2], b4r[4][2];
#pragma unroll
    for (int ni = 0; ni < 4; ++ni) {
        const int col = colBase + ni * 8 + cq;
        b1r[ni][0] = b1[col]; b1r[ni][1] = b1[col + 1];
        b2r[ni][0] = b2[col]; b2r[ni][1] = b2[col + 1];
        b3r[ni][0] = b3[col]; b3r[ni][1] = b3[col + 1];
        b4r[ni][0] = b4[col]; b4r[ni][1] = b4[col + 1];
    }

    for (int tile = blockIdx.x * 2 + half; tile < nTiles; tile += gridDim.x * 2) {
        const int m0 = tile * 64;
        BARH(barid);
#pragma unroll
        for (int rr = 0; rr < 8; ++rr) {
            const int r = wl * 8 + rr;
            const int row = m0 + r;
            float4 v = make_float4(0.f, 0.f, 0.f, 0.f);
            if (row < M) v = ((const float4*)A)[(size_t)row * 32 + lane];
            split_store4(v, As_h + r * SA + lane * 4, As_l + r * SA + lane * 4);
        }
        BARH(barid);

        float acc[2][4][4];
        gemm_pass(As_h, As_l, Wah, Wal, rowBase, colBase, lrow, lkoff, acc);
        BARH(barid);
        epi_to_smem(acc, b1r, As_h, As_l, rowBase, colBase, lane);
        BARH(barid);
        gemm_pass(As_h, As_l, Wbh, Wbl, rowBase, colBase, lrow, lkoff, acc);
        BARH(barid);
        epi_to_smem(acc, b2r, As_h, As_l, rowBase, colBase, lane);  // layer out (relu)
        BARH(barid);
        gemm_pass_frag(As_h, As_l, F1h, F1l, rowBase, cc, lrow, lkoff, lane, acc);
        BARH(barid);
        epi_to_smem(acc, b3r, As_h, As_l, rowBase, colBase, lane);  // mlp hidden (relu)
        BARH(barid);
        gemm_pass_frag(As_h, As_l, F2h, F2l, rowBase, cc, lrow, lkoff, lane, acc);
        write_out128<false>(acc, b4r, C, m0, rowBase, colBase, cq, rq, M);
    }
}

// ---------------- weight prep ------------------------------------------------
struct PrepArgs {
    const float *W1[5], *b1[5], *g[5], *bb[5], *m[5], *v[5], *W2[5], *Wo;
    __nv_bfloat16 *W1h[5], *W1l[5], *W2h[5], *W2l[5];
    uint32_t *Wofh, *Wofl;
    float* bf[5];
};

__global__ void prep_weights(PrepArgs a) {
    const int blk = blockIdx.x, tid = threadIdx.x;
    if (blk < 320) {
        const int j = blk >> 6;
        const int idx = ((blk & 63) << 8) + tid;
        const int k = idx >> 7, n = idx & 127;
        float s = a.g[j][n] * rsqrtf(a.v[j][n] + 1e-5f);
        float val = a.W1[j][idx] * s;
        __nv_bfloat16 h = __float2bfloat16(val);
        a.W1h[j][n * 128 + k] = h;
        a.W1l[j][n * 128 + k] = __float2bfloat16(val - __bfloat162float(h));
        if (idx < 128)
            a.bf[j][idx] = a.b1[j][idx] * s + a.bb[j][idx] - a.m[j][idx] * s;
    } else if (blk < 640) {
        const int j = (blk - 320) >> 6;
        const int idx = (((blk - 320) & 63) << 8) + tid;
        const int k = idx >> 7, n = idx & 127;
        float val = a.W2[j][idx];
        __nv_bfloat16 h = __float2bfloat16(val);
        a.W2h[j][n * 128 + k] = h;
        a.W2l[j][n * 128 + k] = __float2bfloat16(val - __bfloat162float(h));
    } else {
        const int idx = ((blk - 640) << 8) + tid;  // 0..4095 (Wo frags)
        const int j = idx & 3, L = (idx >> 2) & 31;
        const int ks = (idx >> 7) & 7, cc = idx >> 10;
        const int n = cc * 16 + (j & 1) * 8 + (L >> 2);
        const int k = ks * 16 + ((j >> 1)) * 8 + (L & 3) * 2;
        float v0 = a.Wo[k * OD + n];
        float v1 = a.Wo[(k + 1) * OD + n];
        a.Wofh[((cc * 8 + ks) * 32 + L) * 4 + j] = pack_hi(v0, v1);
        a.Wofl[((cc * 8 + ks) * 32 + L) * 4 + j] = pack_lo(v0, v1);
    }
}

// convert mlp W images (j=2, n-major [n*128+k]) into N=128 frag arrays
__global__ void frag_mlp(const __nv_bfloat16* __restrict__ i1h,
                         const __nv_bfloat16* __restrict__ i1l,
                         const __nv_bfloat16* __restrict__ i2h,
                         const __nv_bfloat16* __restrict__ i2l,
                         uint32_t* __restrict__ F1h, uint32_t* __restrict__ F1l,
                         uint32_t* __restrict__ F2h, uint32_t* __restrict__ F2l) {
    const int i = blockIdx.x * 256 + threadIdx.x;   // 0..32767
    const int m = i >> 13, e = i & 8191;
    const int j = e & 3, L = (e >> 2) & 31;
    const int ks = (e >> 7) & 7, g = e >> 10;       // g = cc*2+nj, 0..7
    const int n = g * 16 + (j & 1) * 8 + (L >> 2);
    const int k = ks * 16 + (j >> 1) * 8 + (L & 3) * 2;
    const __nv_bfloat16* src;
    uint32_t* dst;
    switch (m) {
        case 0: src = i1h; dst = F1h; break;
        case 1: src = i1l; dst = F1l; break;
        case 2: src = i2h; dst = F2h; break;
        default: src = i2l; dst = F2l; break;
    }
    dst[e] = *(const uint32_t*)(src + n * 128 + k);
}

// ---------------- CSR build ----------------------------------------------------
__global__ void count_deg(const int* __restrict__ dst, int E, int* __restrict__ deg) {
    int e = blockIdx.x * 256 + threadIdx.x;
    if (e < E) atomicAdd(&deg[dst[e]], 1);
}

__global__ void scan1(const int* __restrict__ deg, int* __restrict__ ex,
                      int* __restrict__ bsum, int n) {
    __shared__ int wsum[32];
    const int t = threadIdx.x;
    const int base = blockIdx.x * 4096 + t * 4;
    int v[4], s = 0;
#pragma unroll
    for (int i = 0; i < 4; ++i) {
        int idx = base + i;
        v[i] = idx < n ? deg[idx] : 0;
        s += v[i];
    }
    const int lane = t & 31, w = t >> 5;
    int ps = s;
#pragma unroll
    for (int o = 1; o < 32; o <<= 1) {
        int y = __shfl_up_sync(~0u, ps, o);
        if (lane >= o) ps += y;
    }
    if (lane == 31) wsum[w] = ps;
    __syncthreads();
    if (w == 0) {
        int x = wsum[lane];
#pragma unroll
        for (int o = 1; o < 32; o <<= 1) {
            int y = __shfl_up_sync(~0u, x, o);
            if (lane >= o) x += y;
        }
        wsum[lane] = x;
    }
    __syncthreads();
    const int warpoff = w ? wsum[w - 1] : 0;
    int run = warpoff + ps - s;
#pragma unroll
    for (int i = 0; i < 4; ++i) {
        int idx = base + i;
        if (idx < n) ex[idx] = run;
        run += v[i];
    }
    if (t == 0) bsum[blockIdx.x] = wsum[31];
}

__global__ void scan2(int* __restrict__ bsum, int nb) {
    __shared__ int sm_[1024];
    const int t = threadIdx.x;
    int v = (t < nb) ? bsum[t] : 0;
    sm_[t] = v;
    __syncthreads();
    for (int o = 1; o < 1024; o <<= 1) {
        int y = (t >= o) ? sm_[t - o] : 0;
        __syncthreads();
        sm_[t] += y;
        __syncthreads();
    }
    if (t < nb) bsum[t] = sm_[t] - v;
}

__global__ void scan3(const int* __restrict__ ex, const int* __restrict__ boff,
                      int* __restrict__ rp, int* __restrict__ cur, int n, int E) {
    int i = blockIdx.x * 1024 + threadIdx.x;
    if (i < n) {
        int vv = ex[i] + boff[i >> 12];
        rp[i] = vv;
        cur[i] = vv;
    } else if (i == n) {
        rp[n] = E;
    }
}

__global__ void fill_csr(const int* __restrict__ src, const int* __restrict__ dst,
                         int E, int* __restrict__ cur, int* __restrict__ adj) {
    int e = blockIdx.x * 256 + threadIdx.x;
    if (e < E) {
        int p = atomicAdd(&cur[dst[e]], 1);
        adj[p] = src[e];
    }
}

// ---------------- gather aggregation: agg[r] = x[r] + sum x[nbr] ---------------
__global__ void gather_agg(const float* __restrict__ x,
                           const int* __restrict__ rp,
                           const int* __restrict__ adj,
                           float* __restrict__ agg, int n) {
    unsigned t = blockIdx.x * 256u + threadIdx.x;
    unsigned r = t >> 5, lane = t & 31u;
    if (r >= (unsigned)n) return;
    const int s = rp[r], e = rp[r + 1];
    float4 acc = ((const float4*)(x + (size_t)r * HD))[lane];
    const int cnt = e - s;
    int nb_l = ((int)lane < cnt) ? adj[s + lane] : 0;
    const int lim = cnt < 32 ? cnt : 32;
    for (int j = 0; j < lim; ++j) {
        const int nb = __shfl_sync(~0u, nb_l, j);
        float4 u = ((const float4*)(x + (size_t)nb * HD))[lane];
        acc.x += u.x; acc.y += u.y; acc.z += u.z; acc.w += u.w;
    }
    for (int j = s + 32; j < e; ++j) {  // rare high-degree tail
        const int nb = adj[j];
        float4 u = ((const float4*)(x + (size_t)nb * HD))[lane];
        acc.x += u.x; acc.y += u.y; acc.z += u.z; acc.w += u.w;
    }
    ((float4*)(agg + (size_t)r * HD))[lane] = acc;
}

// ---- fused pair lift + aggregation (edge layer 0) ----------------------------
// agg[r] = pair(r) + sum_{nb} pair(nb), pair(i) = y[ep[2i]] + y[ep[2i+1]]
// y = nodeD (51 MB, L2-resident): all gathers are L2 hits.
__global__ void pair_agg(const int* __restrict__ ep,
                         const float* __restrict__ y,
                         const int* __restrict__ rp,
                         const int* __restrict__ adj,
                         float* __restrict__ agg, int n) {
    unsigned t = blockIdx.x * 256u + threadIdx.x;
    unsigned r = t >> 5, lane = t & 31u;
    if (r >= (unsigned)n) return;
    const int s = rp[r], e = rp[r + 1];
    const int cnt = e - s;
    // self pair
    const int i0 = ep[2 * r], i1 = ep[2 * r + 1];
    float4 acc = ((const float4*)(y + (size_t)i0 * HD))[lane];
    float4 b = ((const float4*)(y + (size_t)i1 * HD))[lane];
    acc.x += b.x; acc.y += b.y; acc.z += b.z; acc.w += b.w;
    // neighbor pair indices prefetched per-lane, broadcast via shfl
    int p0_l = 0, p1_l = 0;
    if ((int)lane < cnt) {
        const int nb = adj[s + lane];
        p0_l = ep[2 * nb];
        p1_l = ep[2 * nb + 1];
    }
    const int lim = cnt < 32 ? cnt : 32;
    for (int j = 0; j < lim; ++j) {
        const int q0 = __shfl_sync(~0u, p0_l, j);
        const int q1 = __shfl_sync(~0u, p1_l, j);
        float4 u = ((const float4*)(y + (size_t)q0 * HD))[lane];
        float4 w = ((const float4*)(y + (size_t)q1 * HD))[lane];
        acc.x += u.x + w.x; acc.y += u.y + w.y;
        acc.z += u.z + w.z; acc.w += u.w + w.w;
    }
    for (int j = s + 32; j < e; ++j) {  // rare high-degree tail
        const int nb = adj[j];
        const int q0 = ep[2 * nb], q1 = ep[2 * nb + 1];
        float4 u = ((const float4*)(y + (size_t)q0 * HD))[lane];
        float4 w = ((const float4*)(y + (size_t)q1 * HD))[lane];
        acc.x += u.x + w.x; acc.y += u.y + w.y;
        acc.z += u.z + w.z; acc.w += u.w + w.w;
    }
    ((float4*)(agg + (size_t)r * HD))[lane] = acc;
}

// ----------------------------------------------------------------------------------
extern "C" void kernel_launch(void* const* d_in, const int* in_sizes, int n_in,
                              void* d_out, int out_size) {
    const int*   edge_index = (const int*)d_in[0];
    const float* x_orig     = (const float*)d_in[1];
    const int*   ei_orig    = (const int*)d_in[2];
    const int*   edge_pairs = (const int*)d_in[3];
    const float* init_W1 = (const float*)d_in[4];
    const float* init_b1 = (const float*)d_in[5];
    const float* init_g  = (const float*)d_in[6];
    const float* init_bb = (const float*)d_in[7];
    const float* init_m  = (const float*)d_in[8];
    const float* init_v  = (const float*)d_in[9];
    const float* init_W2 = (const float*)d_in[10];
    const float* init_b2 = (const float*)d_in[11];
    const float* gin_W1  = (const float*)d_in[12];
    const float* gin_b1  = (const float*)d_in[13];
    const float* gin_g   = (const float*)d_in[14];
    const float* gin_bb  = (const float*)d_in[15];
    const float* gin_m   = (const float*)d_in[16];
    const float* gin_v   = (const float*)d_in[17];
    const float* gin_W2  = (const float*)d_in[18];
    const float* gin_b2  = (const float*)d_in[19];
    const float* mlp_W1  = (const float*)d_in[20];
    const float* mlp_b1  = (const float*)d_in[21];
    const float* mlp_g   = (const float*)d_in[22];
    const float* mlp_bb  = (const float*)d_in[23];
    const float* mlp_m   = (const float*)d_in[24];
    const float* mlp_v   = (const float*)d_in[25];
    const float* mlp_W2  = (const float*)d_in[26];
    const float* mlp_b2  = (const float*)d_in[27];
    const float* out_W   = (const float*)d_in[28];
    const float* out_b   = (const float*)d_in[29];
    float* out = (float*)d_out;

    float *nodeA, *nodeB, *nodeC, *nodeD, *edgeA, *edgeB, *edgeC, *bfb;
    __nv_bfloat16 *W1h, *W1l, *W2h, *W2l;
    uint32_t *Wofh, *Wofl, *F1h, *F1l, *F2h, *F2l;
    int *deg, *ex, *bsum, *rpN, *adjN, *curN, *rpE, *adjE, *curE;
    cudaGetSymbolAddress((void**)&nodeA, g_nodeA);
    cudaGetSymbolAddress((void**)&nodeB, g_nodeB);
    cudaGetSymbolAddress((void**)&nodeC, g_nodeC);
    cudaGetSymbolAddress((void**)&nodeD, g_nodeD);
    cudaGetSymbolAddress((void**)&edgeA, g_edgeA);
    cudaGetSymbolAddress((void**)&edgeB, g_edgeB);
    cudaGetSymbolAddress((void**)&edgeC, g_edgeC);
    cudaGetSymbolAddress((void**)&bfb, g_bfb);
    cudaGetSymbolAddress((void**)&W1h, g_W1h);
    cudaGetSymbolAddress((void**)&W1l, g_W1l);
    cudaGetSymbolAddress((void**)&W2h, g_W2h);
    cudaGetSymbolAddress((void**)&W2l, g_W2l);
    cudaGetSymbolAddress((void**)&Wofh, g_Wofh);
    cudaGetSymbolAddress((void**)&Wofl, g_Wofl);
    cudaGetSymbolAddress((void**)&F1h, g_F1h);
    cudaGetSymbolAddress((void**)&F1l, g_F1l);
    cudaGetSymbolAddress((void**)&F2h, g_F2h);
    cudaGetSymbolAddress((void**)&F2l, g_F2l);
    cudaGetSymbolAddress((void**)&deg, g_deg);
    cudaGetSymbolAddress((void**)&ex, g_ex);
    cudaGetSymbolAddress((void**)&bsum, g_bsum);
    cudaGetSymbolAddress((void**)&rpN, g_rpN);
    cudaGetSymbolAddress((void**)&adjN, g_adjN);
    cudaGetSymbolAddress((void**)&curN, g_curN);
    cudaGetSymbolAddress((void**)&rpE, g_rpE);
    cudaGetSymbolAddress((void**)&adjE, g_adjE);
    cudaGetSymbolAddress((void**)&curE, g_curE);

    // ---- weight prep --------------------------------------------------------
    PrepArgs pa;
    const float* W1s[5]  = {init_W1, init_W1 + HD * HD, mlp_W1, gin_W1, gin_W1 + HD * HD};
    const float* b1s[5]  = {init_b1, init_b1 + HD, mlp_b1, gin_b1, gin_b1 + HD};
    const float* gs[5]   = {init_g, init_g + HD, mlp_g, gin_g, gin_g + HD};
    const float* bbs[5]  = {init_bb, init_bb + HD, mlp_bb, gin_bb, gin_bb + HD};
    const float* ms[5]   = {init_m, init_m + HD, mlp_m, gin_m, gin_m + HD};
    const float* vs[5]   = {init_v, init_v + HD, mlp_v, gin_v, gin_v + HD};
    const float* W2s[5]  = {init_W2, init_W2 + HD * HD, mlp_W2, gin_W2, gin_W2 + HD * HD};
    for (int j = 0; j < 5; ++j) {
        pa.W1[j] = W1s[j]; pa.b1[j] = b1s[j]; pa.g[j] = gs[j]; pa.bb[j] = bbs[j];
        pa.m[j] = ms[j]; pa.v[j] = vs[j]; pa.W2[j] = W2s[j];
        pa.W1h[j] = W1h + (size_t)j * HD * HD; pa.W1l[j] = W1l + (size_t)j * HD * HD;
        pa.W2h[j] = W2h + (size_t)j * HD * HD; pa.W2l[j] = W2l + (size_t)j * HD * HD;
        pa.bf[j] = bfb + j * HD;
    }
    pa.Wo = out_W; pa.Wofh = Wofh; pa.Wofl = Wofl;
    prep_weights<<<656, 256>>>(pa);
    frag_mlp<<<128, 256>>>(W1h + 2 * HD * HD, W1l + 2 * HD * HD,
                           W2h + 2 * HD * HD, W2l + 2 * HD * HD,
                           F1h, F1l, F2h, F2l);

    // ---- CSR build: node graph (dst = ei_orig[1]) ----------------------------
    cudaMemsetAsync(deg, 0, NN * sizeof(int));
    count_deg<<<(EO + 255) / 256, 256>>>(ei_orig + EO, EO, deg);
    scan1<<<(NN + 4095) / 4096, 1024>>>(deg, ex, bsum, NN);
    scan2<<<1, 1024>>>(bsum, (NN + 4095) / 4096);
    scan3<<<(NN + 1024) / 1024 + 1, 1024>>>(ex, bsum, rpN, curN, NN, EO);
    fill_csr<<<(EO + 255) / 256, 256>>>(ei_orig, ei_orig + EO, EO, curN, adjN);

    // ---- CSR build: line graph (dst = edge_index[1]) --------------------------
    cudaMemsetAsync(deg, 0, EO * sizeof(int));
    count_deg<<<(EL + 255) / 256, 256>>>(edge_index + EL, EL, deg);
    scan1<<<(EO + 4095) / 4096, 1024>>>(deg, ex, bsum, EO);
    scan2<<<1, 1024>>>(bsum, (EO + 4095) / 4096);
    scan3<<<(EO + 1024) / 1024 + 1, 1024>>>(ex, bsum, rpE, curE, EO, EL);
    fill_csr<<<(EL + 255) / 256, 256>>>(edge_index, edge_index + EL, EL, curE, adjE);

    // ---- main pipeline ----------------------------------------------------------
    const int SMEM_F = 208896;
    cudaFuncSetAttribute(fused_gin<false>,
                         cudaFuncAttributeMaxDynamicSharedMemorySize, SMEM_F);
    cudaFuncSetAttribute(fused_gin<true>,
                         cudaFuncAttributeMaxDynamicSharedMemorySize, SMEM_F);
    cudaFuncSetAttribute(fused_gin_mlp,
                         cudaFuncAttributeMaxDynamicSharedMemorySize, SMEM_F);

    const int GRID = 148;
    const int tilesN = (NN + 63) / 64;
    const int tilesE = (EO + 63) / 64;
    const int gaN = ((unsigned)NN * 32u + 255u) / 256u;
    const int gaE = ((unsigned)EO * 32u + 255u) / 256u;
    const size_t WSZ = (size_t)HD * HD;

    // node layer 0: agg(x_orig) -> nodeB; GEMM -> nodeA
    gather_agg<<<gaN, 256>>>(x_orig, rpN, adjN, nodeB, NN);
    fused_gin<false><<<GRID, 512, SMEM_F>>>(
        nodeB, W1h, W1l, W2h, W2l, nullptr, nullptr,
        bfb, init_b2, nullptr, nodeA, NN, tilesN);

    // node layer 1 + MLP: agg(nodeA) -> nodeC; 4-pass GEMM -> nodeD
    gather_agg<<<gaN, 256>>>(nodeA, rpN, adjN, nodeC, NN);
    fused_gin_mlp<<<GRID, 512, SMEM_F>>>(
        nodeC, W1h + WSZ, W1l + WSZ, W2h + WSZ, W2l + WSZ,
        (const uint4*)F1h, (const uint4*)F1l, (const uint4*)F2h, (const uint4*)F2l,
        bfb + HD, init_b2 + HD, bfb + 2 * HD, mlp_b2, nodeD, NN, tilesN);

    // edge layer 0: fused pair-lift + agg (gathers from L2-resident nodeD)
    pair_agg<<<gaE, 256>>>(edge_pairs, nodeD, rpE, adjE, edgeB, EO);
    fused_gin<false><<<GRID, 512, SMEM_F>>>(
        edgeB, W1h + 3 * WSZ, W1l + 3 * WSZ, W2h + 3 * WSZ, W2l + 3 * WSZ,
        nullptr, nullptr, bfb + 3 * HD, gin_b2, nullptr, edgeC, EO, tilesE);

    // edge layer 1 + head: agg(edgeC) -> edgeA; GEMM+head -> out
    gather_agg<<<gaE, 256>>>(edgeC, rpE, adjE, edgeA, EO);
    fused_gin<true><<<GRID, 512, SMEM_F>>>(
        edgeA, W1h + 4 * WSZ, W1l + 4 * WSZ, W2h + 4 * WSZ, W2l + 4 * WSZ,
        (const uint4*)Wofh, (const uint4*)Wofl,
        bfb + 4 * HD, gin_b2 + HD, out_b, out, EO, tilesE);
}

// round 10
// speedup vs baseline: 1.7056x; 1.0208x over previous
#include <cuda_runtime.h>
#include <cuda_bf16.h>
#include <cstdint>

#define NN 100000
#define EO 600000
#define EL 1200000
#define HD 128
#define OD 64
#define SA 136   // smem row stride (bf16) -> conflict-spread ldmatrix/stmatrix

// ---------------- scratch (device globals) ---------------------------------
static __device__ float g_nodeA[(size_t)NN * HD];
static __device__ float g_nodeB[(size_t)NN * HD];
static __device__ float g_nodeC[(size_t)NN * HD];
static __device__ float g_nodeD[(size_t)NN * HD];
static __device__ float g_edgeA[(size_t)EO * HD];
static __device__ float g_edgeB[(size_t)EO * HD];
static __device__ float g_edgeC[(size_t)EO * HD];
static __device__ __nv_bfloat16 g_W1h[5][HD * HD], g_W1l[5][HD * HD];
static __device__ __nv_bfloat16 g_W2h[5][HD * HD], g_W2l[5][HD * HD];
static __device__ uint32_t g_W2Fh[5][8192], g_W2Fl[5][8192];  // W2 frags (N=128)
static __device__ uint32_t g_F1h[8192], g_F1l[8192];          // mlp W1 frags
static __device__ uint32_t g_Wofh[4096], g_Wofl[4096];        // Wo frags (N=64)
static __device__ float g_bfb[5][HD];
// CSR scratch
static __device__ int g_deg[EO], g_ex[EO], g_bsum[1024];
static __device__ int g_rpN[NN + 1], g_adjN[EO], g_curN[NN];
static __device__ int g_rpE[EO + 1], g_adjE[EL], g_curE[EO];

// ---------------- PTX helpers ----------------------------------------------
__device__ __forceinline__ void ldsm4(uint32_t* r, const void* p) {
    uint32_t a = (uint32_t)__cvta_generic_to_shared(p);
    asm volatile("ldmatrix.sync.aligned.m8n8.x4.shared.b16 {%0,%1,%2,%3}, [%4];"
                 : "=r"(r[0]), "=r"(r[1]), "=r"(r[2]), "=r"(r[3]) : "r"(a));
}
__device__ __forceinline__ void stsm4(void* p, uint32_t r0, uint32_t r1,
                                      uint32_t r2, uint32_t r3) {
    uint32_t a = (uint32_t)__cvta_generic_to_shared(p);
    asm volatile("stmatrix.sync.aligned.m8n8.x4.shared.b16 [%0], {%1,%2,%3,%4};"
                 :: "r"(a), "r"(r0), "r"(r1), "r"(r2), "r"(r3) : "memory");
}
__device__ __forceinline__ void mma_bf16(float* d, const uint32_t* a,
                                         uint32_t b0, uint32_t b1) {
    asm volatile(
        "mma.sync.aligned.m16n8k16.row.col.f32.bf16.bf16.f32 "
        "{%0,%1,%2,%3}, {%4,%5,%6,%7}, {%8,%9}, {%0,%1,%2,%3};"
        : "+f"(d[0]), "+f"(d[1]), "+f"(d[2]), "+f"(d[3])
        : "r"(a[0]), "r"(a[1]), "r"(a[2]), "r"(a[3]), "r"(b0), "r"(b1));
}
__device__ __forceinline__ void cp16(void* sdst, const void* gsrc) {
    uint32_t a = (uint32_t)__cvta_generic_to_shared(sdst);
    asm volatile("cp.async.cg.shared.global [%0], [%1], 16;"
                 :: "r"(a), "l"(gsrc) : "memory");
}
#define CP_COMMIT() asm volatile("cp.async.commit_group;" ::: "memory")
#define CP_WAIT0()  asm volatile("cp.async.wait_group 0;" ::: "memory")

__device__ __forceinline__ uint32_t pack_hi(float a, float b) {
    __nv_bfloat162 t = __halves2bfloat162(__float2bfloat16(a), __float2bfloat16(b));
    return *(uint32_t*)&t;
}
__device__ __forceinline__ uint32_t pack_lo(float a, float b) {
    float ra = a - __bfloat162float(__float2bfloat16(a));
    float rb = b - __bfloat162float(__float2bfloat16(b));
    __nv_bfloat162 t = __halves2bfloat162(__float2bfloat16(ra), __float2bfloat16(rb));
    return *(uint32_t*)&t;
}
__device__ __forceinline__ void split_store4(float4 v, __nv_bfloat16* ph,
                                             __nv_bfloat16* pl) {
    *(uint2*)ph = make_uint2(pack_hi(v.x, v.y), pack_hi(v.z, v.w));
    *(uint2*)pl = make_uint2(pack_lo(v.x, v.y), pack_lo(v.z, v.w));
}
#define BARH(id) asm volatile("bar.sync %0, 256;" :: "r"(id) : "memory")

// ---------------- GEMM passes ------------------------------------------------
// pass with B from smem (W1)
__device__ __forceinline__ void gemm_pass(
    const __nv_bfloat16* As_h, const __nv_bfloat16* As_l,
    const __nv_bfloat16* Wh, const __nv_bfloat16* Wl,
    int rowBase, int colBase, int lrow, int lkoff, float (&acc)[2][4][4]) {
#pragma unroll
    for (int mi = 0; mi < 2; ++mi)
#pragma unroll
        for (int ni = 0; ni < 4; ++ni)
#pragma unroll
            for (int q = 0; q < 4; ++q) acc[mi][ni][q] = 0.f;
#pragma unroll
    for (int ks = 0; ks < 8; ++ks) {
        const int k0 = ks * 16 + lkoff;
        uint32_t ah[2][4], al[2][4];
#pragma unroll
        for (int mi = 0; mi < 2; ++mi) {
            const int base = (rowBase + mi * 16 + lrow) * SA + k0;
            ldsm4(ah[mi], As_h + base);
            ldsm4(al[mi], As_l + base);
        }
        uint32_t bh[2][4], bl[2][4];
#pragma unroll
        for (int nj = 0; nj < 2; ++nj) {
            const int base = (colBase + nj * 16 + lrow) * SA + k0;
            ldsm4(bh[nj], Wh + base);
            ldsm4(bl[nj], Wl + base);
        }
#pragma unroll
        for (int mi = 0; mi < 2; ++mi)
#pragma unroll
            for (int ni = 0; ni < 4; ++ni) {
                const int nj = ni >> 1, hh = ni & 1;
                mma_bf16(acc[mi][ni], ah[mi], bh[nj][hh], bh[nj][hh + 2]);
                mma_bf16(acc[mi][ni], ah[mi], bl[nj][hh], bl[nj][hh + 2]);
                mma_bf16(acc[mi][ni], al[mi], bh[nj][hh], bh[nj][hh + 2]);
            }
    }
}

// pass with B fragments from gmem (N=128; warp covers cols cc*32..cc*32+31)
__device__ __forceinline__ void gemm_pass_frag(
    const __nv_bfloat16* As_h, const __nv_bfloat16* As_l,
    const uint4* __restrict__ Fh, const uint4* __restrict__ Fl,
    int rowBase, int cc, int lrow, int lkoff, int lane, float (&acc)[2][4][4]) {
#pragma unroll
    for (int mi = 0; mi < 2; ++mi)
#pragma unroll
        for (int ni = 0; ni < 4; ++ni)
#pragma unroll
            for (int q = 0; q < 4; ++q) acc[mi][ni][q] = 0.f;
#pragma unroll
    for (int ks = 0; ks < 8; ++ks) {
        const int k0 = ks * 16 + lkoff;
        uint32_t ah[2][4], al[2][4];
#pragma unroll
        for (int mi = 0; mi < 2; ++mi) {
            const int base = (rowBase + mi * 16 + lrow) * SA + k0;
            ldsm4(ah[mi], As_h + base);
            ldsm4(al[mi], As_l + base);
        }
#pragma unroll
        for (int nj = 0; nj < 2; ++nj) {
            const uint4 bh = Fh[((cc * 2 + nj) * 8 + ks) * 32 + lane];
            const uint4 bl = Fl[((cc * 2 + nj) * 8 + ks) * 32 + lane];
#pragma unroll
            for (int mi = 0; mi < 2; ++mi) {
                const int n0 = nj * 2;
                mma_bf16(acc[mi][n0], ah[mi], bh.x, bh.z);
                mma_bf16(acc[mi][n0], ah[mi], bl.x, bl.z);
                mma_bf16(acc[mi][n0], al[mi], bh.x, bh.z);
                mma_bf16(acc[mi][n0 + 1], ah[mi], bh.y, bh.w);
                mma_bf16(acc[mi][n0 + 1], ah[mi], bl.y, bl.w);
                mma_bf16(acc[mi][n0 + 1], al[mi], bh.y, bh.w);
            }
        }
    }
}

// bias+relu then stmatrix both splits back into As
__device__ __forceinline__ void epi_to_smem(
    const float (&acc)[2][4][4], const float (&br)[4][2],
    __nv_bfloat16* As_h, __nv_bfloat16* As_l,
    int rowBase, int colBase, int lane) {
    const int srow = (lane & 7) + ((lane >> 3) & 1) * 8;
    const int scol = (lane >> 4) * 8;
#pragma unroll
    for (int mi = 0; mi < 2; ++mi) {
#pragma unroll
        for (int ng = 0; ng < 2; ++ng) {
            float v[2][4];
#pragma unroll
            for (int q = 0; q < 2; ++q) {
                const int ni = ng * 2 + q;
                v[q][0] = fmaxf(acc[mi][ni][0] + br[ni][0], 0.f);
                v[q][1] = fmaxf(acc[mi][ni][1] + br[ni][1], 0.f);
                v[q][2] = fmaxf(acc[mi][ni][2] + br[ni][0], 0.f);
                v[q][3] = fmaxf(acc[mi][ni][3] + br[ni][1], 0.f);
            }
            const int off = (rowBase + mi * 16 + srow) * SA + colBase + ng * 16 + scol;
            stsm4(As_h + off, pack_hi(v[0][0], v[0][1]), pack_hi(v[0][2], v[0][3]),
                  pack_hi(v[1][0], v[1][1]), pack_hi(v[1][2], v[1][3]));
            stsm4(As_l + off, pack_lo(v[0][0], v[0][1]), pack_lo(v[0][2], v[0][3]),
                  pack_lo(v[1][0], v[1][1]), pack_lo(v[1][2], v[1][3]));
        }
    }
}

// gmem write: acc + bias (+relu) -> C [M,HD]
template <bool RELU>
__device__ __forceinline__ void write_out128(
    const float (&acc)[2][4][4], const float (&br)[4][2],
    float* __restrict__ C, int m0, int rowBase, int colBase,
    int cq, int rq, int M) {
#pragma unroll
    for (int mi = 0; mi < 2; ++mi)
#pragma unroll
        for (int ni = 0; ni < 4; ++ni) {
            const int col = colBase + ni * 8 + cq;
            const int r0 = m0 + rowBase + mi * 16 + rq, r1 = r0 + 8;
            float v00 = acc[mi][ni][0] + br[ni][0];
            float v01 = acc[mi][ni][1] + br[ni][1];
            float v10 = acc[mi][ni][2] + br[ni][0];
            float v11 = acc[mi][ni][3] + br[ni][1];
            if (RELU) {
                v00 = fmaxf(v00, 0.f); v01 = fmaxf(v01, 0.f);
                v10 = fmaxf(v10, 0.f); v11 = fmaxf(v11, 0.f);
            }
            if (r0 < M) *(float2*)(C + (size_t)r0 * HD + col) = make_float2(v00, v01);
            if (r1 < M) *(float2*)(C + (size_t)r1 * HD + col) = make_float2(v10, v11);
        }
}

// smem layout: per half: As_h(17408) As_l(17408) stage(32768) = 67584
// then W1h(34816) W1l(34816) -> total 204800
#define HALF_SZ 67584
#define W1_OFF  135168
#define SMEM_F  204800

// issue cp.async for one 64-row tile into this half's stage buffer
__device__ __forceinline__ void issue_cp_tile(const float* __restrict__ A,
                                              float* stagef, int tile, int M,
                                              int tih) {
#pragma unroll
    for (int q = 0; q < 8; ++q) {
        const int i = tih + 256 * q;          // 0..2047
        const int r = i >> 5, c = i & 31;     // 32 x 16B chunks per row
        const int grow = tile * 64 + r;
        float* dst = stagef + r * 128 + c * 4;
        if (grow < M)
            cp16(dst, A + (size_t)grow * 128 + c * 4);
        else
            *(float4*)dst = make_float4(0.f, 0.f, 0.f, 0.f);
    }
}

// ---------------- fused GIN layer (pass1 smem-W1, pass2 frag-W2, opt head) --
template <bool HEAD>
__global__ __launch_bounds__(512, 1) void fused_gin(
    const float* __restrict__ A,
    const __nv_bfloat16* __restrict__ W1hI, const __nv_bfloat16* __restrict__ W1lI,
    const uint4* __restrict__ W2Fh, const uint4* __restrict__ W2Fl,
    const uint4* __restrict__ WoFh, const uint4* __restrict__ WoFl,
    const float* __restrict__ b1, const float* __restrict__ b2,
    const float* __restrict__ b3,
    float* __restrict__ C, int M, int nTiles) {
    extern __shared__ char smem[];
    const int tid = threadIdx.x, lane = tid & 31, wid = tid >> 5;
    const int half = wid >> 3, wl = wid & 7, tih = tid & 255;

    __nv_bfloat16* As_h = (__nv_bfloat16*)(smem + half * HALF_SZ);
    __nv_bfloat16* As_l = (__nv_bfloat16*)(smem + half * HALF_SZ + 17408);
    float* stagef = (float*)(smem + half * HALF_SZ + 34816);
    __nv_bfloat16* Wah = (__nv_bfloat16*)(smem + W1_OFF);
    __nv_bfloat16* Wal = (__nv_bfloat16*)(smem + W1_OFF + 34816);

    {   // stage W1 once per CTA
        const uint4* s1 = (const uint4*)W1hI;
        const uint4* s2 = (const uint4*)W1lI;
        for (int i = tid; i < 2048; i += 512) {
            int r = i >> 4, c = i & 15;
            *(uint4*)(Wah + r * SA + c * 8) = s1[i];
            *(uint4*)(Wal + r * SA + c * 8) = s2[i];
        }
    }

    const int barid = 1 + half;
    const int rowBase = (wl >> 2) * 32, colBase = (wl & 3) * 32;
    const int lrow = lane & 15, lkoff = (lane >> 4) * 8;
    const int cq = (lane & 3) * 2, rq = lane >> 2;
    const int cc = wl & 3;

    float b1r[4][2], b2r[4][2], b3r[2][2];
#pragma unroll
    for (int ni = 0; ni < 4; ++ni) {
        const int col = colBase + ni * 8 + cq;
        b1r[ni][0] = b1[col]; b1r[ni][1] = b1[col + 1];
        b2r[ni][0] = b2[col]; b2r[ni][1] = b2[col + 1];
    }
    if (HEAD) {
#pragma unroll
        for (int ni = 0; ni < 2; ++ni) {
            const int col = cc * 16 + ni * 8 + cq;
            b3r[ni][0] = b3[col]; b3r[ni][1] = b3[col + 1];
        }
    }

    int tile = blockIdx.x * 2 + half;
    if (tile < nTiles) issue_cp_tile(A, stagef, tile, M, tih);
    CP_COMMIT();
    __syncthreads();   // W1 staged + stage prologue ordered

    for (; tile < nTiles; tile += gridDim.x * 2) {
        const int m0 = tile * 64;
        CP_WAIT0();
        BARH(barid);     // all half threads' cp.async data landed (+ As free)

        // build A tile from staged f32 (smem->smem split)
#pragma unroll
        for (int rr = 0; rr < 8; ++rr) {
            const int r = wl * 8 + rr;
            float4 v = ((const float4*)stagef)[r * 32 + lane];
            split_store4(v, As_h + r * SA + lane * 4, As_l + r * SA + lane * 4);
        }
        BARH(barid);

        // prefetch next tile while computing
        const int nxt = tile + gridDim.x * 2;
        if (nxt < nTiles) issue_cp_tile(A, stagef, nxt, M, tih);
        CP_COMMIT();

        float acc[2][4][4];
        gemm_pass(As_h, As_l, Wah, Wal, rowBase, colBase, lrow, lkoff, acc);
        BARH(barid);
        epi_to_smem(acc, b1r, As_h, As_l, rowBase, colBase, lane);
        BARH(barid);
        gemm_pass_frag(As_h, As_l, W2Fh, W2Fl, rowBase, cc, lrow, lkoff, lane, acc);

        if (!HEAD) {
            write_out128<true>(acc, b2r, C, m0, rowBase, colBase, cq, rq, M);
        } else {
            BARH(barid);
            epi_to_smem(acc, b2r, As_h, As_l, rowBase, colBase, lane);
            BARH(barid);
            float acc3[2][2][4];
#pragma unroll
            for (int mi = 0; mi < 2; ++mi)
#pragma unroll
                for (int ni = 0; ni < 2; ++ni)
#pragma unroll
                    for (int q = 0; q < 4; ++q) acc3[mi][ni][q] = 0.f;
#pragma unroll
            for (int ks = 0; ks < 8; ++ks) {
                const int k0 = ks * 16 + lkoff;
                uint32_t ah[2][4], al[2][4];
#pragma unroll
                for (int mi = 0; mi < 2; ++mi) {
                    const int base = (rowBase + mi * 16 + lrow) * SA + k0;
                    ldsm4(ah[mi], As_h + base);
                    ldsm4(al[mi], As_l + base);
                }
                const uint4 bh = WoFh[(cc * 8 + ks) * 32 + lane];
                const uint4 bl = WoFl[(cc * 8 + ks) * 32 + lane];
#pragma unroll
                for (int mi = 0; mi < 2; ++mi) {
                    mma_bf16(acc3[mi][0], ah[mi], bh.x, bh.z);
                    mma_bf16(acc3[mi][0], ah[mi], bl.x, bl.z);
                    mma_bf16(acc3[mi][0], al[mi], bh.x, bh.z);
                    mma_bf16(acc3[mi][1], ah[mi], bh.y, bh.w);
                    mma_bf16(acc3[mi][1], ah[mi], bl.y, bl.w);
                    mma_bf16(acc3[mi][1], al[mi], bh.y, bh.w);
                }
            }
#pragma unroll
            for (int mi = 0; mi < 2; ++mi)
#pragma unroll
                for (int ni = 0; ni < 2; ++ni) {
                    const int col = cc * 16 + ni * 8 + cq;
                    const int r0 = m0 + rowBase + mi * 16 + rq, r1 = r0 + 8;
                    if (r0 < M)
                        *(float2*)(C + (size_t)r0 * OD + col) = make_float2(
                            acc3[mi][ni][0] + b3r[ni][0], acc3[mi][ni][1] + b3r[ni][1]);
                    if (r1 < M)
                        *(float2*)(C + (size_t)r1 * OD + col) = make_float2(
                            acc3[mi][ni][2] + b3r[ni][0], acc3[mi][ni][3] + b3r[ni][1]);
                }
        }
    }
}

// ---------------- fused node layer 1 + MLP (4 passes) ----------------------
__global__ __launch_bounds__(512, 1) void fused_gin_mlp(
    const float* __restrict__ A,
    const __nv_bfloat16* __restrict__ W1hI, const __nv_bfloat16* __restrict__ W1lI,
    const uint4* __restrict__ W2Fh, const uint4* __restrict__ W2Fl,
    const uint4* __restrict__ F1h, const uint4* __restrict__ F1l,
    const uint4* __restrict__ F2h, const uint4* __restrict__ F2l,
    const float* __restrict__ b1, const float* __restrict__ b2,
    const float* __restrict__ b3, const float* __restrict__ b4,
    float* __restrict__ C, int M, int nTiles) {
    extern __shared__ char smem[];
    const int tid = threadIdx.x, lane = tid & 31, wid = tid >> 5;
    const int half = wid >> 3, wl = wid & 7, tih = tid & 255;

    __nv_bfloat16* As_h = (__nv_bfloat16*)(smem + half * HALF_SZ);
    __nv_bfloat16* As_l = (__nv_bfloat16*)(smem + half * HALF_SZ + 17408);
    float* stagef = (float*)(smem + half * HALF_SZ + 34816);
    __nv_bfloat16* Wah = (__nv_bfloat16*)(smem + W1_OFF);
    __nv_bfloat16* Wal = (__nv_bfloat16*)(smem + W1_OFF + 34816);

    {
        const uint4* s1 = (const uint4*)W1hI;
        const uint4* s2 = (const uint4*)W1lI;
        for (int i = tid; i < 2048; i += 512) {
            int r = i >> 4, c = i & 15;
            *(uint4*)(Wah + r * SA + c * 8) = s1[i];
            *(uint4*)(Wal + r * SA + c * 8) = s2[i];
        }
    }

    const int barid = 1 + half;
    const int rowBase = (wl >> 2) * 32, colBase = (wl & 3) * 32;
    const int lrow = lane & 15, lkoff = (lane >> 4) * 8;
    const int cq = (lane & 3) * 2, rq = lane >> 2;
    const int cc = wl & 3;

    float b1r[4][2], b2r[4][2], b3r[4][2], b4r[4][2];
#pragma unroll
    for (int ni = 0; ni < 4; ++ni) {
        const int col = colBase + ni * 8 + cq;
        b1r[ni][0] = b1[col]; b1r[ni][1] = b1[col + 1];
        b2r[ni][0] = b2[col]; b2r[ni][1] = b2[col + 1];
        b3r[ni][0] = b3[col]; b3r[ni][1] = b3[col + 1];
        b4r[ni][0] = b4[col]; b4r[ni][1] = b4[col + 1];
    }

    int tile = blockIdx.x * 2 + half;
    if (tile < nTiles) issue_cp_tile(A, stagef, tile, M, tih);
    CP_COMMIT();
    __syncthreads();

    for (; tile < nTiles; tile += gridDim.x * 2) {
        const int m0 = tile * 64;
        CP_WAIT0();
        BARH(barid);
#pragma unroll
        for (int rr = 0; rr < 8; ++rr) {
            const int r = wl * 8 + rr;
            float4 v = ((const float4*)stagef)[r * 32 + lane];
            split_store4(v, As_h + r * SA + lane * 4, As_l + r * SA + lane * 4);
        }
        BARH(barid);
        const int nxt = tile + gridDim.x * 2;
        if (nxt < nTiles) issue_cp_tile(A, stagef, nxt, M, tih);
        CP_COMMIT();

        float acc[2][4][4];
        gemm_pass(As_h, As_l, Wah, Wal, rowBase, colBase, lrow, lkoff, acc);
        BARH(barid);
        epi_to_smem(acc, b1r, As_h, As_l, rowBase, colBase, lane);
        BARH(barid);
        gemm_pass_frag(As_h, As_l, W2Fh, W2Fl, rowBase, cc, lrow, lkoff, lane, acc);
        BARH(barid);
        epi_to_smem(acc, b2r, As_h, As_l, rowBase, colBase, lane);  // layer out
        BARH(barid);
        gemm_pass_frag(As_h, As_l, F1h, F1l, rowBase, cc, lrow, lkoff, lane, acc);
        BARH(barid);
        epi_to_smem(acc, b3r, As_h, As_l, rowBase, colBase, lane);  // mlp hidden
        BARH(barid);
        gemm_pass_frag(As_h, As_l, F2h, F2l, rowBase, cc, lrow, lkoff, lane, acc);
        write_out128<false>(acc, b4r, C, m0, rowBase, colBase, cq, rq, M);
    }
}

// ---------------- weight prep ------------------------------------------------
struct PrepArgs {
    const float *W1[5], *b1[5], *g[5], *bb[5], *m[5], *v[5], *W2[5], *Wo;
    __nv_bfloat16 *W1h[5], *W1l[5], *W2h[5], *W2l[5];
    uint32_t *Wofh, *Wofl;
    float* bf[5];
};

__global__ void prep_weights(PrepArgs a) {
    const int blk = blockIdx.x, tid = threadIdx.x;
    if (blk < 320) {
        const int j = blk >> 6;
        const int idx = ((blk & 63) << 8) + tid;
        const int k = idx >> 7, n = idx & 127;
        float s = a.g[j][n] * rsqrtf(a.v[j][n] + 1e-5f);
        float val = a.W1[j][idx] * s;
        __nv_bfloat16 h = __float2bfloat16(val);
        a.W1h[j][n * 128 + k] = h;
        a.W1l[j][n * 128 + k] = __float2bfloat16(val - __bfloat162float(h));
        if (idx < 128)
            a.bf[j][idx] = a.b1[j][idx] * s + a.bb[j][idx] - a.m[j][idx] * s;
    } else if (blk < 640) {
        const int j = (blk - 320) >> 6;
        const int idx = (((blk - 320) & 63) << 8) + tid;
        const int k = idx >> 7, n = idx & 127;
        float val = a.W2[j][idx];
        __nv_bfloat16 h = __float2bfloat16(val);
        a.W2h[j][n * 128 + k] = h;
        a.W2l[j][n * 128 + k] = __float2bfloat16(val - __bfloat162float(h));
    } else {
        const int idx = ((blk - 640) << 8) + tid;  // 0..4095 (Wo frags)
        const int j = idx & 3, L = (idx >> 2) & 31;
        const int ks = (idx >> 7) & 7, cc = idx >> 10;
        const int n = cc * 16 + (j & 1) * 8 + (L >> 2);
        const int k = ks * 16 + ((j >> 1)) * 8 + (L & 3) * 2;
        float v0 = a.Wo[k * OD + n];
        float v1 = a.Wo[(k + 1) * OD + n];
        a.Wofh[((cc * 8 + ks) * 32 + L) * 4 + j] = pack_hi(v0, v1);
        a.Wofl[((cc * 8 + ks) * 32 + L) * 4 + j] = pack_lo(v0, v1);
    }
}

// convert n-major bf16 images into ldmatrix-order frag arrays (N=128)
// 12 jobs: m=0..4 W2h[j]->W2Fh[j]; m=5..9 W2l; m=10 W1h[2]->F1h; m=11 W1l[2]->F1l
struct FragArgs {
    const __nv_bfloat16* src[12];
    uint32_t* dst[12];
};
__global__ void frag_all(FragArgs a) {
    const int i = blockIdx.x * 256 + threadIdx.x;   // 0..98303
    const int m = i >> 13, e = i & 8191;
    const int j = e & 3, L = (e >> 2) & 31;
    const int ks = (e >> 7) & 7, g = e >> 10;
    const int n = g * 16 + (j & 1) * 8 + (L >> 2);
    const int k = ks * 16 + (j >> 1) * 8 + (L & 3) * 2;
    a.dst[m][e] = *(const uint32_t*)(a.src[m] + n * 128 + k);
}

// ---------------- CSR build ----------------------------------------------------
__global__ void count_deg(const int* __restrict__ dst, int E, int* __restrict__ deg) {
    int e = blockIdx.x * 256 + threadIdx.x;
    if (e < E) atomicAdd(&deg[dst[e]], 1);
}

__global__ void scan1(const int* __restrict__ deg, int* __restrict__ ex,
                      int* __restrict__ bsum, int n) {
    __shared__ int wsum[32];
    const int t = threadIdx.x;
    const int base = blockIdx.x * 4096 + t * 4;
    int v[4], s = 0;
#pragma unroll
    for (int i = 0; i < 4; ++i) {
        int idx = base + i;
        v[i] = idx < n ? deg[idx] : 0;
        s += v[i];
    }
    const int lane = t & 31, w = t >> 5;
    int ps = s;
#pragma unroll
    for (int o = 1; o < 32; o <<= 1) {
        int y = __shfl_up_sync(~0u, ps, o);
        if (lane >= o) ps += y;
    }
    if (lane == 31) wsum[w] = ps;
    __syncthreads();
    if (w == 0) {
        int x = wsum[lane];
#pragma unroll
        for (int o = 1; o < 32; o <<= 1) {
            int y = __shfl_up_sync(~0u, x, o);
            if (lane >= o) x += y;
        }
        wsum[lane] = x;
    }
    __syncthreads();
    const int warpoff = w ? wsum[w - 1] : 0;
    int run = warpoff + ps - s;
#pragma unroll
    for (int i = 0; i < 4; ++i) {
        int idx = base + i;
        if (idx < n) ex[idx] = run;
        run += v[i];
    }
    if (t == 0) bsum[blockIdx.x] = wsum[31];
}

__global__ void scan2(int* __restrict__ bsum, int nb) {
    __shared__ int sm_[1024];
    const int t = threadIdx.x;
    int v = (t < nb) ? bsum[t] : 0;
    sm_[t] = v;
    __syncthreads();
    for (int o = 1; o < 1024; o <<= 1) {
        int y = (t >= o) ? sm_[t - o] : 0;
        __syncthreads();
        sm_[t] += y;
        __syncthreads();
    }
    if (t < nb) bsum[t] = sm_[t] - v;
}

__global__ void scan3(const int* __restrict__ ex, const int* __restrict__ boff,
                      int* __restrict__ rp, int* __restrict__ cur, int n, int E) {
    int i = blockIdx.x * 1024 + threadIdx.x;
    if (i < n) {
        int vv = ex[i] + boff[i >> 12];
        rp[i] = vv;
        cur[i] = vv;
    } else if (i == n) {
        rp[n] = E;
    }
}

__global__ void fill_csr(const int* __restrict__ src, const int* __restrict__ dst,
                         int E, int* __restrict__ cur, int* __restrict__ adj) {
    int e = blockIdx.x * 256 + threadIdx.x;
    if (e < E) {
        int p = atomicAdd(&cur[dst[e]], 1);
        adj[p] = src[e];
    }
}

// ---------------- gather aggregation: agg[r] = x[r] + sum x[nbr] ---------------
__global__ void gather_agg(const float* __restrict__ x,
                           const int* __restrict__ rp,
                           const int* __restrict__ adj,
                           float* __restrict__ agg, int n) {
    unsigned t = blockIdx.x * 256u + threadIdx.x;
    unsigned r = t >> 5, lane = t & 31u;
    if (r >= (unsigned)n) return;
    const int s = rp[r], e = rp[r + 1];
    float4 acc = ((const float4*)(x + (size_t)r * HD))[lane];
    const int cnt = e - s;
    int nb_l = ((int)lane < cnt) ? adj[s + lane] : 0;
    const int lim = cnt < 32 ? cnt : 32;
    for (int j = 0; j < lim; ++j) {
        const int nb = __shfl_sync(~0u, nb_l, j);
        float4 u = ((const float4*)(x + (size_t)nb * HD))[lane];
        acc.x += u.x; acc.y += u.y; acc.z += u.z; acc.w += u.w;
    }
    for (int j = s + 32; j < e; ++j) {
        const int nb = adj[j];
        float4 u = ((const float4*)(x + (size_t)nb * HD))[lane];
        acc.x += u.x; acc.y += u.y; acc.z += u.z; acc.w += u.w;
    }
    ((float4*)(agg + (size_t)r * HD))[lane] = acc;
}

// ---- fused pair lift + aggregation (edge layer 0; y L2-resident) ------------
__global__ void pair_agg(const int* __restrict__ ep,
                         const float* __restrict__ y,
                         const int* __restrict__ rp,
                         const int* __restrict__ adj,
                         float* __restrict__ agg, int n) {
    unsigned t = blockIdx.x * 256u + threadIdx.x;
    unsigned r = t >> 5, lane = t & 31u;
    if (r >= (unsigned)n) return;
    const int s = rp[r], e = rp[r + 1];
    const int cnt = e - s;
    const int i0 = ep[2 * r], i1 = ep[2 * r + 1];
    float4 acc = ((const float4*)(y + (size_t)i0 * HD))[lane];
    float4 b = ((const float4*)(y + (size_t)i1 * HD))[lane];
    acc.x += b.x; acc.y += b.y; acc.z += b.z; acc.w += b.w;
    int p0_l = 0, p1_l = 0;
    if ((int)lane < cnt) {
        const int nb = adj[s + lane];
        p0_l = ep[2 * nb];
        p1_l = ep[2 * nb + 1];
    }
    const int lim = cnt < 32 ? cnt : 32;
    for (int j = 0; j < lim; ++j) {
        const int q0 = __shfl_sync(~0u, p0_l, j);
        const int q1 = __shfl_sync(~0u, p1_l, j);
        float4 u = ((const float4*)(y + (size_t)q0 * HD))[lane];
        float4 w = ((const float4*)(y + (size_t)q1 * HD))[lane];
        acc.x += u.x + w.x; acc.y += u.y + w.y;
        acc.z += u.z + w.z; acc.w += u.w + w.w;
    }
    for (int j = s + 32; j < e; ++j) {
        const int nb = adj[j];
        const int q0 = ep[2 * nb], q1 = ep[2 * nb + 1];
        float4 u = ((const float4*)(y + (size_t)q0 * HD))[lane];
        float4 w = ((const float4*)(y + (size_t)q1 * HD))[lane];
        acc.x += u.x + w.x; acc.y += u.y + w.y;
        acc.z += u.z + w.z; acc.w += u.w + w.w;
    }
    ((float4*)(agg + (size_t)r * HD))[lane] = acc;
}

// ----------------------------------------------------------------------------------
extern "C" void kernel_launch(void* const* d_in, const int* in_sizes, int n_in,
                              void* d_out, int out_size) {
    const int*   edge_index = (const int*)d_in[0];
    const float* x_orig     = (const float*)d_in[1];
    const int*   ei_orig    = (const int*)d_in[2];
    const int*   edge_pairs = (const int*)d_in[3];
    const float* init_W1 = (const float*)d_in[4];
    const float* init_b1 = (const float*)d_in[5];
    const float* init_g  = (const float*)d_in[6];
    const float* init_bb = (const float*)d_in[7];
    const float* init_m  = (const float*)d_in[8];
    const float* init_v  = (const float*)d_in[9];
    const float* init_W2 = (const float*)d_in[10];
    const float* init_b2 = (const float*)d_in[11];
    const float* gin_W1  = (const float*)d_in[12];
    const float* gin_b1  = (const float*)d_in[13];
    const float* gin_g   = (const float*)d_in[14];
    const float* gin_bb  = (const float*)d_in[15];
    const float* gin_m   = (const float*)d_in[16];
    const float* gin_v   = (const float*)d_in[17];
    const float* gin_W2  = (const float*)d_in[18];
    const float* gin_b2  = (const float*)d_in[19];
    const float* mlp_W1  = (const float*)d_in[20];
    const float* mlp_b1  = (const float*)d_in[21];
    const float* mlp_g   = (const float*)d_in[22];
    const float* mlp_bb  = (const float*)d_in[23];
    const float* mlp_m   = (const float*)d_in[24];
    const float* mlp_v   = (const float*)d_in[25];
    const float* mlp_W2  = (const float*)d_in[26];
    const float* mlp_b2  = (const float*)d_in[27];
    const float* out_W   = (const float*)d_in[28];
    const float* out_b   = (const float*)d_in[29];
    float* out = (float*)d_out;

    float *nodeA, *nodeB, *nodeC, *nodeD, *edgeA, *edgeB, *edgeC, *bfb;
    __nv_bfloat16 *W1h, *W1l, *W2h, *W2l;
    uint32_t *W2Fh, *W2Fl, *F1h, *F1l, *Wofh, *Wofl;
    int *deg, *ex, *bsum, *rpN, *adjN, *curN, *rpE, *adjE, *curE;
    cudaGetSymbolAddress((void**)&nodeA, g_nodeA);
    cudaGetSymbolAddress((void**)&nodeB, g_nodeB);
    cudaGetSymbolAddress((void**)&nodeC, g_nodeC);
    cudaGetSymbolAddress((void**)&nodeD, g_nodeD);
    cudaGetSymbolAddress((void**)&edgeA, g_edgeA);
    cudaGetSymbolAddress((void**)&edgeB, g_edgeB);
    cudaGetSymbolAddress((void**)&edgeC, g_edgeC);
    cudaGetSymbolAddress((void**)&bfb, g_bfb);
    cudaGetSymbolAddress((void**)&W1h, g_W1h);
    cudaGetSymbolAddress((void**)&W1l, g_W1l);
    cudaGetSymbolAddress((void**)&W2h, g_W2h);
    cudaGetSymbolAddress((void**)&W2l, g_W2l);
    cudaGetSymbolAddress((void**)&W2Fh, g_W2Fh);
    cudaGetSymbolAddress((void**)&W2Fl, g_W2Fl);
    cudaGetSymbolAddress((void**)&F1h, g_F1h);
    cudaGetSymbolAddress((void**)&F1l, g_F1l);
    cudaGetSymbolAddress((void**)&Wofh, g_Wofh);
    cudaGetSymbolAddress((void**)&Wofl, g_Wofl);
    cudaGetSymbolAddress((void**)&deg, g_deg);
    cudaGetSymbolAddress((void**)&ex, g_ex);
    cudaGetSymbolAddress((void**)&bsum, g_bsum);
    cudaGetSymbolAddress((void**)&rpN, g_rpN);
    cudaGetSymbolAddress((void**)&adjN, g_adjN);
    cudaGetSymbolAddress((void**)&curN, g_curN);
    cudaGetSymbolAddress((void**)&rpE, g_rpE);
    cudaGetSymbolAddress((void**)&adjE, g_adjE);
    cudaGetSymbolAddress((void**)&curE, g_curE);

    // ---- weight prep --------------------------------------------------------
    PrepArgs pa;
    const float* W1s[5]  = {init_W1, init_W1 + HD * HD, mlp_W1, gin_W1, gin_W1 + HD * HD};
    const float* b1s[5]  = {init_b1, init_b1 + HD, mlp_b1, gin_b1, gin_b1 + HD};
    const float* gs[5]   = {init_g, init_g + HD, mlp_g, gin_g, gin_g + HD};
    const float* bbs[5]  = {init_bb, init_bb + HD, mlp_bb, gin_bb, gin_bb + HD};
    const float* ms[5]   = {init_m, init_m + HD, mlp_m, gin_m, gin_m + HD};
    const float* vs[5]   = {init_v, init_v + HD, mlp_v, gin_v, gin_v + HD};
    const float* W2s[5]  = {init_W2, init_W2 + HD * HD, mlp_W2, gin_W2, gin_W2 + HD * HD};
    for (int j = 0; j < 5; ++j) {
        pa.W1[j] = W1s[j]; pa.b1[j] = b1s[j]; pa.g[j] = gs[j]; pa.bb[j] = bbs[j];
        pa.m[j] = ms[j]; pa.v[j] = vs[j]; pa.W2[j] = W2s[j];
        pa.W1h[j] = W1h + (size_t)j * HD * HD; pa.W1l[j] = W1l + (size_t)j * HD * HD;
        pa.W2h[j] = W2h + (size_t)j * HD * HD; pa.W2l[j] = W2l + (size_t)j * HD * HD;
        pa.bf[j] = bfb + j * HD;
    }
    pa.Wo = out_W; pa.Wofh = Wofh; pa.Wofl = Wofl;
    prep_weights<<<656, 256>>>(pa);

    FragArgs fa;
    for (int j = 0; j < 5; ++j) {
        fa.src[j] = W2h + (size_t)j * HD * HD;     fa.dst[j] = W2Fh + (size_t)j * 8192;
        fa.src[5 + j] = W2l + (size_t)j * HD * HD; fa.dst[5 + j] = W2Fl + (size_t)j * 8192;
    }
    fa.src[10] = W1h + (size_t)2 * HD * HD; fa.dst[10] = F1h;
    fa.src[11] = W1l + (size_t)2 * HD * HD; fa.dst[11] = F1l;
    frag_all<<<384, 256>>>(fa);

    // ---- CSR build: node graph (dst = ei_orig[1]) ----------------------------
    cudaMemsetAsync(deg, 0, NN * sizeof(int));
    count_deg<<<(EO + 255) / 256, 256>>>(ei_orig + EO, EO, deg);
    scan1<<<(NN + 4095) / 4096, 1024>>>(deg, ex, bsum, NN);
    scan2<<<1, 1024>>>(bsum, (NN + 4095) / 4096);
    scan3<<<(NN + 1024) / 1024 + 1, 1024>>>(ex, bsum, rpN, curN, NN, EO);
    fill_csr<<<(EO + 255) / 256, 256>>>(ei_orig, ei_orig + EO, EO, curN, adjN);

    // ---- CSR build: line graph (dst = edge_index[1]) --------------------------
    cudaMemsetAsync(deg, 0, EO * sizeof(int));
    count_deg<<<(EL + 255) / 256, 256>>>(edge_index + EL, EL, deg);
    scan1<<<(EO + 4095) / 4096, 1024>>>(deg, ex, bsum, EO);
    scan2<<<1, 1024>>>(bsum, (EO + 4095) / 4096);
    scan3<<<(EO + 1024) / 1024 + 1, 1024>>>(ex, bsum, rpE, curE, EO, EL);
    fill_csr<<<(EL + 255) / 256, 256>>>(edge_index, edge_index + EL, EL, curE, adjE);

    // ---- main pipeline ----------------------------------------------------------
    cudaFuncSetAttribute(fused_gin<false>,
                         cudaFuncAttributeMaxDynamicSharedMemorySize, SMEM_F);
    cudaFuncSetAttribute(fused_gin<true>,
                         cudaFuncAttributeMaxDynamicSharedMemorySize, SMEM_F);
    cudaFuncSetAttribute(fused_gin_mlp,
                         cudaFuncAttributeMaxDynamicSharedMemorySize, SMEM_F);

    const int GRID = 148;
    const int tilesN = (NN + 63) / 64;
    const int tilesE = (EO + 63) / 64;
    const int gaN = ((unsigned)NN * 32u + 255u) / 256u;
    const int gaE = ((unsigned)EO * 32u + 255u) / 256u;
    const size_t WSZ = (size_t)HD * HD;

    // node layer 0: agg(x_orig) -> nodeB; GEMM -> nodeA
    gather_agg<<<gaN, 256>>>(x_orig, rpN, adjN, nodeB, NN);
    fused_gin<false><<<GRID, 512, SMEM_F>>>(
        nodeB, W1h, W1l,
        (const uint4*)W2Fh, (const uint4*)W2Fl, nullptr, nullptr,
        bfb, init_b2, nullptr, nodeA, NN, tilesN);

    // node layer 1 + MLP: agg(nodeA) -> nodeC; 4-pass GEMM -> nodeD
    gather_agg<<<gaN, 256>>>(nodeA, rpN, adjN, nodeC, NN);
    fused_gin_mlp<<<GRID, 512, SMEM_F>>>(
        nodeC, W1h + WSZ, W1l + WSZ,
        (const uint4*)(W2Fh + 8192), (const uint4*)(W2Fl + 8192),
        (const uint4*)F1h, (const uint4*)F1l,
        (const uint4*)(W2Fh + 2 * 8192), (const uint4*)(W2Fl + 2 * 8192),
        bfb + HD, init_b2 + HD, bfb + 2 * HD, mlp_b2, nodeD, NN, tilesN);

    // edge layer 0: fused pair-lift + agg (L2-resident nodeD) -> edgeB; GEMM -> edgeC
    pair_agg<<<gaE, 256>>>(edge_pairs, nodeD, rpE, adjE, edgeB, EO);
    fused_gin<false><<<GRID, 512, SMEM_F>>>(
        edgeB, W1h + 3 * WSZ, W1l + 3 * WSZ,
        (const uint4*)(W2Fh + 3 * 8192), (const uint4*)(W2Fl + 3 * 8192),
        nullptr, nullptr, bfb + 3 * HD, gin_b2, nullptr, edgeC, EO, tilesE);

    // edge layer 1 + head: agg(edgeC) -> edgeA; GEMM+head -> out
    gather_agg<<<gaE, 256>>>(edgeC, rpE, adjE, edgeA, EO);
    fused_gin<true><<<GRID, 512, SMEM_F>>>(
        edgeA, W1h + 4 * WSZ, W1l + 4 * WSZ,
        (const uint4*)(W2Fh + 4 * 8192), (const uint4*)(W2Fl + 4 * 8192),
        (const uint4*)Wofh, (const uint4*)Wofl,
        bfb + 4 * HD, gin_b2 + HD, out_b, out, EO, tilesE);
}

// round 11
// speedup vs baseline: 1.7141x; 1.0050x over previous
#include <cuda_runtime.h>
#include <cuda_bf16.h>
#include <cstdint>

#define NN 100000
#define EO 600000
#define EL 1200000
#define HD 128
#define OD 64
#define SA 136   // smem row stride (bf16) -> conflict-spread ldmatrix/stmatrix

// ---------------- scratch (device globals) ---------------------------------
static __device__ float g_nodeA[(size_t)NN * HD];
static __device__ float g_nodeB[(size_t)NN * HD];
static __device__ float g_nodeC[(size_t)NN * HD];
static __device__ float g_nodeD[(size_t)NN * HD];
static __device__ float g_edgeA[(size_t)EO * HD];
static __device__ float g_edgeB[(size_t)EO * HD];
static __device__ float g_edgeC[(size_t)EO * HD];
static __device__ __nv_bfloat16 g_W1h[5][HD * HD], g_W1l[5][HD * HD];
static __device__ __nv_bfloat16 g_W2h[5][HD * HD], g_W2l[5][HD * HD];
static __device__ uint32_t g_W1Fh[5][8192], g_W1Fl[5][8192];  // W1 frags (N=128)
static __device__ uint32_t g_W2Fh[5][8192], g_W2Fl[5][8192];  // W2 frags (N=128)
static __device__ uint32_t g_Wofh[4096], g_Wofl[4096];        // Wo frags (N=64)
static __device__ float g_bfb[5][HD];
// CSR scratch
static __device__ int g_deg[EO], g_ex[EO], g_bsum[1024];
static __device__ int g_rpN[NN + 1], g_adjN[EO], g_curN[NN];
static __device__ int g_rpE[EO + 1], g_adjE[EL], g_curE[EO];

// ---------------- PTX helpers ----------------------------------------------
__device__ __forceinline__ void ldsm4(uint32_t* r, const void* p) {
    uint32_t a = (uint32_t)__cvta_generic_to_shared(p);
    asm volatile("ldmatrix.sync.aligned.m8n8.x4.shared.b16 {%0,%1,%2,%3}, [%4];"
                 : "=r"(r[0]), "=r"(r[1]), "=r"(r[2]), "=r"(r[3]) : "r"(a));
}
__device__ __forceinline__ void stsm4(void* p, uint32_t r0, uint32_t r1,
                                      uint32_t r2, uint32_t r3) {
    uint32_t a = (uint32_t)__cvta_generic_to_shared(p);
    asm volatile("stmatrix.sync.aligned.m8n8.x4.shared.b16 [%0], {%1,%2,%3,%4};"
                 :: "r"(a), "r"(r0), "r"(r1), "r"(r2), "r"(r3) : "memory");
}
__device__ __forceinline__ void mma_bf16(float* d, const uint32_t* a,
                                         uint32_t b0, uint32_t b1) {
    asm volatile(
        "mma.sync.aligned.m16n8k16.row.col.f32.bf16.bf16.f32 "
        "{%0,%1,%2,%3}, {%4,%5,%6,%7}, {%8,%9}, {%0,%1,%2,%3};"
        : "+f"(d[0]), "+f"(d[1]), "+f"(d[2]), "+f"(d[3])
        : "r"(a[0]), "r"(a[1]), "r"(a[2]), "r"(a[3]), "r"(b0), "r"(b1));
}
__device__ __forceinline__ void cp16(void* sdst, const void* gsrc) {
    uint32_t a = (uint32_t)__cvta_generic_to_shared(sdst);
    asm volatile("cp.async.cg.shared.global [%0], [%1], 16;"
                 :: "r"(a), "l"(gsrc) : "memory");
}
#define CP_COMMIT() asm volatile("cp.async.commit_group;" ::: "memory")
#define CP_WAIT0()  asm volatile("cp.async.wait_group 0;" ::: "memory")

__device__ __forceinline__ uint32_t pack_hi(float a, float b) {
    __nv_bfloat162 t = __halves2bfloat162(__float2bfloat16(a), __float2bfloat16(b));
    return *(uint32_t*)&t;
}
__device__ __forceinline__ uint32_t pack_lo(float a, float b) {
    float ra = a - __bfloat162float(__float2bfloat16(a));
    float rb = b - __bfloat162float(__float2bfloat16(b));
    __nv_bfloat162 t = __halves2bfloat162(__float2bfloat16(ra), __float2bfloat16(rb));
    return *(uint32_t*)&t;
}
__device__ __forceinline__ void split_store4(float4 v, __nv_bfloat16* ph,
                                             __nv_bfloat16* pl) {
    *(uint2*)ph = make_uint2(pack_hi(v.x, v.y), pack_hi(v.z, v.w));
    *(uint2*)pl = make_uint2(pack_lo(v.x, v.y), pack_lo(v.z, v.w));
}
#define BARQ(id) asm volatile("bar.sync %0, 128;" :: "r"(id) : "memory")

// ---------------- GEMM pass: A from smem ldsm, B frags from gmem -----------
// quarter tile 32(M) x 128(N); warp covers 32 x 32 (cols cc*32..cc*32+31)
__device__ __forceinline__ void gemm_pass_frag(
    const __nv_bfloat16* As_h, const __nv_bfloat16* As_l,
    const uint4* __restrict__ Fh, const uint4* __restrict__ Fl,
    int cc, int lrow, int lkoff, int lane, float (&acc)[2][4][4]) {
#pragma unroll
    for (int mi = 0; mi < 2; ++mi)
#pragma unroll
        for (int ni = 0; ni < 4; ++ni)
#pragma unroll
            for (int q = 0; q < 4; ++q) acc[mi][ni][q] = 0.f;
#pragma unroll
    for (int ks = 0; ks < 8; ++ks) {
        const int k0 = ks * 16 + lkoff;
        uint32_t ah[2][4], al[2][4];
#pragma unroll
        for (int mi = 0; mi < 2; ++mi) {
            const int base = (mi * 16 + lrow) * SA + k0;
            ldsm4(ah[mi], As_h + base);
            ldsm4(al[mi], As_l + base);
        }
#pragma unroll
        for (int nj = 0; nj < 2; ++nj) {
            const uint4 bh = Fh[((cc * 2 + nj) * 8 + ks) * 32 + lane];
            const uint4 bl = Fl[((cc * 2 + nj) * 8 + ks) * 32 + lane];
#pragma unroll
            for (int mi = 0; mi < 2; ++mi) {
                const int n0 = nj * 2;
                mma_bf16(acc[mi][n0], ah[mi], bh.x, bh.z);
                mma_bf16(acc[mi][n0], ah[mi], bl.x, bl.z);
                mma_bf16(acc[mi][n0], al[mi], bh.x, bh.z);
                mma_bf16(acc[mi][n0 + 1], ah[mi], bh.y, bh.w);
                mma_bf16(acc[mi][n0 + 1], ah[mi], bl.y, bl.w);
                mma_bf16(acc[mi][n0 + 1], al[mi], bh.y, bh.w);
            }
        }
    }
}

// bias+relu then stmatrix both splits back into As (quarter: rows 0..31)
__device__ __forceinline__ void epi_to_smem(
    const float (&acc)[2][4][4], const float (&br)[4][2],
    __nv_bfloat16* As_h, __nv_bfloat16* As_l, int colBase, int lane) {
    const int srow = (lane & 7) + ((lane >> 3) & 1) * 8;
    const int scol = (lane >> 4) * 8;
#pragma unroll
    for (int mi = 0; mi < 2; ++mi) {
#pragma unroll
        for (int ng = 0; ng < 2; ++ng) {
            float v[2][4];
#pragma unroll
            for (int q = 0; q < 2; ++q) {
                const int ni = ng * 2 + q;
                v[q][0] = fmaxf(acc[mi][ni][0] + br[ni][0], 0.f);
                v[q][1] = fmaxf(acc[mi][ni][1] + br[ni][1], 0.f);
                v[q][2] = fmaxf(acc[mi][ni][2] + br[ni][0], 0.f);
                v[q][3] = fmaxf(acc[mi][ni][3] + br[ni][1], 0.f);
            }
            const int off = (mi * 16 + srow) * SA + colBase + ng * 16 + scol;
            stsm4(As_h + off, pack_hi(v[0][0], v[0][1]), pack_hi(v[0][2], v[0][3]),
                  pack_hi(v[1][0], v[1][1]), pack_hi(v[1][2], v[1][3]));
            stsm4(As_l + off, pack_lo(v[0][0], v[0][1]), pack_lo(v[0][2], v[0][3]),
                  pack_lo(v[1][0], v[1][1]), pack_lo(v[1][2], v[1][3]));
        }
    }
}

// gmem write: acc + bias (+relu) -> C [M,HD]
template <bool RELU>
__device__ __forceinline__ void write_out128(
    const float (&acc)[2][4][4], const float (&br)[4][2],
    float* __restrict__ C, int m0, int colBase, int cq, int rq, int M) {
#pragma unroll
    for (int mi = 0; mi < 2; ++mi)
#pragma unroll
        for (int ni = 0; ni < 4; ++ni) {
            const int col = colBase + ni * 8 + cq;
            const int r0 = m0 + mi * 16 + rq, r1 = r0 + 8;
            float v00 = acc[mi][ni][0] + br[ni][0];
            float v01 = acc[mi][ni][1] + br[ni][1];
            float v10 = acc[mi][ni][2] + br[ni][0];
            float v11 = acc[mi][ni][3] + br[ni][1];
            if (RELU) {
                v00 = fmaxf(v00, 0.f); v01 = fmaxf(v01, 0.f);
                v10 = fmaxf(v10, 0.f); v11 = fmaxf(v11, 0.f);
            }
            if (r0 < M) *(float2*)(C + (size_t)r0 * HD + col) = make_float2(v00, v01);
            if (r1 < M) *(float2*)(C + (size_t)r1 * HD + col) = make_float2(v10, v11);
        }
}

// smem: per quarter: As_h(8704) As_l(8704) stage(16384) = 33792; x4 = 135168
#define QSZ    33792
#define SMEM_F 135168

// issue cp.async for one 32-row tile into this quarter's stage buffer
__device__ __forceinline__ void issue_cp_tile(const float* __restrict__ A,
                                              float* stagef, int tile, int M,
                                              int tiq) {
#pragma unroll
    for (int qq = 0; qq < 8; ++qq) {
        const int i = tiq + 128 * qq;         // 0..1023
        const int r = i >> 5, c = i & 31;
        const int grow = tile * 32 + r;
        float* dst = stagef + r * 128 + c * 4;
        if (grow < M)
            cp16(dst, A + (size_t)grow * 128 + c * 4);
        else
            *(float4*)dst = make_float4(0.f, 0.f, 0.f, 0.f);
    }
}

// ---------------- fused GIN layer: 4 independent quarter-pipelines ----------
template <bool HEAD>
__global__ __launch_bounds__(512, 1) void fused_gin(
    const float* __restrict__ A,
    const uint4* __restrict__ W1Fh, const uint4* __restrict__ W1Fl,
    const uint4* __restrict__ W2Fh, const uint4* __restrict__ W2Fl,
    const uint4* __restrict__ WoFh, const uint4* __restrict__ WoFl,
    const float* __restrict__ b1, const float* __restrict__ b2,
    const float* __restrict__ b3,
    float* __restrict__ C, int M, int nTiles) {
    extern __shared__ char smem[];
    const int tid = threadIdx.x, lane = tid & 31, wid = tid >> 5;
    const int q = wid >> 2, cc = wid & 3, tiq = tid & 127;

    __nv_bfloat16* As_h = (__nv_bfloat16*)(smem + q * QSZ);
    __nv_bfloat16* As_l = (__nv_bfloat16*)(smem + q * QSZ + 8704);
    float* stagef = (float*)(smem + q * QSZ + 17408);

    const int barid = 1 + q;
    const int colBase = cc * 32;
    const int lrow = lane & 15, lkoff = (lane >> 4) * 8;
    const int cq = (lane & 3) * 2, rq = lane >> 2;

    float b1r[4][2], b2r[4][2], b3r[2][2];
#pragma unroll
    for (int ni = 0; ni < 4; ++ni) {
        const int col = colBase + ni * 8 + cq;
        b1r[ni][0] = b1[col]; b1r[ni][1] = b1[col + 1];
        b2r[ni][0] = b2[col]; b2r[ni][1] = b2[col + 1];
    }
    if (HEAD) {
#pragma unroll
        for (int ni = 0; ni < 2; ++ni) {
            const int col = cc * 16 + ni * 8 + cq;
            b3r[ni][0] = b3[col]; b3r[ni][1] = b3[col + 1];
        }
    }

    int tile = blockIdx.x * 4 + q;
    if (tile < nTiles) issue_cp_tile(A, stagef, tile, M, tiq);
    CP_COMMIT();

    for (; tile < nTiles; tile += gridDim.x * 4) {
        const int m0 = tile * 32;
        CP_WAIT0();
        BARQ(barid);   // stage data landed; prev iter's As readers done

        // build A tile (32 rows; 4 warps x 8 rows)
#pragma unroll
        for (int rr = 0; rr < 8; ++rr) {
            const int r = cc * 8 + rr;
            float4 v = ((const float4*)stagef)[r * 32 + lane];
            split_store4(v, As_h + r * SA + lane * 4, As_l + r * SA + lane * 4);
        }
        BARQ(barid);

        const int nxt = tile + gridDim.x * 4;
        if (nxt < nTiles) issue_cp_tile(A, stagef, nxt, M, tiq);
        CP_COMMIT();

        float acc[2][4][4];
        gemm_pass_frag(As_h, As_l, W1Fh, W1Fl, cc, lrow, lkoff, lane, acc);
        BARQ(barid);
        epi_to_smem(acc, b1r, As_h, As_l, colBase, lane);
        BARQ(barid);
        gemm_pass_frag(As_h, As_l, W2Fh, W2Fl, cc, lrow, lkoff, lane, acc);

        if (!HEAD) {
            write_out128<true>(acc, b2r, C, m0, colBase, cq, rq, M);
        } else {
            BARQ(barid);
            epi_to_smem(acc, b2r, As_h, As_l, colBase, lane);
            BARQ(barid);
            float acc3[2][2][4];
#pragma unroll
            for (int mi = 0; mi < 2; ++mi)
#pragma unroll
                for (int ni = 0; ni < 2; ++ni)
#pragma unroll
                    for (int p = 0; p < 4; ++p) acc3[mi][ni][p] = 0.f;
#pragma unroll
            for (int ks = 0; ks < 8; ++ks) {
                const int k0 = ks * 16 + lkoff;
                uint32_t ah[2][4], al[2][4];
#pragma unroll
                for (int mi = 0; mi < 2; ++mi) {
                    const int base = (mi * 16 + lrow) * SA + k0;
                    ldsm4(ah[mi], As_h + base);
                    ldsm4(al[mi], As_l + base);
                }
                const uint4 bh = WoFh[(cc * 8 + ks) * 32 + lane];
                const uint4 bl = WoFl[(cc * 8 + ks) * 32 + lane];
#pragma unroll
                for (int mi = 0; mi < 2; ++mi) {
                    mma_bf16(acc3[mi][0], ah[mi], bh.x, bh.z);
                    mma_bf16(acc3[mi][0], ah[mi], bl.x, bl.z);
                    mma_bf16(acc3[mi][0], al[mi], bh.x, bh.z);
                    mma_bf16(acc3[mi][1], ah[mi], bh.y, bh.w);
                    mma_bf16(acc3[mi][1], ah[mi], bl.y, bl.w);
                    mma_bf16(acc3[mi][1], al[mi], bh.y, bh.w);
                }
            }
#pragma unroll
            for (int mi = 0; mi < 2; ++mi)
#pragma unroll
                for (int ni = 0; ni < 2; ++ni) {
                    const int col = cc * 16 + ni * 8 + cq;
                    const int r0 = m0 + mi * 16 + rq, r1 = r0 + 8;
                    if (r0 < M)
                        *(float2*)(C + (size_t)r0 * OD + col) = make_float2(
                            acc3[mi][ni][0] + b3r[ni][0], acc3[mi][ni][1] + b3r[ni][1]);
                    if (r1 < M)
                        *(float2*)(C + (size_t)r1 * OD + col) = make_float2(
                            acc3[mi][ni][2] + b3r[ni][0], acc3[mi][ni][3] + b3r[ni][1]);
                }
        }
    }
}

// ---------------- fused node layer 1 + MLP (4 passes, all frags) -----------
__global__ __launch_bounds__(512, 1) void fused_gin_mlp(
    const float* __restrict__ A,
    const uint4* __restrict__ WaFh, const uint4* __restrict__ WaFl,
    const uint4* __restrict__ WbFh, const uint4* __restrict__ WbFl,
    const uint4* __restrict__ WcFh, const uint4* __restrict__ WcFl,
    const uint4* __restrict__ WdFh, const uint4* __restrict__ WdFl,
    const float* __restrict__ b1, const float* __restrict__ b2,
    const float* __restrict__ b3, const float* __restrict__ b4,
    float* __restrict__ C, int M, int nTiles) {
    extern __shared__ char smem[];
    const int tid = threadIdx.x, lane = tid & 31, wid = tid >> 5;
    const int q = wid >> 2, cc = wid & 3, tiq = tid & 127;

    __nv_bfloat16* As_h = (__nv_bfloat16*)(smem + q * QSZ);
    __nv_bfloat16* As_l = (__nv_bfloat16*)(smem + q * QSZ + 8704);
    float* stagef = (float*)(smem + q * QSZ + 17408);

    const int barid = 1 + q;
    const int colBase = cc * 32;
    const int lrow = lane & 15, lkoff = (lane >> 4) * 8;
    const int cq = (lane & 3) * 2, rq = lane >> 2;

    float b1r[4][2], b2r[4][2], b3r[4][2], b4r[4][2];
#pragma unroll
    for (int ni = 0; ni < 4; ++ni) {
        const int col = colBase + ni * 8 + cq;
        b1r[ni][0] = b1[col]; b1r[ni][1] = b1[col + 1];
        b2r[ni][0] = b2[col]; b2r[ni][1] = b2[col + 1];
        b3r[ni][0] = b3[col]; b3r[ni][1] = b3[col + 1];
        b4r[ni][0] = b4[col]; b4r[ni][1] = b4[col + 1];
    }

    int tile = blockIdx.x * 4 + q;
    if (tile < nTiles) issue_cp_tile(A, stagef, tile, M, tiq);
    CP_COMMIT();

    for (; tile < nTiles; tile += gridDim.x * 4) {
        const int m0 = tile * 32;
        CP_WAIT0();
        BARQ(barid);
#pragma unroll
        for (int rr = 0; rr < 8; ++rr) {
            const int r = cc * 8 + rr;
            float4 v = ((const float4*)stagef)[r * 32 + lane];
            split_store4(v, As_h + r * SA + lane * 4, As_l + r * SA + lane * 4);
        }
        BARQ(barid);
        const int nxt = tile + gridDim.x * 4;
        if (nxt < nTiles) issue_cp_tile(A, stagef, nxt, M, tiq);
        CP_COMMIT();

        float acc[2][4][4];
        gemm_pass_frag(As_h, As_l, WaFh, WaFl, cc, lrow, lkoff, lane, acc);
        BARQ(barid);
        epi_to_smem(acc, b1r, As_h, As_l, colBase, lane);
        BARQ(barid);
        gemm_pass_frag(As_h, As_l, WbFh, WbFl, cc, lrow, lkoff, lane, acc);
        BARQ(barid);
        epi_to_smem(acc, b2r, As_h, As_l, colBase, lane);   // layer out (relu)
        BARQ(barid);
        gemm_pass_frag(As_h, As_l, WcFh, WcFl, cc, lrow, lkoff, lane, acc);
        BARQ(barid);
        epi_to_smem(acc, b3r, As_h, As_l, colBase, lane);   // mlp hidden (relu)
        BARQ(barid);
        gemm_pass_frag(As_h, As_l, WdFh, WdFl, cc, lrow, lkoff, lane, acc);
        write_out128<false>(acc, b4r, C, m0, colBase, cq, rq, M);
    }
}

// ---------------- weight prep ------------------------------------------------
struct PrepArgs {
    const float *W1[5], *b1[5], *g[5], *bb[5], *m[5], *v[5], *W2[5], *Wo;
    __nv_bfloat16 *W1h[5], *W1l[5], *W2h[5], *W2l[5];
    uint32_t *Wofh, *Wofl;
    float* bf[5];
};

__global__ void prep_weights(PrepArgs a) {
    const int blk = blockIdx.x, tid = threadIdx.x;
    if (blk < 320) {
        const int j = blk >> 6;
        const int idx = ((blk & 63) << 8) + tid;
        const int k = idx >> 7, n = idx & 127;
        float s = a.g[j][n] * rsqrtf(a.v[j][n] + 1e-5f);
        float val = a.W1[j][idx] * s;
        __nv_bfloat16 h = __float2bfloat16(val);
        a.W1h[j][n * 128 + k] = h;
        a.W1l[j][n * 128 + k] = __float2bfloat16(val - __bfloat162float(h));
        if (idx < 128)
            a.bf[j][idx] = a.b1[j][idx] * s + a.bb[j][idx] - a.m[j][idx] * s;
    } else if (blk < 640) {
        const int j = (blk - 320) >> 6;
        const int idx = (((blk - 320) & 63) << 8) + tid;
        const int k = idx >> 7, n = idx & 127;
        float val = a.W2[j][idx];
        __nv_bfloat16 h = __float2bfloat16(val);
        a.W2h[j][n * 128 + k] = h;
        a.W2l[j][n * 128 + k] = __float2bfloat16(val - __bfloat162float(h));
    } else {
        const int idx = ((blk - 640) << 8) + tid;  // 0..4095 (Wo frags)
        const int j = idx & 3, L = (idx >> 2) & 31;
        const int ks = (idx >> 7) & 7, cc = idx >> 10;
        const int n = cc * 16 + (j & 1) * 8 + (L >> 2);
        const int k = ks * 16 + ((j >> 1)) * 8 + (L & 3) * 2;
        float v0 = a.Wo[k * OD + n];
        float v1 = a.Wo[(k + 1) * OD + n];
        a.Wofh[((cc * 8 + ks) * 32 + L) * 4 + j] = pack_hi(v0, v1);
        a.Wofl[((cc * 8 + ks) * 32 + L) * 4 + j] = pack_lo(v0, v1);
    }
}

// convert n-major bf16 images into ldmatrix-order frag arrays (N=128); 20 jobs
struct FragArgs {
    const __nv_bfloat16* src[20];
    uint32_t* dst[20];
};
__global__ void frag_all(FragArgs a) {
    const int i = blockIdx.x * 256 + threadIdx.x;   // 0..163839
    const int m = i >> 13, e = i & 8191;
    const int j = e & 3, L = (e >> 2) & 31;
    const int ks = (e >> 7) & 7, g = e >> 10;
    const int n = g * 16 + (j & 1) * 8 + (L >> 2);
    const int k = ks * 16 + (j >> 1) * 8 + (L & 3) * 2;
    a.dst[m][e] = *(const uint32_t*)(a.src[m] + n * 128 + k);
}

// ---------------- CSR build ----------------------------------------------------
__global__ void count_deg(const int* __restrict__ dst, int E, int* __restrict__ deg) {
    int e = blockIdx.x * 256 + threadIdx.x;
    if (e < E) atomicAdd(&deg[dst[e]], 1);
}

__global__ void scan1(const int* __restrict__ deg, int* __restrict__ ex,
                      int* __restrict__ bsum, int n) {
    __shared__ int wsum[32];
    const int t = threadIdx.x;
    const int base = blockIdx.x * 4096 + t * 4;
    int v[4], s = 0;
#pragma unroll
    for (int i = 0; i < 4; ++i) {
        int idx = base + i;
        v[i] = idx < n ? deg[idx] : 0;
        s += v[i];
    }
    const int lane = t & 31, w = t >> 5;
    int ps = s;
#pragma unroll
    for (int o = 1; o < 32; o <<= 1) {
        int y = __shfl_up_sync(~0u, ps, o);
        if (lane >= o) ps += y;
    }
    if (lane == 31) wsum[w] = ps;
    __syncthreads();
    if (w == 0) {
        int x = wsum[lane];
#pragma unroll
        for (int o = 1; o < 32; o <<= 1) {
            int y = __shfl_up_sync(~0u, x, o);
            if (lane >= o) x += y;
        }
        wsum[lane] = x;
    }
    __syncthreads();
    const int warpoff = w ? wsum[w - 1] : 0;
    int run = warpoff + ps - s;
#pragma unroll
    for (int i = 0; i < 4; ++i) {
        int idx = base + i;
        if (idx < n) ex[idx] = run;
        run += v[i];
    }
    if (t == 0) bsum[blockIdx.x] = wsum[31];
}

__global__ void scan2(int* __restrict__ bsum, int nb) {
    __shared__ int sm_[1024];
    const int t = threadIdx.x;
    int v = (t < nb) ? bsum[t] : 0;
    sm_[t] = v;
    __syncthreads();
    for (int o = 1; o < 1024; o <<= 1) {
        int y = (t >= o) ? sm_[t - o] : 0;
        __syncthreads();
        sm_[t] += y;
        __syncthreads();
    }
    if (t < nb) bsum[t] = sm_[t] - v;
}

__global__ void scan3(const int* __restrict__ ex, const int* __restrict__ boff,
                      int* __restrict__ rp, int* __restrict__ cur, int n, int E) {
    int i = blockIdx.x * 1024 + threadIdx.x;
    if (i < n) {
        int vv = ex[i] + boff[i >> 12];
        rp[i] = vv;
        cur[i] = vv;
    } else if (i == n) {
        rp[n] = E;
    }
}

__global__ void fill_csr(const int* __restrict__ src, const int* __restrict__ dst,
                         int E, int* __restrict__ cur, int* __restrict__ adj) {
    int e = blockIdx.x * 256 + threadIdx.x;
    if (e < E) {
        int p = atomicAdd(&cur[dst[e]], 1);
        adj[p] = src[e];
    }
}

// ---------------- gather aggregation: agg[r] = x[r] + sum x[nbr] ---------------
__global__ void gather_agg(const float* __restrict__ x,
                           const int* __restrict__ rp,
                           const int* __restrict__ adj,
                           float* __restrict__ agg, int n) {
    unsigned t = blockIdx.x * 256u + threadIdx.x;
    unsigned r = t >> 5, lane = t & 31u;
    if (r >= (unsigned)n) return;
    const int s = rp[r], e = rp[r + 1];
    float4 acc = ((const float4*)(x + (size_t)r * HD))[lane];
    const int cnt = e - s;
    int nb_l = ((int)lane < cnt) ? adj[s + lane] : 0;
    const int lim = cnt < 32 ? cnt : 32;
    for (int j = 0; j < lim; ++j) {
        const int nb = __shfl_sync(~0u, nb_l, j);
        float4 u = ((const float4*)(x + (size_t)nb * HD))[lane];
        acc.x += u.x; acc.y += u.y; acc.z += u.z; acc.w += u.w;
    }
    for (int j = s + 32; j < e; ++j) {
        const int nb = adj[j];
        float4 u = ((const float4*)(x + (size_t)nb * HD))[lane];
        acc.x += u.x; acc.y += u.y; acc.z += u.z; acc.w += u.w;
    }
    ((float4*)(agg + (size_t)r * HD))[lane] = acc;
}

// ---- fused pair lift + aggregation (edge layer 0; y L2-resident) ------------
__global__ void pair_agg(const int* __restrict__ ep,
                         const float* __restrict__ y,
                         const int* __restrict__ rp,
                         const int* __restrict__ adj,
                         float* __restrict__ agg, int n) {
    unsigned t = blockIdx.x * 256u + threadIdx.x;
    unsigned r = t >> 5, lane = t & 31u;
    if (r >= (unsigned)n) return;
    const int s = rp[r], e = rp[r + 1];
    const int cnt = e - s;
    const int i0 = ep[2 * r], i1 = ep[2 * r + 1];
    float4 acc = ((const float4*)(y + (size_t)i0 * HD))[lane];
    float4 b = ((const float4*)(y + (size_t)i1 * HD))[lane];
    acc.x += b.x; acc.y += b.y; acc.z += b.z; acc.w += b.w;
    int p0_l = 0, p1_l = 0;
    if ((int)lane < cnt) {
        const int nb = adj[s + lane];
        p0_l = ep[2 * nb];
        p1_l = ep[2 * nb + 1];
    }
    const int lim = cnt < 32 ? cnt : 32;
    for (int j = 0; j < lim; ++j) {
        const int q0 = __shfl_sync(~0u, p0_l, j);
        const int q1 = __shfl_sync(~0u, p1_l, j);
        float4 u = ((const float4*)(y + (size_t)q0 * HD))[lane];
        float4 w = ((const float4*)(y + (size_t)q1 * HD))[lane];
        acc.x += u.x + w.x; acc.y += u.y + w.y;
        acc.z += u.z + w.z; acc.w += u.w + w.w;
    }
    for (int j = s + 32; j < e; ++j) {
        const int nb = adj[j];
        const int q0 = ep[2 * nb], q1 = ep[2 * nb + 1];
        float4 u = ((const float4*)(y + (size_t)q0 * HD))[lane];
        float4 w = ((const float4*)(y + (size_t)q1 * HD))[lane];
        acc.x += u.x + w.x; acc.y += u.y + w.y;
        acc.z += u.z + w.z; acc.w += u.w + w.w;
    }
    ((float4*)(agg + (size_t)r * HD))[lane] = acc;
}

// ----------------------------------------------------------------------------------
extern "C" void kernel_launch(void* const* d_in, const int* in_sizes, int n_in,
                              void* d_out, int out_size) {
    const int*   edge_index = (const int*)d_in[0];
    const float* x_orig     = (const float*)d_in[1];
    const int*   ei_orig    = (const int*)d_in[2];
    const int*   edge_pairs = (const int*)d_in[3];
    const float* init_W1 = (const float*)d_in[4];
    const float* init_b1 = (const float*)d_in[5];
    const float* init_g  = (const float*)d_in[6];
    const float* init_bb = (const float*)d_in[7];
    const float* init_m  = (const float*)d_in[8];
    const float* init_v  = (const float*)d_in[9];
    const float* init_W2 = (const float*)d_in[10];
    const float* init_b2 = (const float*)d_in[11];
    const float* gin_W1  = (const float*)d_in[12];
    const float* gin_b1  = (const float*)d_in[13];
    const float* gin_g   = (const float*)d_in[14];
    const float* gin_bb  = (const float*)d_in[15];
    const float* gin_m   = (const float*)d_in[16];
    const float* gin_v   = (const float*)d_in[17];
    const float* gin_W2  = (const float*)d_in[18];
    const float* gin_b2  = (const float*)d_in[19];
    const float* mlp_W1  = (const float*)d_in[20];
    const float* mlp_b1  = (const float*)d_in[21];
    const float* mlp_g   = (const float*)d_in[22];
    const float* mlp_bb  = (const float*)d_in[23];
    const float* mlp_m   = (const float*)d_in[24];
    const float* mlp_v   = (const float*)d_in[25];
    const float* mlp_W2  = (const float*)d_in[26];
    const float* mlp_b2  = (const float*)d_in[27];
    const float* out_W   = (const float*)d_in[28];
    const float* out_b   = (const float*)d_in[29];
    float* out = (float*)d_out;

    float *nodeA, *nodeB, *nodeC, *nodeD, *edgeA, *edgeB, *edgeC, *bfb;
    __nv_bfloat16 *W1h, *W1l, *W2h, *W2l;
    uint32_t *W1Fh, *W1Fl, *W2Fh, *W2Fl, *Wofh, *Wofl;
    int *deg, *ex, *bsum, *rpN, *adjN, *curN, *rpE, *adjE, *curE;
    cudaGetSymbolAddress((void**)&nodeA, g_nodeA);
    cudaGetSymbolAddress((void**)&nodeB, g_nodeB);
    cudaGetSymbolAddress((void**)&nodeC, g_nodeC);
    cudaGetSymbolAddress((void**)&nodeD, g_nodeD);
    cudaGetSymbolAddress((void**)&edgeA, g_edgeA);
    cudaGetSymbolAddress((void**)&edgeB, g_edgeB);
    cudaGetSymbolAddress((void**)&edgeC, g_edgeC);
    cudaGetSymbolAddress((void**)&bfb, g_bfb);
    cudaGetSymbolAddress((void**)&W1h, g_W1h);
    cudaGetSymbolAddress((void**)&W1l, g_W1l);
    cudaGetSymbolAddress((void**)&W2h, g_W2h);
    cudaGetSymbolAddress((void**)&W2l, g_W2l);
    cudaGetSymbolAddress((void**)&W1Fh, g_W1Fh);
    cudaGetSymbolAddress((void**)&W1Fl, g_W1Fl);
    cudaGetSymbolAddress((void**)&W2Fh, g_W2Fh);
    cudaGetSymbolAddress((void**)&W2Fl, g_W2Fl);
    cudaGetSymbolAddress((void**)&Wofh, g_Wofh);
    cudaGetSymbolAddress((void**)&Wofl, g_Wofl);
    cudaGetSymbolAddress((void**)&deg, g_deg);
    cudaGetSymbolAddress((void**)&ex, g_ex);
    cudaGetSymbolAddress((void**)&bsum, g_bsum);
    cudaGetSymbolAddress((void**)&rpN, g_rpN);
    cudaGetSymbolAddress((void**)&adjN, g_adjN);
    cudaGetSymbolAddress((void**)&curN, g_curN);
    cudaGetSymbolAddress((void**)&rpE, g_rpE);
    cudaGetSymbolAddress((void**)&adjE, g_adjE);
    cudaGetSymbolAddress((void**)&curE, g_curE);

    // ---- weight prep --------------------------------------------------------
    PrepArgs pa;
    const float* W1s[5]  = {init_W1, init_W1 + HD * HD, mlp_W1, gin_W1, gin_W1 + HD * HD};
    const float* b1s[5]  = {init_b1, init_b1 + HD, mlp_b1, gin_b1, gin_b1 + HD};
    const float* gs[5]   = {init_g, init_g + HD, mlp_g, gin_g, gin_g + HD};
    const float* bbs[5]  = {init_bb, init_bb + HD, mlp_bb, gin_bb, gin_bb + HD};
    const float* ms[5]   = {init_m, init_m + HD, mlp_m, gin_m, gin_m + HD};
    const float* vs[5]   = {init_v, init_v + HD, mlp_v, gin_v, gin_v + HD};
    const float* W2s[5]  = {init_W2, init_W2 + HD * HD, mlp_W2, gin_W2, gin_W2 + HD * HD};
    for (int j = 0; j < 5; ++j) {
        pa.W1[j] = W1s[j]; pa.b1[j] = b1s[j]; pa.g[j] = gs[j]; pa.bb[j] = bbs[j];
        pa.m[j] = ms[j]; pa.v[j] = vs[j]; pa.W2[j] = W2s[j];
        pa.W1h[j] = W1h + (size_t)j * HD * HD; pa.W1l[j] = W1l + (size_t)j * HD * HD;
        pa.W2h[j] = W2h + (size_t)j * HD * HD; pa.W2l[j] = W2l + (size_t)j * HD * HD;
        pa.bf[j] = bfb + j * HD;
    }
    pa.Wo = out_W; pa.Wofh = Wofh; pa.Wofl = Wofl;
    prep_weights<<<656, 256>>>(pa);

    FragArgs fa;
    for (int j = 0; j < 5; ++j) {
        fa.src[j]      = W1h + (size_t)j * HD * HD; fa.dst[j]      = W1Fh + (size_t)j * 8192;
        fa.src[5 + j]  = W1l + (size_t)j * HD * HD; fa.dst[5 + j]  = W1Fl + (size_t)j * 8192;
        fa.src[10 + j] = W2h + (size_t)j * HD * HD; fa.dst[10 + j] = W2Fh + (size_t)j * 8192;
        fa.src[15 + j] = W2l + (size_t)j * HD * HD; fa.dst[15 + j] = W2Fl + (size_t)j * 8192;
    }
    frag_all<<<640, 256>>>(fa);

    // ---- CSR build: node graph (dst = ei_orig[1]) ----------------------------
    cudaMemsetAsync(deg, 0, NN * sizeof(int));
    count_deg<<<(EO + 255) / 256, 256>>>(ei_orig + EO, EO, deg);
    scan1<<<(NN + 4095) / 4096, 1024>>>(deg, ex, bsum, NN);
    scan2<<<1, 1024>>>(bsum, (NN + 4095) / 4096);
    scan3<<<(NN + 1024) / 1024 + 1, 1024>>>(ex, bsum, rpN, curN, NN, EO);
    fill_csr<<<(EO + 255) / 256, 256>>>(ei_orig, ei_orig + EO, EO, curN, adjN);

    // ---- CSR build: line graph (dst = edge_index[1]) --------------------------
    cudaMemsetAsync(deg, 0, EO * sizeof(int));
    count_deg<<<(EL + 255) / 256, 256>>>(edge_index + EL, EL, deg);
    scan1<<<(EO + 4095) / 4096, 1024>>>(deg, ex, bsum, EO);
    scan2<<<1, 1024>>>(bsum, (EO + 4095) / 4096);
    scan3<<<(EO + 1024) / 1024 + 1, 1024>>>(ex, bsum, rpE, curE, EO, EL);
    fill_csr<<<(EL + 255) / 256, 256>>>(edge_index, edge_index + EL, EL, curE, adjE);

    // ---- main pipeline ----------------------------------------------------------
    cudaFuncSetAttribute(fused_gin<false>,
                         cudaFuncAttributeMaxDynamicSharedMemorySize, SMEM_F);
    cudaFuncSetAttribute(fused_gin<true>,
                         cudaFuncAttributeMaxDynamicSharedMemorySize, SMEM_F);
    cudaFuncSetAttribute(fused_gin_mlp,
                         cudaFuncAttributeMaxDynamicSharedMemorySize, SMEM_F);

    const int GRID = 148;
    const int tilesN = (NN + 31) / 32;   // 3125
    const int tilesE = (EO + 31) / 32;   // 18750
    const int gaN = ((unsigned)NN * 32u + 255u) / 256u;
    const int gaE = ((unsigned)EO * 32u + 255u) / 256u;

    // node layer 0: agg(x_orig) -> nodeB; GEMM -> nodeA
    gather_agg<<<gaN, 256>>>(x_orig, rpN, adjN, nodeB, NN);
    fused_gin<false><<<GRID, 512, SMEM_F>>>(
        nodeB, (const uint4*)W1Fh, (const uint4*)W1Fl,
        (const uint4*)W2Fh, (const uint4*)W2Fl, nullptr, nullptr,
        bfb, init_b2, nullptr, nodeA, NN, tilesN);

    // node layer 1 + MLP: agg(nodeA) -> nodeC; 4-pass GEMM -> nodeD
    gather_agg<<<gaN, 256>>>(nodeA, rpN, adjN, nodeC, NN);
    fused_gin_mlp<<<GRID, 512, SMEM_F>>>(
        nodeC,
        (const uint4*)(W1Fh + 8192), (const uint4*)(W1Fl + 8192),
        (const uint4*)(W2Fh + 8192), (const uint4*)(W2Fl + 8192),
        (const uint4*)(W1Fh + 2 * 8192), (const uint4*)(W1Fl + 2 * 8192),
        (const uint4*)(W2Fh + 2 * 8192), (const uint4*)(W2Fl + 2 * 8192),
        bfb + HD, init_b2 + HD, bfb + 2 * HD, mlp_b2, nodeD, NN, tilesN);

    // edge layer 0: fused pair-lift + agg (L2-resident nodeD) -> edgeB; GEMM -> edgeC
    pair_agg<<<gaE, 256>>>(edge_pairs, nodeD, rpE, adjE, edgeB, EO);
    fused_gin<false><<<GRID, 512, SMEM_F>>>(
        edgeB, (const uint4*)(W1Fh + 3 * 8192), (const uint4*)(W1Fl + 3 * 8192),
        (const uint4*)(W2Fh + 3 * 8192), (const uint4*)(W2Fl + 3 * 8192),
        nullptr, nullptr, bfb + 3 * HD, gin_b2, nullptr, edgeC, EO, tilesE);

    // edge layer 1 + head: agg(edgeC) -> edgeA; GEMM+head -> out
    gather_agg<<<gaE, 256>>>(edgeC, rpE, adjE, edgeA, EO);
    fused_gin<true><<<GRID, 512, SMEM_F>>>(
        edgeA, (const uint4*)(W1Fh + 4 * 8192), (const uint4*)(W1Fl + 4 * 8192),
        (const uint4*)(W2Fh + 4 * 8192), (const uint4*)(W2Fl + 4 * 8192),
        (const uint4*)Wofh, (const uint4*)Wofl,
        bfb + 4 * HD, gin_b2 + HD, out_b, out, EO, tilesE);
}

// round 12
// speedup vs baseline: 2.0404x; 1.1904x over previous
#include <cuda_runtime.h>
#include <cuda_fp16.h>
#include <cstdint>

#define NN 100000
#define EO 600000
#define EL 1200000
#define HD 128
#define OD 64
#define SA 136   // smem row stride (fp16) -> conflict-spread ldmatrix/stmatrix

// ---------------- scratch (device globals) ---------------------------------
static __device__ float g_nodeA[(size_t)NN * HD];
static __device__ float g_nodeB[(size_t)NN * HD];
static __device__ float g_nodeC[(size_t)NN * HD];
static __device__ float g_nodeD[(size_t)NN * HD];
static __device__ float g_edgeA[(size_t)EO * HD];
static __device__ float g_edgeB[(size_t)EO * HD];
static __device__ float g_edgeC[(size_t)EO * HD];
static __device__ __half g_W1h[5][HD * HD], g_W1l[5][HD * HD];   // n-major images
static __device__ __half g_W2h[5][HD * HD], g_W2l[5][HD * HD];
static __device__ uint32_t g_W1Fh[5][8192], g_W1Fl[5][8192];     // W1 frags (N=128)
static __device__ uint32_t g_W2Fh[5][8192], g_W2Fl[5][8192];     // W2 frags (N=128)
static __device__ uint32_t g_Wofh[4096], g_Wofl[4096];           // Wo frags (N=64)
static __device__ float g_bfb[5][HD];
// CSR scratch
static __device__ int g_deg[EO], g_ex[EO], g_bsum[1024];
static __device__ int g_rpN[NN + 1], g_adjN[EO], g_curN[NN];
static __device__ int g_rpE[EO + 1], g_adjE[EL], g_curE[EO];

// ---------------- PTX helpers ----------------------------------------------
__device__ __forceinline__ void ldsm4(uint32_t* r, const void* p) {
    uint32_t a = (uint32_t)__cvta_generic_to_shared(p);
    asm volatile("ldmatrix.sync.aligned.m8n8.x4.shared.b16 {%0,%1,%2,%3}, [%4];"
                 : "=r"(r[0]), "=r"(r[1]), "=r"(r[2]), "=r"(r[3]) : "r"(a));
}
__device__ __forceinline__ void stsm4(void* p, uint32_t r0, uint32_t r1,
                                      uint32_t r2, uint32_t r3) {
    uint32_t a = (uint32_t)__cvta_generic_to_shared(p);
    asm volatile("stmatrix.sync.aligned.m8n8.x4.shared.b16 [%0], {%1,%2,%3,%4};"
                 :: "r"(a), "r"(r0), "r"(r1), "r"(r2), "r"(r3) : "memory");
}
__device__ __forceinline__ void mma_f16(float* d, const uint32_t* a,
                                        uint32_t b0, uint32_t b1) {
    asm volatile(
        "mma.sync.aligned.m16n8k16.row.col.f32.f16.f16.f32 "
        "{%0,%1,%2,%3}, {%4,%5,%6,%7}, {%8,%9}, {%0,%1,%2,%3};"
        : "+f"(d[0]), "+f"(d[1]), "+f"(d[2]), "+f"(d[3])
        : "r"(a[0]), "r"(a[1]), "r"(a[2]), "r"(a[3]), "r"(b0), "r"(b1));
}
__device__ __forceinline__ void cp16(void* sdst, const void* gsrc) {
    uint32_t a = (uint32_t)__cvta_generic_to_shared(sdst);
    asm volatile("cp.async.cg.shared.global [%0], [%1], 16;"
                 :: "r"(a), "l"(gsrc) : "memory");
}
#define CP_COMMIT() asm volatile("cp.async.commit_group;" ::: "memory")
#define CP_WAIT0()  asm volatile("cp.async.wait_group 0;" ::: "memory")

__device__ __forceinline__ uint32_t packh(float a, float b) {
    __half2 t = __floats2half2_rn(a, b);
    return *(uint32_t*)&t;
}
#define BARQ(id) asm volatile("bar.sync %0, 128;" :: "r"(id) : "memory")

// ---------------- GEMM pass: A fp16 from smem, W fp16 hi+lo frags ----------
// quarter tile 32(M) x 128(N); warp covers 32 x 32 (cols cc*32..cc*32+31)
__device__ __forceinline__ void gemm_pass_frag(
    const __half* As,
    const uint4* __restrict__ Fh, const uint4* __restrict__ Fl,
    int cc, int lrow, int lkoff, int lane, float (&acc)[2][4][4]) {
#pragma unroll
    for (int mi = 0; mi < 2; ++mi)
#pragma unroll
        for (int ni = 0; ni < 4; ++ni)
#pragma unroll
            for (int q = 0; q < 4; ++q) acc[mi][ni][q] = 0.f;
#pragma unroll
    for (int ks = 0; ks < 8; ++ks) {
        const int k0 = ks * 16 + lkoff;
        uint32_t ah[2][4];
#pragma unroll
        for (int mi = 0; mi < 2; ++mi)
            ldsm4(ah[mi], As + (mi * 16 + lrow) * SA + k0);
#pragma unroll
        for (int nj = 0; nj < 2; ++nj) {
            const uint4 bh = Fh[((cc * 2 + nj) * 8 + ks) * 32 + lane];
            const uint4 bl = Fl[((cc * 2 + nj) * 8 + ks) * 32 + lane];
#pragma unroll
            for (int mi = 0; mi < 2; ++mi) {
                const int n0 = nj * 2;
                mma_f16(acc[mi][n0], ah[mi], bh.x, bh.z);
                mma_f16(acc[mi][n0], ah[mi], bl.x, bl.z);
                mma_f16(acc[mi][n0 + 1], ah[mi], bh.y, bh.w);
                mma_f16(acc[mi][n0 + 1], ah[mi], bl.y, bl.w);
            }
        }
    }
}

// bias+relu then stmatrix back into As (quarter rows 0..31)
__device__ __forceinline__ void epi_to_smem(
    const float (&acc)[2][4][4], const float (&br)[4][2],
    __half* As, int colBase, int lane) {
    const int srow = (lane & 7) + ((lane >> 3) & 1) * 8;
    const int scol = (lane >> 4) * 8;
#pragma unroll
    for (int mi = 0; mi < 2; ++mi) {
#pragma unroll
        for (int ng = 0; ng < 2; ++ng) {
            float v[2][4];
#pragma unroll
            for (int q = 0; q < 2; ++q) {
                const int ni = ng * 2 + q;
                v[q][0] = fmaxf(acc[mi][ni][0] + br[ni][0], 0.f);
                v[q][1] = fmaxf(acc[mi][ni][1] + br[ni][1], 0.f);
                v[q][2] = fmaxf(acc[mi][ni][2] + br[ni][0], 0.f);
                v[q][3] = fmaxf(acc[mi][ni][3] + br[ni][1], 0.f);
            }
            const int off = (mi * 16 + srow) * SA + colBase + ng * 16 + scol;
            stsm4(As + off, packh(v[0][0], v[0][1]), packh(v[0][2], v[0][3]),
                  packh(v[1][0], v[1][1]), packh(v[1][2], v[1][3]));
        }
    }
}

// gmem write: acc + bias (+relu) -> C [M,HD]
template <bool RELU>
__device__ __forceinline__ void write_out128(
    const float (&acc)[2][4][4], const float (&br)[4][2],
    float* __restrict__ C, int m0, int colBase, int cq, int rq, int M) {
#pragma unroll
    for (int mi = 0; mi < 2; ++mi)
#pragma unroll
        for (int ni = 0; ni < 4; ++ni) {
            const int col = colBase + ni * 8 + cq;
            const int r0 = m0 + mi * 16 + rq, r1 = r0 + 8;
            float v00 = acc[mi][ni][0] + br[ni][0];
            float v01 = acc[mi][ni][1] + br[ni][1];
            float v10 = acc[mi][ni][2] + br[ni][0];
            float v11 = acc[mi][ni][3] + br[ni][1];
            if (RELU) {
                v00 = fmaxf(v00, 0.f); v01 = fmaxf(v01, 0.f);
                v10 = fmaxf(v10, 0.f); v11 = fmaxf(v11, 0.f);
            }
            if (r0 < M) *(float2*)(C + (size_t)r0 * HD + col) = make_float2(v00, v01);
            if (r1 < M) *(float2*)(C + (size_t)r1 * HD + col) = make_float2(v10, v11);
        }
}

// smem: per quarter: As(8704) stage(16384) = 25088; x4 = 100352
#define QSZ    25088
#define SMEM_F 100352

__device__ __forceinline__ void issue_cp_tile(const float* __restrict__ A,
                                              float* stagef, int tile, int M,
                                              int tiq) {
#pragma unroll
    for (int qq = 0; qq < 8; ++qq) {
        const int i = tiq + 128 * qq;         // 0..1023
        const int r = i >> 5, c = i & 31;
        const int grow = tile * 32 + r;
        float* dst = stagef + r * 128 + c * 4;
        if (grow < M)
            cp16(dst, A + (size_t)grow * 128 + c * 4);
        else
            *(float4*)dst = make_float4(0.f, 0.f, 0.f, 0.f);
    }
}

// ---------------- fused GIN layer: 4 independent quarter-pipelines ----------
template <bool HEAD>
__global__ __launch_bounds__(512, 1) void fused_gin(
    const float* __restrict__ A,
    const uint4* __restrict__ W1Fh, const uint4* __restrict__ W1Fl,
    const uint4* __restrict__ W2Fh, const uint4* __restrict__ W2Fl,
    const uint4* __restrict__ WoFh, const uint4* __restrict__ WoFl,
    const float* __restrict__ b1, const float* __restrict__ b2,
    const float* __restrict__ b3,
    float* __restrict__ C, int M, int nTiles) {
    extern __shared__ char smem[];
    const int tid = threadIdx.x, lane = tid & 31, wid = tid >> 5;
    const int q = wid >> 2, cc = wid & 3, tiq = tid & 127;

    __half* As = (__half*)(smem + q * QSZ);
    float* stagef = (float*)(smem + q * QSZ + 8704);

    const int barid = 1 + q;
    const int colBase = cc * 32;
    const int lrow = lane & 15, lkoff = (lane >> 4) * 8;
    const int cq = (lane & 3) * 2, rq = lane >> 2;

    float b1r[4][2], b2r[4][2], b3r[2][2];
#pragma unroll
    for (int ni = 0; ni < 4; ++ni) {
        const int col = colBase + ni * 8 + cq;
        b1r[ni][0] = b1[col]; b1r[ni][1] = b1[col + 1];
        b2r[ni][0] = b2[col]; b2r[ni][1] = b2[col + 1];
    }
    if (HEAD) {
#pragma unroll
        for (int ni = 0; ni < 2; ++ni) {
            const int col = cc * 16 + ni * 8 + cq;
            b3r[ni][0] = b3[col]; b3r[ni][1] = b3[col + 1];
        }
    }

    int tile = blockIdx.x * 4 + q;
    if (tile < nTiles) issue_cp_tile(A, stagef, tile, M, tiq);
    CP_COMMIT();

    for (; tile < nTiles; tile += gridDim.x * 4) {
        const int m0 = tile * 32;
        CP_WAIT0();
        BARQ(barid);

        // build A tile (32 rows; 4 warps x 8 rows), f32 -> fp16
#pragma unroll
        for (int rr = 0; rr < 8; ++rr) {
            const int r = cc * 8 + rr;
            float4 v = ((const float4*)stagef)[r * 32 + lane];
            *(uint2*)(As + r * SA + lane * 4) =
                make_uint2(packh(v.x, v.y), packh(v.z, v.w));
        }
        BARQ(barid);

        const int nxt = tile + gridDim.x * 4;
        if (nxt < nTiles) issue_cp_tile(A, stagef, nxt, M, tiq);
        CP_COMMIT();

        float acc[2][4][4];
        gemm_pass_frag(As, W1Fh, W1Fl, cc, lrow, lkoff, lane, acc);
        BARQ(barid);
        epi_to_smem(acc, b1r, As, colBase, lane);
        BARQ(barid);
        gemm_pass_frag(As, W2Fh, W2Fl, cc, lrow, lkoff, lane, acc);

        if (!HEAD) {
            write_out128<true>(acc, b2r, C, m0, colBase, cq, rq, M);
        } else {
            BARQ(barid);
            epi_to_smem(acc, b2r, As, colBase, lane);
            BARQ(barid);
            float acc3[2][2][4];
#pragma unroll
            for (int mi = 0; mi < 2; ++mi)
#pragma unroll
                for (int ni = 0; ni < 2; ++ni)
#pragma unroll
                    for (int p = 0; p < 4; ++p) acc3[mi][ni][p] = 0.f;
#pragma unroll
            for (int ks = 0; ks < 8; ++ks) {
                const int k0 = ks * 16 + lkoff;
                uint32_t ah[2][4];
#pragma unroll
                for (int mi = 0; mi < 2; ++mi)
                    ldsm4(ah[mi], As + (mi * 16 + lrow) * SA + k0);
                const uint4 bh = WoFh[(cc * 8 + ks) * 32 + lane];
                const uint4 bl = WoFl[(cc * 8 + ks) * 32 + lane];
#pragma unroll
                for (int mi = 0; mi < 2; ++mi) {
                    mma_f16(acc3[mi][0], ah[mi], bh.x, bh.z);
                    mma_f16(acc3[mi][0], ah[mi], bl.x, bl.z);
                    mma_f16(acc3[mi][1], ah[mi], bh.y, bh.w);
                    mma_f16(acc3[mi][1], ah[mi], bl.y, bl.w);
                }
            }
#pragma unroll
            for (int mi = 0; mi < 2; ++mi)
#pragma unroll
                for (int ni = 0; ni < 2; ++ni) {
                    const int col = cc * 16 + ni * 8 + cq;
                    const int r0 = m0 + mi * 16 + rq, r1 = r0 + 8;
                    if (r0 < M)
                        *(float2*)(C + (size_t)r0 * OD + col) = make_float2(
                            acc3[mi][ni][0] + b3r[ni][0], acc3[mi][ni][1] + b3r[ni][1]);
                    if (r1 < M)
                        *(float2*)(C + (size_t)r1 * OD + col) = make_float2(
                            acc3[mi][ni][2] + b3r[ni][0], acc3[mi][ni][3] + b3r[ni][1]);
                }
        }
    }
}

// ---------------- fused node layer 1 + MLP (4 passes) ----------------------
__global__ __launch_bounds__(512, 1) void fused_gin_mlp(
    const float* __restrict__ A,
    const uint4* __restrict__ WaFh, const uint4* __restrict__ WaFl,
    const uint4* __restrict__ WbFh, const uint4* __restrict__ WbFl,
    const uint4* __restrict__ WcFh, const uint4* __restrict__ WcFl,
    const uint4* __restrict__ WdFh, const uint4* __restrict__ WdFl,
    const float* __restrict__ b1, const float* __restrict__ b2,
    const float* __restrict__ b3, const float* __restrict__ b4,
    float* __restrict__ C, int M, int nTiles) {
    extern __shared__ char smem[];
    const int tid = threadIdx.x, lane = tid & 31, wid = tid >> 5;
    const int q = wid >> 2, cc = wid & 3, tiq = tid & 127;

    __half* As = (__half*)(smem + q * QSZ);
    float* stagef = (float*)(smem + q * QSZ + 8704);

    const int barid = 1 + q;
    const int colBase = cc * 32;
    const int lrow = lane & 15, lkoff = (lane >> 4) * 8;
    const int cq = (lane & 3) * 2, rq = lane >> 2;

    float b1r[4][2], b2r[4][2], b3r[4][2], b4r[4][2];
#pragma unroll
    for (int ni = 0; ni < 4; ++ni) {
        const int col = colBase + ni * 8 + cq;
        b1r[ni][0] = b1[col]; b1r[ni][1] = b1[col + 1];
        b2r[ni][0] = b2[col]; b2r[ni][1] = b2[col + 1];
        b3r[ni][0] = b3[col]; b3r[ni][1] = b3[col + 1];
        b4r[ni][0] = b4[col]; b4r[ni][1] = b4[col + 1];
    }

    int tile = blockIdx.x * 4 + q;
    if (tile < nTiles) issue_cp_tile(A, stagef, tile, M, tiq);
    CP_COMMIT();

    for (; tile < nTiles; tile += gridDim.x * 4) {
        const int m0 = tile * 32;
        CP_WAIT0();
        BARQ(barid);
#pragma unroll
        for (int rr = 0; rr < 8; ++rr) {
            const int r = cc * 8 + rr;
            float4 v = ((const float4*)stagef)[r * 32 + lane];
            *(uint2*)(As + r * SA + lane * 4) =
                make_uint2(packh(v.x, v.y), packh(v.z, v.w));
        }
        BARQ(barid);
        const int nxt = tile + gridDim.x * 4;
        if (nxt < nTiles) issue_cp_tile(A, stagef, nxt, M, tiq);
        CP_COMMIT();

        float acc[2][4][4];
        gemm_pass_frag(As, WaFh, WaFl, cc, lrow, lkoff, lane, acc);
        BARQ(barid);
        epi_to_smem(acc, b1r, As, colBase, lane);
        BARQ(barid);
        gemm_pass_frag(As, WbFh, WbFl, cc, lrow, lkoff, lane, acc);
        BARQ(barid);
        epi_to_smem(acc, b2r, As, colBase, lane);   // layer out (relu)
        BARQ(barid);
        gemm_pass_frag(As, WcFh, WcFl, cc, lrow, lkoff, lane, acc);
        BARQ(barid);
        epi_to_smem(acc, b3r, As, colBase, lane);   // mlp hidden (relu)
        BARQ(barid);
        gemm_pass_frag(As, WdFh, WdFl, cc, lrow, lkoff, lane, acc);
        write_out128<false>(acc, b4r, C, m0, colBase, cq, rq, M);
    }
}

// ---------------- weight prep ------------------------------------------------
struct PrepArgs {
    const float *W1[5], *b1[5], *g[5], *bb[5], *m[5], *v[5], *W2[5], *Wo;
    __half *W1h[5], *W1l[5], *W2h[5], *W2l[5];
    uint32_t *Wofh, *Wofl;
    float* bf[5];
};

__global__ void prep_weights(PrepArgs a) {
    const int blk = blockIdx.x, tid = threadIdx.x;
    if (blk < 320) {
        const int j = blk >> 6;
        const int idx = ((blk & 63) << 8) + tid;
        const int k = idx >> 7, n = idx & 127;
        float s = a.g[j][n] * rsqrtf(a.v[j][n] + 1e-5f);
        float val = a.W1[j][idx] * s;
        __half h = __float2half(val);
        a.W1h[j][n * 128 + k] = h;
        a.W1l[j][n * 128 + k] = __float2half(val - __half2float(h));
        if (idx < 128)
            a.bf[j][idx] = a.b1[j][idx] * s + a.bb[j][idx] - a.m[j][idx] * s;
    } else if (blk < 640) {
        const int j = (blk - 320) >> 6;
        const int idx = (((blk - 320) & 63) << 8) + tid;
        const int k = idx >> 7, n = idx & 127;
        float val = a.W2[j][idx];
        __half h = __float2half(val);
        a.W2h[j][n * 128 + k] = h;
        a.W2l[j][n * 128 + k] = __float2half(val - __half2float(h));
    } else {
        const int idx = ((blk - 640) << 8) + tid;  // 0..4095 (Wo frags)
        const int j = idx & 3, L = (idx >> 2) & 31;
        const int ks = (idx >> 7) & 7, cc = idx >> 10;
        const int n = cc * 16 + (j & 1) * 8 + (L >> 2);
        const int k = ks * 16 + ((j >> 1)) * 8 + (L & 3) * 2;
        float v0 = a.Wo[k * OD + n];
        float v1 = a.Wo[(k + 1) * OD + n];
        __half h0 = __float2half(v0), h1 = __float2half(v1);
        __half l0 = __float2half(v0 - __half2float(h0));
        __half l1 = __float2half(v1 - __half2float(h1));
        __half2 th = __halves2half2(h0, h1), tl = __halves2half2(l0, l1);
        a.Wofh[((cc * 8 + ks) * 32 + L) * 4 + j] = *(uint32_t*)&th;
        a.Wofl[((cc * 8 + ks) * 32 + L) * 4 + j] = *(uint32_t*)&tl;
    }
}

// convert n-major fp16 images into ldmatrix-order frag arrays (N=128); 20 jobs
struct FragArgs {
    const __half* src[20];
    uint32_t* dst[20];
};
__global__ void frag_all(FragArgs a) {
    const int i = blockIdx.x * 256 + threadIdx.x;   // 0..163839
    const int m = i >> 13, e = i & 8191;
    const int j = e & 3, L = (e >> 2) & 31;
    const int ks = (e >> 7) & 7, g = e >> 10;
    const int n = g * 16 + (j & 1) * 8 + (L >> 2);
    const int k = ks * 16 + (j >> 1) * 8 + (L & 3) * 2;
    a.dst[m][e] = *(const uint32_t*)(a.src[m] + n * 128 + k);
}

// ---------------- CSR build ----------------------------------------------------
__global__ void count_deg(const int* __restrict__ dst, int E, int* __restrict__ deg) {
    int e = blockIdx.x * 256 + threadIdx.x;
    if (e < E) atomicAdd(&deg[dst[e]], 1);
}

__global__ void scan1(const int* __restrict__ deg, int* __restrict__ ex,
                      int* __restrict__ bsum, int n) {
    __shared__ int wsum[32];
    const int t = threadIdx.x;
    const int base = blockIdx.x * 4096 + t * 4;
    int v[4], s = 0;
#pragma unroll
    for (int i = 0; i < 4; ++i) {
        int idx = base + i;
        v[i] = idx < n ? deg[idx] : 0;
        s += v[i];
    }
    const int lane = t & 31, w = t >> 5;
    int ps = s;
#pragma unroll
    for (int o = 1; o < 32; o <<= 1) {
        int y = __shfl_up_sync(~0u, ps, o);
        if (lane >= o) ps += y;
    }
    if (lane == 31) wsum[w] = ps;
    __syncthreads();
    if (w == 0) {
        int x = wsum[lane];
#pragma unroll
        for (int o = 1; o < 32; o <<= 1) {
            int y = __shfl_up_sync(~0u, x, o);
            if (lane >= o) x += y;
        }
        wsum[lane] = x;
    }
    __syncthreads();
    const int warpoff = w ? wsum[w - 1] : 0;
    int run = warpoff + ps - s;
#pragma unroll
    for (int i = 0; i < 4; ++i) {
        int idx = base + i;
        if (idx < n) ex[idx] = run;
        run += v[i];
    }
    if (t == 0) bsum[blockIdx.x] = wsum[31];
}

__global__ void scan2(int* __restrict__ bsum, int nb) {
    __shared__ int sm_[1024];
    const int t = threadIdx.x;
    int v = (t < nb) ? bsum[t] : 0;
    sm_[t] = v;
    __syncthreads();
    for (int o = 1; o < 1024; o <<= 1) {
        int y = (t >= o) ? sm_[t - o] : 0;
        __syncthreads();
        sm_[t] += y;
        __syncthreads();
    }
    if (t < nb) bsum[t] = sm_[t] - v;
}

__global__ void scan3(const int* __restrict__ ex, const int* __restrict__ boff,
                      int* __restrict__ rp, int* __restrict__ cur, int n, int E) {
    int i = blockIdx.x * 1024 + threadIdx.x;
    if (i < n) {
        int vv = ex[i] + boff[i >> 12];
        rp[i] = vv;
        cur[i] = vv;
    } else if (i == n) {
        rp[n] = E;
    }
}

__global__ void fill_csr(const int* __restrict__ src, const int* __restrict__ dst,
                         int E, int* __restrict__ cur, int* __restrict__ adj) {
    int e = blockIdx.x * 256 + threadIdx.x;
    if (e < E) {
        int p = atomicAdd(&cur[dst[e]], 1);
        adj[p] = src[e];
    }
}

// ---------------- gather aggregation: agg[r] = x[r] + sum x[nbr] ---------------
__global__ void gather_agg(const float* __restrict__ x,
                           const int* __restrict__ rp,
                           const int* __restrict__ adj,
                           float* __restrict__ agg, int n) {
    unsigned t = blockIdx.x * 256u + threadIdx.x;
    unsigned r = t >> 5, lane = t & 31u;
    if (r >= (unsigned)n) return;
    const int s = rp[r], e = rp[r + 1];
    float4 acc = ((const float4*)(x + (size_t)r * HD))[lane];
    const int cnt = e - s;
    int nb_l = ((int)lane < cnt) ? adj[s + lane] : 0;
    const int lim = cnt < 32 ? cnt : 32;
    for (int j = 0; j < lim; ++j) {
        const int nb = __shfl_sync(~0u, nb_l, j);
        float4 u = ((const float4*)(x + (size_t)nb * HD))[lane];
        acc.x += u.x; acc.y += u.y; acc.z += u.z; acc.w += u.w;
    }
    for (int j = s + 32; j < e; ++j) {
        const int nb = adj[j];
        float4 u = ((const float4*)(x + (size_t)nb * HD))[lane];
        acc.x += u.x; acc.y += u.y; acc.z += u.z; acc.w += u.w;
    }
    ((float4*)(agg + (size_t)r * HD))[lane] = acc;
}

// ---- fused pair lift + aggregation (edge layer 0; y L2-resident) ------------
__global__ void pair_agg(const int* __restrict__ ep,
                         const float* __restrict__ y,
                         const int* __restrict__ rp,
                         const int* __restrict__ adj,
                         float* __restrict__ agg, int n) {
    unsigned t = blockIdx.x * 256u + threadIdx.x;
    unsigned r = t >> 5, lane = t & 31u;
    if (r >= (unsigned)n) return;
    const int s = rp[r], e = rp[r + 1];
    const int cnt = e - s;
    const int i0 = ep[2 * r], i1 = ep[2 * r + 1];
    float4 acc = ((const float4*)(y + (size_t)i0 * HD))[lane];
    float4 b = ((const float4*)(y + (size_t)i1 * HD))[lane];
    acc.x += b.x; acc.y += b.y; acc.z += b.z; acc.w += b.w;
    int p0_l = 0, p1_l = 0;
    if ((int)lane < cnt) {
        const int nb = adj[s + lane];
        p0_l = ep[2 * nb];
        p1_l = ep[2 * nb + 1];
    }
    const int lim = cnt < 32 ? cnt : 32;
    for (int j = 0; j < lim; ++j) {
        const int q0 = __shfl_sync(~0u, p0_l, j);
        const int q1 = __shfl_sync(~0u, p1_l, j);
        float4 u = ((const float4*)(y + (size_t)q0 * HD))[lane];
        float4 w = ((const float4*)(y + (size_t)q1 * HD))[lane];
        acc.x += u.x + w.x; acc.y += u.y + w.y;
        acc.z += u.z + w.z; acc.w += u.w + w.w;
    }
    for (int j = s + 32; j < e; ++j) {
        const int nb = adj[j];
        const int q0 = ep[2 * nb], q1 = ep[2 * nb + 1];
        float4 u = ((const float4*)(y + (size_t)q0 * HD))[lane];
        float4 w = ((const float4*)(y + (size_t)q1 * HD))[lane];
        acc.x += u.x + w.x; acc.y += u.y + w.y;
        acc.z += u.z + w.z; acc.w += u.w + w.w;
    }
    ((float4*)(agg + (size_t)r * HD))[lane] = acc;
}

// ----------------------------------------------------------------------------------
extern "C" void kernel_launch(void* const* d_in, const int* in_sizes, int n_in,
                              void* d_out, int out_size) {
    const int*   edge_index = (const int*)d_in[0];
    const float* x_orig     = (const float*)d_in[1];
    const int*   ei_orig    = (const int*)d_in[2];
    const int*   edge_pairs = (const int*)d_in[3];
    const float* init_W1 = (const float*)d_in[4];
    const float* init_b1 = (const float*)d_in[5];
    const float* init_g  = (const float*)d_in[6];
    const float* init_bb = (const float*)d_in[7];
    const float* init_m  = (const float*)d_in[8];
    const float* init_v  = (const float*)d_in[9];
    const float* init_W2 = (const float*)d_in[10];
    const float* init_b2 = (const float*)d_in[11];
    const float* gin_W1  = (const float*)d_in[12];
    const float* gin_b1  = (const float*)d_in[13];
    const float* gin_g   = (const float*)d_in[14];
    const float* gin_bb  = (const float*)d_in[15];
    const float* gin_m   = (const float*)d_in[16];
    const float* gin_v   = (const float*)d_in[17];
    const float* gin_W2  = (const float*)d_in[18];
    const float* gin_b2  = (const float*)d_in[19];
    const float* mlp_W1  = (const float*)d_in[20];
    const float* mlp_b1  = (const float*)d_in[21];
    const float* mlp_g   = (const float*)d_in[22];
    const float* mlp_bb  = (const float*)d_in[23];
    const float* mlp_m   = (const float*)d_in[24];
    const float* mlp_v   = (const float*)d_in[25];
    const float* mlp_W2  = (const float*)d_in[26];
    const float* mlp_b2  = (const float*)d_in[27];
    const float* out_W   = (const float*)d_in[28];
    const float* out_b   = (const float*)d_in[29];
    float* out = (float*)d_out;

    float *nodeA, *nodeB, *nodeC, *nodeD, *edgeA, *edgeB, *edgeC, *bfb;
    __half *W1h, *W1l, *W2h, *W2l;
    uint32_t *W1Fh, *W1Fl, *W2Fh, *W2Fl, *Wofh, *Wofl;
    int *deg, *ex, *bsum, *rpN, *adjN, *curN, *rpE, *adjE, *curE;
    cudaGetSymbolAddress((void**)&nodeA, g_nodeA);
    cudaGetSymbolAddress((void**)&nodeB, g_nodeB);
    cudaGetSymbolAddress((void**)&nodeC, g_nodeC);
    cudaGetSymbolAddress((void**)&nodeD, g_nodeD);
    cudaGetSymbolAddress((void**)&edgeA, g_edgeA);
    cudaGetSymbolAddress((void**)&edgeB, g_edgeB);
    cudaGetSymbolAddress((void**)&edgeC, g_edgeC);
    cudaGetSymbolAddress((void**)&bfb, g_bfb);
    cudaGetSymbolAddress((void**)&W1h, g_W1h);
    cudaGetSymbolAddress((void**)&W1l, g_W1l);
    cudaGetSymbolAddress((void**)&W2h, g_W2h);
    cudaGetSymbolAddress((void**)&W2l, g_W2l);
    cudaGetSymbolAddress((void**)&W1Fh, g_W1Fh);
    cudaGetSymbolAddress((void**)&W1Fl, g_W1Fl);
    cudaGetSymbolAddress((void**)&W2Fh, g_W2Fh);
    cudaGetSymbolAddress((void**)&W2Fl, g_W2Fl);
    cudaGetSymbolAddress((void**)&Wofh, g_Wofh);
    cudaGetSymbolAddress((void**)&Wofl, g_Wofl);
    cudaGetSymbolAddress((void**)&deg, g_deg);
    cudaGetSymbolAddress((void**)&ex, g_ex);
    cudaGetSymbolAddress((void**)&bsum, g_bsum);
    cudaGetSymbolAddress((void**)&rpN, g_rpN);
    cudaGetSymbolAddress((void**)&adjN, g_adjN);
    cudaGetSymbolAddress((void**)&curN, g_curN);
    cudaGetSymbolAddress((void**)&rpE, g_rpE);
    cudaGetSymbolAddress((void**)&adjE, g_adjE);
    cudaGetSymbolAddress((void**)&curE, g_curE);

    // ---- weight prep --------------------------------------------------------
    PrepArgs pa;
    const float* W1s[5]  = {init_W1, init_W1 + HD * HD, mlp_W1, gin_W1, gin_W1 + HD * HD};
    const float* b1s[5]  = {init_b1, init_b1 + HD, mlp_b1, gin_b1, gin_b1 + HD};
    const float* gs[5]   = {init_g, init_g + HD, mlp_g, gin_g, gin_g + HD};
    const float* bbs[5]  = {init_bb, init_bb + HD, mlp_bb, gin_bb, gin_bb + HD};
    const float* ms[5]   = {init_m, init_m + HD, mlp_m, gin_m, gin_m + HD};
    const float* vs[5]   = {init_v, init_v + HD, mlp_v, gin_v, gin_v + HD};
    const float* W2s[5]  = {init_W2, init_W2 + HD * HD, mlp_W2, gin_W2, gin_W2 + HD * HD};
    for (int j = 0; j < 5; ++j) {
        pa.W1[j] = W1s[j]; pa.b1[j] = b1s[j]; pa.g[j] = gs[j]; pa.bb[j] = bbs[j];
        pa.m[j] = ms[j]; pa.v[j] = vs[j]; pa.W2[j] = W2s[j];
        pa.W1h[j] = W1h + (size_t)j * HD * HD; pa.W1l[j] = W1l + (size_t)j * HD * HD;
        pa.W2h[j] = W2h + (size_t)j * HD * HD; pa.W2l[j] = W2l + (size_t)j * HD * HD;
        pa.bf[j] = bfb + j * HD;
    }
    pa.Wo = out_W; pa.Wofh = Wofh; pa.Wofl = Wofl;
    prep_weights<<<656, 256>>>(pa);

    FragArgs fa;
    for (int j = 0; j < 5; ++j) {
        fa.src[j]      = W1h + (size_t)j * HD * HD; fa.dst[j]      = W1Fh + (size_t)j * 8192;
        fa.src[5 + j]  = W1l + (size_t)j * HD * HD; fa.dst[5 + j]  = W1Fl + (size_t)j * 8192;
        fa.src[10 + j] = W2h + (size_t)j * HD * HD; fa.dst[10 + j] = W2Fh + (size_t)j * 8192;
        fa.src[15 + j] = W2l + (size_t)j * HD * HD; fa.dst[15 + j] = W2Fl + (size_t)j * 8192;
    }
    frag_all<<<640, 256>>>(fa);

    // ---- CSR build: node graph (dst = ei_orig[1]) ----------------------------
    cudaMemsetAsync(deg, 0, NN * sizeof(int));
    count_deg<<<(EO + 255) / 256, 256>>>(ei_orig + EO, EO, deg);
    scan1<<<(NN + 4095) / 4096, 1024>>>(deg, ex, bsum, NN);
    scan2<<<1, 1024>>>(bsum, (NN + 4095) / 4096);
    scan3<<<(NN + 1024) / 1024 + 1, 1024>>>(ex, bsum, rpN, curN, NN, EO);
    fill_csr<<<(EO + 255) / 256, 256>>>(ei_orig, ei_orig + EO, EO, curN, adjN);

    // ---- CSR build: line graph (dst = edge_index[1]) --------------------------
    cudaMemsetAsync(deg, 0, EO * sizeof(int));
    count_deg<<<(EL + 255) / 256, 256>>>(edge_index + EL, EL, deg);
    scan1<<<(EO + 4095) / 4096, 1024>>>(deg, ex, bsum, EO);
    scan2<<<1, 1024>>>(bsum, (EO + 4095) / 4096);
    scan3<<<(EO + 1024) / 1024 + 1, 1024>>>(ex, bsum, rpE, curE, EO, EL);
    fill_csr<<<(EL + 255) / 256, 256>>>(edge_index, edge_index + EL, EL, curE, adjE);

    // ---- main pipeline ----------------------------------------------------------
    cudaFuncSetAttribute(fused_gin<false>,
                         cudaFuncAttributeMaxDynamicSharedMemorySize, SMEM_F);
    cudaFuncSetAttribute(fused_gin<true>,
                         cudaFuncAttributeMaxDynamicSharedMemorySize, SMEM_F);
    cudaFuncSetAttribute(fused_gin_mlp,
                         cudaFuncAttributeMaxDynamicSharedMemorySize, SMEM_F);

    const int GRID = 148;
    const int tilesN = (NN + 31) / 32;   // 3125
    const int tilesE = (EO + 31) / 32;   // 18750
    const int gaN = ((unsigned)NN * 32u + 255u) / 256u;
    const int gaE = ((unsigned)EO * 32u + 255u) / 256u;

    // node layer 0: agg(x_orig) -> nodeB; GEMM -> nodeA
    gather_agg<<<gaN, 256>>>(x_orig, rpN, adjN, nodeB, NN);
    fused_gin<false><<<GRID, 512, SMEM_F>>>(
        nodeB, (const uint4*)W1Fh, (const uint4*)W1Fl,
        (const uint4*)W2Fh, (const uint4*)W2Fl, nullptr, nullptr,
        bfb, init_b2, nullptr, nodeA, NN, tilesN);

    // node layer 1 + MLP: agg(nodeA) -> nodeC; 4-pass GEMM -> nodeD
    gather_agg<<<gaN, 256>>>(nodeA, rpN, adjN, nodeC, NN);
    fused_gin_mlp<<<GRID, 512, SMEM_F>>>(
        nodeC,
        (const uint4*)(W1Fh + 8192), (const uint4*)(W1Fl + 8192),
        (const uint4*)(W2Fh + 8192), (const uint4*)(W2Fl + 8192),
        (const uint4*)(W1Fh + 2 * 8192), (const uint4*)(W1Fl + 2 * 8192),
        (const uint4*)(W2Fh + 2 * 8192), (const uint4*)(W2Fl + 2 * 8192),
        bfb + HD, init_b2 + HD, bfb + 2 * HD, mlp_b2, nodeD, NN, tilesN);

    // edge layer 0: fused pair-lift + agg (L2-resident nodeD) -> edgeB; GEMM -> edgeC
    pair_agg<<<gaE, 256>>>(edge_pairs, nodeD, rpE, adjE, edgeB, EO);
    fused_gin<false><<<GRID, 512, SMEM_F>>>(
        edgeB, (const uint4*)(W1Fh + 3 * 8192), (const uint4*)(W1Fl + 3 * 8192),
        (const uint4*)(W2Fh + 3 * 8192), (const uint4*)(W2Fl + 3 * 8192),
        nullptr, nullptr, bfb + 3 * HD, gin_b2, nullptr, edgeC, EO, tilesE);

    // edge layer 1 + head: agg(edgeC) -> edgeA; GEMM+head -> out
    gather_agg<<<gaE, 256>>>(edgeC, rpE, adjE, edgeA, EO);
    fused_gin<true><<<GRID, 512, SMEM_F>>>(
        edgeA, (const uint4*)(W1Fh + 4 * 8192), (const uint4*)(W1Fl + 4 * 8192),
        (const uint4*)(W2Fh + 4 * 8192), (const uint4*)(W2Fl + 4 * 8192),
        (const uint4*)Wofh, (const uint4*)Wofl,
        bfb + 4 * HD, gin_b2 + HD, out_b, out, EO, tilesE);
}

// round 13
// speedup vs baseline: 2.4114x; 1.1818x over previous
#include <cuda_runtime.h>
#include <cuda_fp16.h>
#include <cstdint>

#define NN 100000
#define EO 600000
#define EL 1200000
#define HD 128
#define OD 64
#define SA 136   // smem row stride (fp16 elems); 272B rows, 16B aligned

// ---------------- scratch (device globals) ---------------------------------
static __device__ __half g_hA[(size_t)NN * HD];
static __device__ __half g_hB[(size_t)NN * HD];
static __device__ __half g_hC[(size_t)NN * HD];
static __device__ __half g_hD[(size_t)NN * HD];
static __device__ __half g_heA[(size_t)EO * HD];
static __device__ __half g_heB[(size_t)EO * HD];
static __device__ __half g_heC[(size_t)EO * HD];
static __device__ __half g_W1h[5][HD * HD], g_W1l[5][HD * HD];   // n-major images
static __device__ __half g_W2h[5][HD * HD], g_W2l[5][HD * HD];
static __device__ uint32_t g_W1Fh[5][8192], g_W1Fl[5][8192];     // W1 frags (N=128)
static __device__ uint32_t g_W2Fh[5][8192], g_W2Fl[5][8192];     // W2 frags (N=128)
static __device__ uint32_t g_Wofh[4096], g_Wofl[4096];           // Wo frags (N=64)
static __device__ float g_bfb[5][HD];
// CSR scratch
static __device__ int g_deg[EO], g_ex[EO], g_bsum[1024];
static __device__ int g_rpN[NN + 1], g_adjN[EO], g_curN[NN];
static __device__ int g_rpE[EO + 1], g_adjE[EL], g_curE[EO];

// ---------------- PTX helpers ----------------------------------------------
__device__ __forceinline__ void ldsm4(uint32_t* r, const void* p) {
    uint32_t a = (uint32_t)__cvta_generic_to_shared(p);
    asm volatile("ldmatrix.sync.aligned.m8n8.x4.shared.b16 {%0,%1,%2,%3}, [%4];"
                 : "=r"(r[0]), "=r"(r[1]), "=r"(r[2]), "=r"(r[3]) : "r"(a));
}
__device__ __forceinline__ void stsm4(void* p, uint32_t r0, uint32_t r1,
                                      uint32_t r2, uint32_t r3) {
    uint32_t a = (uint32_t)__cvta_generic_to_shared(p);
    asm volatile("stmatrix.sync.aligned.m8n8.x4.shared.b16 [%0], {%1,%2,%3,%4};"
                 :: "r"(a), "r"(r0), "r"(r1), "r"(r2), "r"(r3) : "memory");
}
__device__ __forceinline__ void mma_f16(float* d, const uint32_t* a,
                                        uint32_t b0, uint32_t b1) {
    asm volatile(
        "mma.sync.aligned.m16n8k16.row.col.f32.f16.f16.f32 "
        "{%0,%1,%2,%3}, {%4,%5,%6,%7}, {%8,%9}, {%0,%1,%2,%3};"
        : "+f"(d[0]), "+f"(d[1]), "+f"(d[2]), "+f"(d[3])
        : "r"(a[0]), "r"(a[1]), "r"(a[2]), "r"(a[3]), "r"(b0), "r"(b1));
}
__device__ __forceinline__ void cp16(void* sdst, const void* gsrc) {
    uint32_t a = (uint32_t)__cvta_generic_to_shared(sdst);
    asm volatile("cp.async.cg.shared.global [%0], [%1], 16;"
                 :: "r"(a), "l"(gsrc) : "memory");
}
#define CP_COMMIT() asm volatile("cp.async.commit_group;" ::: "memory")
#define CP_WAIT0()  asm volatile("cp.async.wait_group 0;" ::: "memory")

__device__ __forceinline__ uint32_t packh(float a, float b) {
    __half2 t = __floats2half2_rn(a, b);
    return *(uint32_t*)&t;
}
__device__ __forceinline__ void unpackh(uint32_t v, float& a, float& b) {
    __half2 t = *(__half2*)&v;
    a = __half2float(__low2half(t));
    b = __half2float(__high2half(t));
}
#define BARQ(id) asm volatile("bar.sync %0, 128;" :: "r"(id) : "memory")

// ---------------- GEMM pass: A fp16 from smem, W fp16 hi+lo frags ----------
__device__ __forceinline__ void gemm_pass_frag(
    const __half* As,
    const uint4* __restrict__ Fh, const uint4* __restrict__ Fl,
    int cc, int lrow, int lkoff, int lane, float (&acc)[2][4][4]) {
#pragma unroll
    for (int mi = 0; mi < 2; ++mi)
#pragma unroll
        for (int ni = 0; ni < 4; ++ni)
#pragma unroll
            for (int q = 0; q < 4; ++q) acc[mi][ni][q] = 0.f;
#pragma unroll
    for (int ks = 0; ks < 8; ++ks) {
        const int k0 = ks * 16 + lkoff;
        uint32_t ah[2][4];
#pragma unroll
        for (int mi = 0; mi < 2; ++mi)
            ldsm4(ah[mi], As + (mi * 16 + lrow) * SA + k0);
#pragma unroll
        for (int nj = 0; nj < 2; ++nj) {
            const uint4 bh = Fh[((cc * 2 + nj) * 8 + ks) * 32 + lane];
            const uint4 bl = Fl[((cc * 2 + nj) * 8 + ks) * 32 + lane];
#pragma unroll
            for (int mi = 0; mi < 2; ++mi) {
                const int n0 = nj * 2;
                mma_f16(acc[mi][n0], ah[mi], bh.x, bh.z);
                mma_f16(acc[mi][n0], ah[mi], bl.x, bl.z);
                mma_f16(acc[mi][n0 + 1], ah[mi], bh.y, bh.w);
                mma_f16(acc[mi][n0 + 1], ah[mi], bl.y, bl.w);
            }
        }
    }
}

// bias+relu then stmatrix back into As (quarter rows 0..31)
__device__ __forceinline__ void epi_to_smem(
    const float (&acc)[2][4][4], const float (&br)[4][2],
    __half* As, int colBase, int lane) {
    const int srow = (lane & 7) + ((lane >> 3) & 1) * 8;
    const int scol = (lane >> 4) * 8;
#pragma unroll
    for (int mi = 0; mi < 2; ++mi) {
#pragma unroll
        for (int ng = 0; ng < 2; ++ng) {
            float v[2][4];
#pragma unroll
            for (int q = 0; q < 2; ++q) {
                const int ni = ng * 2 + q;
                v[q][0] = fmaxf(acc[mi][ni][0] + br[ni][0], 0.f);
                v[q][1] = fmaxf(acc[mi][ni][1] + br[ni][1], 0.f);
                v[q][2] = fmaxf(acc[mi][ni][2] + br[ni][0], 0.f);
                v[q][3] = fmaxf(acc[mi][ni][3] + br[ni][1], 0.f);
            }
            const int off = (mi * 16 + srow) * SA + colBase + ng * 16 + scol;
            stsm4(As + off, packh(v[0][0], v[0][1]), packh(v[0][2], v[0][3]),
                  packh(v[1][0], v[1][1]), packh(v[1][2], v[1][3]));
        }
    }
}

// gmem write: acc + bias + relu -> C [M,HD] as fp16
__device__ __forceinline__ void write_outh(
    const float (&acc)[2][4][4], const float (&br)[4][2],
    __half* __restrict__ C, int m0, int colBase, int cq, int rq, int M) {
#pragma unroll
    for (int mi = 0; mi < 2; ++mi)
#pragma unroll
        for (int ni = 0; ni < 4; ++ni) {
            const int col = colBase + ni * 8 + cq;
            const int r0 = m0 + mi * 16 + rq, r1 = r0 + 8;
            float v00 = fmaxf(acc[mi][ni][0] + br[ni][0], 0.f);
            float v01 = fmaxf(acc[mi][ni][1] + br[ni][1], 0.f);
            float v10 = fmaxf(acc[mi][ni][2] + br[ni][0], 0.f);
            float v11 = fmaxf(acc[mi][ni][3] + br[ni][1], 0.f);
            if (r0 < M) *(uint32_t*)(C + (size_t)r0 * HD + col) = packh(v00, v01);
            if (r1 < M) *(uint32_t*)(C + (size_t)r1 * HD + col) = packh(v10, v11);
        }
}

// smem: per quarter: two ping-pong As buffers (8704 B each) = 17408; x4
#define QSZ    17408
#define SMEM_F 69632

// cp.async a 32-row fp16 tile straight into ldsm layout (row*SA)
__device__ __forceinline__ void issue_cp_tileh(const __half* __restrict__ A,
                                               __half* Asdst, int tile, int M,
                                               int tiq) {
#pragma unroll
    for (int qq = 0; qq < 4; ++qq) {
        const int i = tiq + 128 * qq;         // 0..511
        const int r = i >> 4, c = i & 15;     // 16 x 16B chunks per 256B row
        const int grow = tile * 32 + r;
        __half* dst = Asdst + r * SA + c * 8;
        if (grow < M)
            cp16(dst, A + (size_t)grow * HD + c * 8);
        else
            *(uint4*)dst = make_uint4(0, 0, 0, 0);
    }
}

// ---------------- fused GIN layer: 4 independent quarter-pipelines ----------
// HEAD=false: out fp16 [M,HD]; HEAD=true: third GEMM vs Wo, out f32 [M,OD]
template <bool HEAD>
__global__ __launch_bounds__(512, 1) void fused_gin(
    const __half* __restrict__ A,
    const uint4* __restrict__ W1Fh, const uint4* __restrict__ W1Fl,
    const uint4* __restrict__ W2Fh, const uint4* __restrict__ W2Fl,
    const uint4* __restrict__ WoFh, const uint4* __restrict__ WoFl,
    const float* __restrict__ b1, const float* __restrict__ b2,
    const float* __restrict__ b3,
    __half* __restrict__ C, float* __restrict__ Cf, int M, int nTiles) {
    extern __shared__ char smem[];
    const int tid = threadIdx.x, lane = tid & 31, wid = tid >> 5;
    const int q = wid >> 2, cc = wid & 3, tiq = tid & 127;

    __half* As0 = (__half*)(smem + q * QSZ);
    __half* As1 = As0 + 32 * SA;

    const int barid = 1 + q;
    const int colBase = cc * 32;
    const int lrow = lane & 15, lkoff = (lane >> 4) * 8;
    const int cq = (lane & 3) * 2, rq = lane >> 2;

    float b1r[4][2], b2r[4][2], b3r[2][2];
#pragma unroll
    for (int ni = 0; ni < 4; ++ni) {
        const int col = colBase + ni * 8 + cq;
        b1r[ni][0] = b1[col]; b1r[ni][1] = b1[col + 1];
        b2r[ni][0] = b2[col]; b2r[ni][1] = b2[col + 1];
    }
    if (HEAD) {
#pragma unroll
        for (int ni = 0; ni < 2; ++ni) {
            const int col = cc * 16 + ni * 8 + cq;
            b3r[ni][0] = b3[col]; b3r[ni][1] = b3[col + 1];
        }
    }

    int tile = blockIdx.x * 4 + q;
    int pb = 0;
    if (tile < nTiles) issue_cp_tileh(A, As0, tile, M, tiq);
    CP_COMMIT();

    for (; tile < nTiles; tile += gridDim.x * 4) {
        const int m0 = tile * 32;
        __half* Asb = pb ? As1 : As0;
        __half* Aso = pb ? As0 : As1;
        CP_WAIT0();
        BARQ(barid);   // this tile's A landed; previous iteration fully done

        const int nxt = tile + gridDim.x * 4;
        if (nxt < nTiles) issue_cp_tileh(A, Aso, nxt, M, tiq);
        CP_COMMIT();

        float acc[2][4][4];
        gemm_pass_frag(Asb, W1Fh, W1Fl, cc, lrow, lkoff, lane, acc);
        BARQ(barid);
        epi_to_smem(acc, b1r, Asb, colBase, lane);
        BARQ(barid);
        gemm_pass_frag(Asb, W2Fh, W2Fl, cc, lrow, lkoff, lane, acc);

        if (!HEAD) {
            write_outh(acc, b2r, C, m0, colBase, cq, rq, M);
        } else {
            BARQ(barid);
            epi_to_smem(acc, b2r, Asb, colBase, lane);
            BARQ(barid);
            float acc3[2][2][4];
#pragma unroll
            for (int mi = 0; mi < 2; ++mi)
#pragma unroll
                for (int ni = 0; ni < 2; ++ni)
#pragma unroll
                    for (int p = 0; p < 4; ++p) acc3[mi][ni][p] = 0.f;
#pragma unroll
            for (int ks = 0; ks < 8; ++ks) {
                const int k0 = ks * 16 + lkoff;
                uint32_t ah[2][4];
#pragma unroll
                for (int mi = 0; mi < 2; ++mi)
                    ldsm4(ah[mi], Asb + (mi * 16 + lrow) * SA + k0);
                const uint4 bh = WoFh[(cc * 8 + ks) * 32 + lane];
                const uint4 bl = WoFl[(cc * 8 + ks) * 32 + lane];
#pragma unroll
                for (int mi = 0; mi < 2; ++mi) {
                    mma_f16(acc3[mi][0], ah[mi], bh.x, bh.z);
                    mma_f16(acc3[mi][0], ah[mi], bl.x, bl.z);
                    mma_f16(acc3[mi][1], ah[mi], bh.y, bh.w);
                    mma_f16(acc3[mi][1], ah[mi], bl.y, bl.w);
                }
            }
#pragma unroll
            for (int mi = 0; mi < 2; ++mi)
#pragma unroll
                for (int ni = 0; ni < 2; ++ni) {
                    const int col = cc * 16 + ni * 8 + cq;
                    const int r0 = m0 + mi * 16 + rq, r1 = r0 + 8;
                    if (r0 < M)
                        *(float2*)(Cf + (size_t)r0 * OD + col) = make_float2(
                            acc3[mi][ni][0] + b3r[ni][0], acc3[mi][ni][1] + b3r[ni][1]);
                    if (r1 < M)
                        *(float2*)(Cf + (size_t)r1 * OD + col) = make_float2(
                            acc3[mi][ni][2] + b3r[ni][0], acc3[mi][ni][3] + b3r[ni][1]);
                }
        }
        pb ^= 1;
    }
}

// ---------------- fused node layer 1 + MLP (4 passes) ----------------------
__global__ __launch_bounds__(512, 1) void fused_gin_mlp(
    const __half* __restrict__ A,
    const uint4* __restrict__ WaFh, const uint4* __restrict__ WaFl,
    const uint4* __restrict__ WbFh, const uint4* __restrict__ WbFl,
    const uint4* __restrict__ WcFh, const uint4* __restrict__ WcFl,
    const uint4* __restrict__ WdFh, const uint4* __restrict__ WdFl,
    const float* __restrict__ b1, const float* __restrict__ b2,
    const float* __restrict__ b3, const float* __restrict__ b4,
    __half* __restrict__ C, int M, int nTiles) {
    extern __shared__ char smem[];
    const int tid = threadIdx.x, lane = tid & 31, wid = tid >> 5;
    const int q = wid >> 2, cc = wid & 3, tiq = tid & 127;

    __half* As0 = (__half*)(smem + q * QSZ);
    __half* As1 = As0 + 32 * SA;

    const int barid = 1 + q;
    const int colBase = cc * 32;
    const int lrow = lane & 15, lkoff = (lane >> 4) * 8;
    const int cq = (lane & 3) * 2, rq = lane >> 2;

    float b1r[4][2], b2r[4][2], b3r[4][2], b4r[4][2];
#pragma unroll
    for (int ni = 0; ni < 4; ++ni) {
        const int col = colBase + ni * 8 + cq;
        b1r[ni][0] = b1[col]; b1r[ni][1] = b1[col + 1];
        b2r[ni][0] = b2[col]; b2r[ni][1] = b2[col + 1];
        b3r[ni][0] = b3[col]; b3r[ni][1] = b3[col + 1];
        b4r[ni][0] = b4[col]; b4r[ni][1] = b4[col + 1];
    }

    int tile = blockIdx.x * 4 + q;
    int pb = 0;
    if (tile < nTiles) issue_cp_tileh(A, As0, tile, M, tiq);
    CP_COMMIT();

    for (; tile < nTiles; tile += gridDim.x * 4) {
        const int m0 = tile * 32;
        __half* Asb = pb ? As1 : As0;
        __half* Aso = pb ? As0 : As1;
        CP_WAIT0();
        BARQ(barid);

        const int nxt = tile + gridDim.x * 4;
        if (nxt < nTiles) issue_cp_tileh(A, Aso, nxt, M, tiq);
        CP_COMMIT();

        float acc[2][4][4];
        gemm_pass_frag(Asb, WaFh, WaFl, cc, lrow, lkoff, lane, acc);
        BARQ(barid);
        epi_to_smem(acc, b1r, Asb, colBase, lane);
        BARQ(barid);
        gemm_pass_frag(Asb, WbFh, WbFl, cc, lrow, lkoff, lane, acc);
        BARQ(barid);
        epi_to_smem(acc, b2r, Asb, colBase, lane);   // layer out (relu)
        BARQ(barid);
        gemm_pass_frag(Asb, WcFh, WcFl, cc, lrow, lkoff, lane, acc);
        BARQ(barid);
        epi_to_smem(acc, b3r, Asb, colBase, lane);   // mlp hidden (relu)
        BARQ(barid);
        gemm_pass_frag(Asb, WdFh, WdFl, cc, lrow, lkoff, lane, acc);
        // mlp out (no relu) -> fp16
#pragma unroll
        for (int mi = 0; mi < 2; ++mi)
#pragma unroll
            for (int ni = 0; ni < 4; ++ni) {
                const int col = colBase + ni * 8 + cq;
                const int r0 = m0 + mi * 16 + rq, r1 = r0 + 8;
                if (r0 < M)
                    *(uint32_t*)(C + (size_t)r0 * HD + col) =
                        packh(acc[mi][ni][0] + b4r[ni][0], acc[mi][ni][1] + b4r[ni][1]);
                if (r1 < M)
                    *(uint32_t*)(C + (size_t)r1 * HD + col) =
                        packh(acc[mi][ni][2] + b4r[ni][0], acc[mi][ni][3] + b4r[ni][1]);
            }
        pb ^= 1;
    }
}

// ---------------- weight prep ------------------------------------------------
struct PrepArgs {
    const float *W1[5], *b1[5], *g[5], *bb[5], *m[5], *v[5], *W2[5], *Wo;
    __half *W1h[5], *W1l[5], *W2h[5], *W2l[5];
    uint32_t *Wofh, *Wofl;
    float* bf[5];
};

__global__ void prep_weights(PrepArgs a) {
    const int blk = blockIdx.x, tid = threadIdx.x;
    if (blk < 320) {
        const int j = blk >> 6;
        const int idx = ((blk & 63) << 8) + tid;
        const int k = idx >> 7, n = idx & 127;
        float s = a.g[j][n] * rsqrtf(a.v[j][n] + 1e-5f);
        float val = a.W1[j][idx] * s;
        __half h = __float2half(val);
        a.W1h[j][n * 128 + k] = h;
        a.W1l[j][n * 128 + k] = __float2half(val - __half2float(h));
        if (idx < 128)
            a.bf[j][idx] = a.b1[j][idx] * s + a.bb[j][idx] - a.m[j][idx] * s;
    } else if (blk < 640) {
        const int j = (blk - 320) >> 6;
        const int idx = (((blk - 320) & 63) << 8) + tid;
        const int k = idx >> 7, n = idx & 127;
        float val = a.W2[j][idx];
        __half h = __float2half(val);
        a.W2h[j][n * 128 + k] = h;
        a.W2l[j][n * 128 + k] = __float2half(val - __half2float(h));
    } else {
        const int idx = ((blk - 640) << 8) + tid;  // 0..4095 (Wo frags)
        const int j = idx & 3, L = (idx >> 2) & 31;
        const int ks = (idx >> 7) & 7, cc = idx >> 10;
        const int n = cc * 16 + (j & 1) * 8 + (L >> 2);
        const int k = ks * 16 + ((j >> 1)) * 8 + (L & 3) * 2;
        float v0 = a.Wo[k * OD + n];
        float v1 = a.Wo[(k + 1) * OD + n];
        __half h0 = __float2half(v0), h1 = __float2half(v1);
        __half l0 = __float2half(v0 - __half2float(h0));
        __half l1 = __float2half(v1 - __half2float(h1));
        __half2 th = __halves2half2(h0, h1), tl = __halves2half2(l0, l1);
        a.Wofh[((cc * 8 + ks) * 32 + L) * 4 + j] = *(uint32_t*)&th;
        a.Wofl[((cc * 8 + ks) * 32 + L) * 4 + j] = *(uint32_t*)&tl;
    }
}

struct FragArgs {
    const __half* src[20];
    uint32_t* dst[20];
};
__global__ void frag_all(FragArgs a) {
    const int i = blockIdx.x * 256 + threadIdx.x;   // 0..163839
    const int m = i >> 13, e = i & 8191;
    const int j = e & 3, L = (e >> 2) & 31;
    const int ks = (e >> 7) & 7, g = e >> 10;
    const int n = g * 16 + (j & 1) * 8 + (L >> 2);
    const int k = ks * 16 + (j >> 1) * 8 + (L & 3) * 2;
    a.dst[m][e] = *(const uint32_t*)(a.src[m] + n * 128 + k);
}

// ---------------- CSR build ----------------------------------------------------
__global__ void count_deg(const int* __restrict__ dst, int E, int* __restrict__ deg) {
    int e = blockIdx.x * 256 + threadIdx.x;
    if (e < E) atomicAdd(&deg[dst[e]], 1);
}

__global__ void scan1(const int* __restrict__ deg, int* __restrict__ ex,
                      int* __restrict__ bsum, int n) {
    __shared__ int wsum[32];
    const int t = threadIdx.x;
    const int base = blockIdx.x * 4096 + t * 4;
    int v[4], s = 0;
#pragma unroll
    for (int i = 0; i < 4; ++i) {
        int idx = base + i;
        v[i] = idx < n ? deg[idx] : 0;
        s += v[i];
    }
    const int lane = t & 31, w = t >> 5;
    int ps = s;
#pragma unroll
    for (int o = 1; o < 32; o <<= 1) {
        int y = __shfl_up_sync(~0u, ps, o);
        if (lane >= o) ps += y;
    }
    if (lane == 31) wsum[w] = ps;
    __syncthreads();
    if (w == 0) {
        int x = wsum[lane];
#pragma unroll
        for (int o = 1; o < 32; o <<= 1) {
            int y = __shfl_up_sync(~0u, x, o);
            if (lane >= o) x += y;
        }
        wsum[lane] = x;
    }
    __syncthreads();
    const int warpoff = w ? wsum[w - 1] : 0;
    int run = warpoff + ps - s;
#pragma unroll
    for (int i = 0; i < 4; ++i) {
        int idx = base + i;
        if (idx < n) ex[idx] = run;
        run += v[i];
    }
    if (t == 0) bsum[blockIdx.x] = wsum[31];
}

__global__ void scan2(int* __restrict__ bsum, int nb) {
    __shared__ int sm_[1024];
    const int t = threadIdx.x;
    int v = (t < nb) ? bsum[t] : 0;
    sm_[t] = v;
    __syncthreads();
    for (int o = 1; o < 1024; o <<= 1) {
        int y = (t >= o) ? sm_[t - o] : 0;
        __syncthreads();
        sm_[t] += y;
        __syncthreads();
    }
    if (t < nb) bsum[t] = sm_[t] - v;
}

__global__ void scan3(const int* __restrict__ ex, const int* __restrict__ boff,
                      int* __restrict__ rp, int* __restrict__ cur, int n, int E) {
    int i = blockIdx.x * 1024 + threadIdx.x;
    if (i < n) {
        int vv = ex[i] + boff[i >> 12];
        rp[i] = vv;
        cur[i] = vv;
    } else if (i == n) {
        rp[n] = E;
    }
}

__global__ void fill_csr(const int* __restrict__ src, const int* __restrict__ dst,
                         int E, int* __restrict__ cur, int* __restrict__ adj) {
    int e = blockIdx.x * 256 + threadIdx.x;
    if (e < E) {
        int p = atomicAdd(&cur[dst[e]], 1);
        adj[p] = src[e];
    }
}

// ---------------- gather aggregation (fp16 rows, f32 accumulate) --------------
// lane handles 4 halves (8B) of the 256B row
__device__ __forceinline__ void addrow_h(const __half* __restrict__ x, int row,
                                         int lane, float (&acc)[4]) {
    uint2 u = *(const uint2*)(x + (size_t)row * HD + lane * 4);
    float a0, a1, a2, a3;
    unpackh(u.x, a0, a1);
    unpackh(u.y, a2, a3);
    acc[0] += a0; acc[1] += a1; acc[2] += a2; acc[3] += a3;
}

// first layer: x f32, out fp16
__global__ void gather_agg_f(const float* __restrict__ x,
                             const int* __restrict__ rp,
                             const int* __restrict__ adj,
                             __half* __restrict__ agg, int n) {
    unsigned t = blockIdx.x * 256u + threadIdx.x;
    unsigned r = t >> 5, lane = t & 31u;
    if (r >= (unsigned)n) return;
    const int s = rp[r], e = rp[r + 1];
    float4 acc = ((const float4*)(x + (size_t)r * HD))[lane];
    const int cnt = e - s;
    int nb_l = ((int)lane < cnt) ? adj[s + lane] : 0;
    const int lim = cnt < 32 ? cnt : 32;
    for (int j = 0; j < lim; ++j) {
        const int nb = __shfl_sync(~0u, nb_l, j);
        float4 u = ((const float4*)(x + (size_t)nb * HD))[lane];
        acc.x += u.x; acc.y += u.y; acc.z += u.z; acc.w += u.w;
    }
    for (int j = s + 32; j < e; ++j) {
        const int nb = adj[j];
        float4 u = ((const float4*)(x + (size_t)nb * HD))[lane];
        acc.x += u.x; acc.y += u.y; acc.z += u.z; acc.w += u.w;
    }
    *(uint2*)(agg + (size_t)r * HD + lane * 4) =
        make_uint2(packh(acc.x, acc.y), packh(acc.z, acc.w));
}

// fp16 in, fp16 out
__global__ void gather_agg_h(const __half* __restrict__ x,
                             const int* __restrict__ rp,
                             const int* __restrict__ adj,
                             __half* __restrict__ agg, int n) {
    unsigned t = blockIdx.x * 256u + threadIdx.x;
    unsigned r = t >> 5, lane = t & 31u;
    if (r >= (unsigned)n) return;
    const int s = rp[r], e = rp[r + 1];
    float acc[4] = {0.f, 0.f, 0.f, 0.f};
    addrow_h(x, r, lane, acc);
    const int cnt = e - s;
    int nb_l = ((int)lane < cnt) ? adj[s + lane] : 0;
    const int lim = cnt < 32 ? cnt : 32;
    for (int j = 0; j < lim; ++j) {
        const int nb = __shfl_sync(~0u, nb_l, j);
        addrow_h(x, nb, lane, acc);
    }
    for (int j = s + 32; j < e; ++j) addrow_h(x, adj[j], lane, acc);
    *(uint2*)(agg + (size_t)r * HD + lane * 4) =
        make_uint2(packh(acc[0], acc[1]), packh(acc[2], acc[3]));
}

// fused pair lift + aggregation (fp16 y, L2-resident)
__global__ void pair_agg_h(const int* __restrict__ ep,
                           const __half* __restrict__ y,
                           const int* __restrict__ rp,
                           const int* __restrict__ adj,
                           __half* __restrict__ agg, int n) {
    unsigned t = blockIdx.x * 256u + threadIdx.x;
    unsigned r = t >> 5, lane = t & 31u;
    if (r >= (unsigned)n) return;
    const int s = rp[r], e = rp[r + 1];
    const int cnt = e - s;
    float acc[4] = {0.f, 0.f, 0.f, 0.f};
    addrow_h(y, ep[2 * r], lane, acc);
    addrow_h(y, ep[2 * r + 1], lane, acc);
    int p0_l = 0, p1_l = 0;
    if ((int)lane < cnt) {
        const int nb = adj[s + lane];
        p0_l = ep[2 * nb];
        p1_l = ep[2 * nb + 1];
    }
    const int lim = cnt < 32 ? cnt : 32;
    for (int j = 0; j < lim; ++j) {
        addrow_h(y, __shfl_sync(~0u, p0_l, j), lane, acc);
        addrow_h(y, __shfl_sync(~0u, p1_l, j), lane, acc);
    }
    for (int j = s + 32; j < e; ++j) {
        const int nb = adj[j];
        addrow_h(y, ep[2 * nb], lane, acc);
        addrow_h(y, ep[2 * nb + 1], lane, acc);
    }
    *(uint2*)(agg + (size_t)r * HD + lane * 4) =
        make_uint2(packh(acc[0], acc[1]), packh(acc[2], acc[3]));
}

// ----------------------------------------------------------------------------------
extern "C" void kernel_launch(void* const* d_in, const int* in_sizes, int n_in,
                              void* d_out, int out_size) {
    const int*   edge_index = (const int*)d_in[0];
    const float* x_orig     = (const float*)d_in[1];
    const int*   ei_orig    = (const int*)d_in[2];
    const int*   edge_pairs = (const int*)d_in[3];
    const float* init_W1 = (const float*)d_in[4];
    const float* init_b1 = (const float*)d_in[5];
    const float* init_g  = (const float*)d_in[6];
    const float* init_bb = (const float*)d_in[7];
    const float* init_m  = (const float*)d_in[8];
    const float* init_v  = (const float*)d_in[9];
    const float* init_W2 = (const float*)d_in[10];
    const float* init_b2 = (const float*)d_in[11];
    const float* gin_W1  = (const float*)d_in[12];
    const float* gin_b1  = (const float*)d_in[13];
    const float* gin_g   = (const float*)d_in[14];
    const float* gin_bb  = (const float*)d_in[15];
    const float* gin_m   = (const float*)d_in[16];
    const float* gin_v   = (const float*)d_in[17];
    const float* gin_W2  = (const float*)d_in[18];
    const float* gin_b2  = (const float*)d_in[19];
    const float* mlp_W1  = (const float*)d_in[20];
    const float* mlp_b1  = (const float*)d_in[21];
    const float* mlp_g   = (const float*)d_in[22];
    const float* mlp_bb  = (const float*)d_in[23];
    const float* mlp_m   = (const float*)d_in[24];
    const float* mlp_v   = (const float*)d_in[25];
    const float* mlp_W2  = (const float*)d_in[26];
    const float* mlp_b2  = (const float*)d_in[27];
    const float* out_W   = (const float*)d_in[28];
    const float* out_b   = (const float*)d_in[29];
    float* out = (float*)d_out;

    __half *hA, *hB, *hC, *hD, *heA, *heB, *heC;
    __half *W1h, *W1l, *W2h, *W2l;
    uint32_t *W1Fh, *W1Fl, *W2Fh, *W2Fl, *Wofh, *Wofl;
    float* bfb;
    int *deg, *ex, *bsum, *rpN, *adjN, *curN, *rpE, *adjE, *curE;
    cudaGetSymbolAddress((void**)&hA, g_hA);
    cudaGetSymbolAddress((void**)&hB, g_hB);
    cudaGetSymbolAddress((void**)&hC, g_hC);
    cudaGetSymbolAddress((void**)&hD, g_hD);
    cudaGetSymbolAddress((void**)&heA, g_heA);
    cudaGetSymbolAddress((void**)&heB, g_heB);
    cudaGetSymbolAddress((void**)&heC, g_heC);
    cudaGetSymbolAddress((void**)&bfb, g_bfb);
    cudaGetSymbolAddress((void**)&W1h, g_W1h);
    cudaGetSymbolAddress((void**)&W1l, g_W1l);
    cudaGetSymbolAddress((void**)&W2h, g_W2h);
    cudaGetSymbolAddress((void**)&W2l, g_W2l);
    cudaGetSymbolAddress((void**)&W1Fh, g_W1Fh);
    cudaGetSymbolAddress((void**)&W1Fl, g_W1Fl);
    cudaGetSymbolAddress((void**)&W2Fh, g_W2Fh);
    cudaGetSymbolAddress((void**)&W2Fl, g_W2Fl);
    cudaGetSymbolAddress((void**)&Wofh, g_Wofh);
    cudaGetSymbolAddress((void**)&Wofl, g_Wofl);
    cudaGetSymbolAddress((void**)&deg, g_deg);
    cudaGetSymbolAddress((void**)&ex, g_ex);
    cudaGetSymbolAddress((void**)&bsum, g_bsum);
    cudaGetSymbolAddress((void**)&rpN, g_rpN);
    cudaGetSymbolAddress((void**)&adjN, g_adjN);
    cudaGetSymbolAddress((void**)&curN, g_curN);
    cudaGetSymbolAddress((void**)&rpE, g_rpE);
    cudaGetSymbolAddress((void**)&adjE, g_adjE);
    cudaGetSymbolAddress((void**)&curE, g_curE);

    // ---- weight prep --------------------------------------------------------
    PrepArgs pa;
    const float* W1s[5]  = {init_W1, init_W1 + HD * HD, mlp_W1, gin_W1, gin_W1 + HD * HD};
    const float* b1s[5]  = {init_b1, init_b1 + HD, mlp_b1, gin_b1, gin_b1 + HD};
    const float* gs[5]   = {init_g, init_g + HD, mlp_g, gin_g, gin_g + HD};
    const float* bbs[5]  = {init_bb, init_bb + HD, mlp_bb, gin_bb, gin_bb + HD};
    const float* ms[5]   = {init_m, init_m + HD, mlp_m, gin_m, gin_m + HD};
    const float* vs[5]   = {init_v, init_v + HD, mlp_v, gin_v, gin_v + HD};
    const float* W2s[5]  = {init_W2, init_W2 + HD * HD, mlp_W2, gin_W2, gin_W2 + HD * HD};
    for (int j = 0; j < 5; ++j) {
        pa.W1[j] = W1s[j]; pa.b1[j] = b1s[j]; pa.g[j] = gs[j]; pa.bb[j] = bbs[j];
        pa.m[j] = ms[j]; pa.v[j] = vs[j]; pa.W2[j] = W2s[j];
        pa.W1h[j] = W1h + (size_t)j * HD * HD; pa.W1l[j] = W1l + (size_t)j * HD * HD;
        pa.W2h[j] = W2h + (size_t)j * HD * HD; pa.W2l[j] = W2l + (size_t)j * HD * HD;
        pa.bf[j] = bfb + j * HD;
    }
    pa.Wo = out_W; pa.Wofh = Wofh; pa.Wofl = Wofl;
    prep_weights<<<656, 256>>>(pa);

    FragArgs fa;
    for (int j = 0; j < 5; ++j) {
        fa.src[j]      = W1h + (size_t)j * HD * HD; fa.dst[j]      = W1Fh + (size_t)j * 8192;
        fa.src[5 + j]  = W1l + (size_t)j * HD * HD; fa.dst[5 + j]  = W1Fl + (size_t)j * 8192;
        fa.src[10 + j] = W2h + (size_t)j * HD * HD; fa.dst[10 + j] = W2Fh + (size_t)j * 8192;
        fa.src[15 + j] = W2l + (size_t)j * HD * HD; fa.dst[15 + j] = W2Fl + (size_t)j * 8192;
    }
    frag_all<<<640, 256>>>(fa);

    // ---- CSR build: node graph --------------------------------------------
    cudaMemsetAsync(deg, 0, NN * sizeof(int));
    count_deg<<<(EO + 255) / 256, 256>>>(ei_orig + EO, EO, deg);
    scan1<<<(NN + 4095) / 4096, 1024>>>(deg, ex, bsum, NN);
    scan2<<<1, 1024>>>(bsum, (NN + 4095) / 4096);
    scan3<<<(NN + 1024) / 1024 + 1, 1024>>>(ex, bsum, rpN, curN, NN, EO);
    fill_csr<<<(EO + 255) / 256, 256>>>(ei_orig, ei_orig + EO, EO, curN, adjN);

    // ---- CSR build: line graph --------------------------------------------
    cudaMemsetAsync(deg, 0, EO * sizeof(int));
    count_deg<<<(EL + 255) / 256, 256>>>(edge_index + EL, EL, deg);
    scan1<<<(EO + 4095) / 4096, 1024>>>(deg, ex, bsum, EO);
    scan2<<<1, 1024>>>(bsum, (EO + 4095) / 4096);
    scan3<<<(EO + 1024) / 1024 + 1, 1024>>>(ex, bsum, rpE, curE, EO, EL);
    fill_csr<<<(EL + 255) / 256, 256>>>(edge_index, edge_index + EL, EL, curE, adjE);

    // ---- main pipeline ------------------------------------------------------
    cudaFuncSetAttribute(fused_gin<false>,
                         cudaFuncAttributeMaxDynamicSharedMemorySize, SMEM_F);
    cudaFuncSetAttribute(fused_gin<true>,
                         cudaFuncAttributeMaxDynamicSharedMemorySize, SMEM_F);
    cudaFuncSetAttribute(fused_gin_mlp,
                         cudaFuncAttributeMaxDynamicSharedMemorySize, SMEM_F);

    const int GRID = 148;
    const int tilesN = (NN + 31) / 32;   // 3125
    const int tilesE = (EO + 31) / 32;   // 18750
    const int gaN = ((unsigned)NN * 32u + 255u) / 256u;
    const int gaE = ((unsigned)EO * 32u + 255u) / 256u;

    // node layer 0: agg(x_orig) -> hB (fp16); GEMM -> hA
    gather_agg_f<<<gaN, 256>>>(x_orig, rpN, adjN, hB, NN);
    fused_gin<false><<<GRID, 512, SMEM_F>>>(
        hB, (const uint4*)W1Fh, (const uint4*)W1Fl,
        (const uint4*)W2Fh, (const uint4*)W2Fl, nullptr, nullptr,
        bfb, init_b2, nullptr, hA, nullptr, NN, tilesN);

    // node layer 1 + MLP: agg(hA) -> hC; 4-pass GEMM -> hD
    gather_agg_h<<<gaN, 256>>>(hA, rpN, adjN, hC, NN);
    fused_gin_mlp<<<GRID, 512, SMEM_F>>>(
        hC,
        (const uint4*)(W1Fh + 8192), (const uint4*)(W1Fl + 8192),
        (const uint4*)(W2Fh + 8192), (const uint4*)(W2Fl + 8192),
        (const uint4*)(W1Fh + 2 * 8192), (const uint4*)(W1Fl + 2 * 8192),
        (const uint4*)(W2Fh + 2 * 8192), (const uint4*)(W2Fl + 2 * 8192),
        bfb + HD, init_b2 + HD, bfb + 2 * HD, mlp_b2, hD, NN, tilesN);

    // edge layer 0: fused pair-lift + agg (hD L2-resident) -> heB; GEMM -> heC
    pair_agg_h<<<gaE, 256>>>(edge_pairs, hD, rpE, adjE, heB, EO);
    fused_gin<false><<<GRID, 512, SMEM_F>>>(
        heB, (const uint4*)(W1Fh + 3 * 8192), (const uint4*)(W1Fl + 3 * 8192),
        (const uint4*)(W2Fh + 3 * 8192), (const uint4*)(W2Fl + 3 * 8192),
        nullptr, nullptr, bfb + 3 * HD, gin_b2, nullptr, heC, nullptr, EO, tilesE);

    // edge layer 1 + head: agg(heC) -> heA; GEMM+head -> out (f32)
    gather_agg_h<<<gaE, 256>>>(heC, rpE, adjE, heA, EO);
    fused_gin<true><<<GRID, 512, SMEM_F>>>(
        heA, (const uint4*)(W1Fh + 4 * 8192), (const uint4*)(W1Fl + 4 * 8192),
        (const uint4*)(W2Fh + 4 * 8192), (const uint4*)(W2Fl + 4 * 8192),
        (const uint4*)Wofh, (const uint4*)Wofl,
        bfb + 4 * HD, gin_b2 + HD, out_b, nullptr, out, EO, tilesE);
}

// round 14
// speedup vs baseline: 3.0947x; 1.2833x over previous
#include <cuda_runtime.h>
#include <cuda_fp16.h>
#include <cstdint>

#define NN 100000
#define EO 600000
#define EL 1200000
#define HD 128
#define OD 64
#define SA 136   // smem row stride (fp16 elems); 272B rows, 16B aligned

// ---------------- scratch (device globals) ---------------------------------
static __device__ __half g_hA[(size_t)NN * HD];
static __device__ __half g_hB[(size_t)NN * HD];
static __device__ __half g_hC[(size_t)NN * HD];
static __device__ __half g_hD[(size_t)NN * HD];
static __device__ __half g_heA[(size_t)EO * HD];
static __device__ __half g_heB[(size_t)EO * HD];
static __device__ __half g_heC[(size_t)EO * HD];
static __device__ __half g_W1h[5][HD * HD];          // n-major fp16 images
static __device__ __half g_W2h[5][HD * HD];
static __device__ uint32_t g_W1F[5][8192];           // W1 frags (N=128)
static __device__ uint32_t g_W2F[5][8192];           // W2 frags (N=128)
static __device__ uint32_t g_Wofh[4096], g_Wofl[4096];  // Wo frags hi+lo (N=64)
static __device__ float g_bfb[5][HD];
// CSR scratch
static __device__ int g_deg[EO], g_ex[EO], g_bsum[1024];
static __device__ int g_rpN[NN + 1], g_adjN[EO], g_curN[NN];
static __device__ int g_rpE[EO + 1], g_adjE[EL], g_curE[EO];

// ---------------- PTX helpers ----------------------------------------------
__device__ __forceinline__ void ldsm4(uint32_t* r, const void* p) {
    uint32_t a = (uint32_t)__cvta_generic_to_shared(p);
    asm volatile("ldmatrix.sync.aligned.m8n8.x4.shared.b16 {%0,%1,%2,%3}, [%4];"
                 : "=r"(r[0]), "=r"(r[1]), "=r"(r[2]), "=r"(r[3]) : "r"(a));
}
__device__ __forceinline__ void stsm4(void* p, uint32_t r0, uint32_t r1,
                                      uint32_t r2, uint32_t r3) {
    uint32_t a = (uint32_t)__cvta_generic_to_shared(p);
    asm volatile("stmatrix.sync.aligned.m8n8.x4.shared.b16 [%0], {%1,%2,%3,%4};"
                 :: "r"(a), "r"(r0), "r"(r1), "r"(r2), "r"(r3) : "memory");
}
__device__ __forceinline__ void mma_f16(float* d, const uint32_t* a,
                                        uint32_t b0, uint32_t b1) {
    asm volatile(
        "mma.sync.aligned.m16n8k16.row.col.f32.f16.f16.f32 "
        "{%0,%1,%2,%3}, {%4,%5,%6,%7}, {%8,%9}, {%0,%1,%2,%3};"
        : "+f"(d[0]), "+f"(d[1]), "+f"(d[2]), "+f"(d[3])
        : "r"(a[0]), "r"(a[1]), "r"(a[2]), "r"(a[3]), "r"(b0), "r"(b1));
}
__device__ __forceinline__ void cp16(void* sdst, const void* gsrc) {
    uint32_t a = (uint32_t)__cvta_generic_to_shared(sdst);
    asm volatile("cp.async.cg.shared.global [%0], [%1], 16;"
                 :: "r"(a), "l"(gsrc) : "memory");
}
#define CP_COMMIT() asm volatile("cp.async.commit_group;" ::: "memory")
#define CP_WAIT0()  asm volatile("cp.async.wait_group 0;" ::: "memory")

__device__ __forceinline__ uint32_t packh(float a, float b) {
    __half2 t = __floats2half2_rn(a, b);
    return *(uint32_t*)&t;
}
__device__ __forceinline__ void unpackh(uint32_t v, float& a, float& b) {
    __half2 t = *(__half2*)&v;
    a = __half2float(__low2half(t));
    b = __half2float(__high2half(t));
}
#define BARQ(id) asm volatile("bar.sync %0, 128;" :: "r"(id) : "memory")

// ---------------- GEMM pass: A fp16 from smem, W single-fp16 frags ----------
__device__ __forceinline__ void gemm_pass_frag(
    const __half* As, const uint4* __restrict__ F,
    int cc, int lrow, int lkoff, int lane, float (&acc)[2][4][4]) {
#pragma unroll
    for (int mi = 0; mi < 2; ++mi)
#pragma unroll
        for (int ni = 0; ni < 4; ++ni)
#pragma unroll
            for (int q = 0; q < 4; ++q) acc[mi][ni][q] = 0.f;
#pragma unroll
    for (int ks = 0; ks < 8; ++ks) {
        const int k0 = ks * 16 + lkoff;
        uint32_t ah[2][4];
#pragma unroll
        for (int mi = 0; mi < 2; ++mi)
            ldsm4(ah[mi], As + (mi * 16 + lrow) * SA + k0);
#pragma unroll
        for (int nj = 0; nj < 2; ++nj) {
            const uint4 b = F[((cc * 2 + nj) * 8 + ks) * 32 + lane];
#pragma unroll
            for (int mi = 0; mi < 2; ++mi) {
                const int n0 = nj * 2;
                mma_f16(acc[mi][n0], ah[mi], b.x, b.z);
                mma_f16(acc[mi][n0 + 1], ah[mi], b.y, b.w);
            }
        }
    }
}

// bias+relu then stmatrix back into As (quarter rows 0..31)
__device__ __forceinline__ void epi_to_smem(
    const float (&acc)[2][4][4], const float (&br)[4][2],
    __half* As, int colBase, int lane) {
    const int srow = (lane & 7) + ((lane >> 3) & 1) * 8;
    const int scol = (lane >> 4) * 8;
#pragma unroll
    for (int mi = 0; mi < 2; ++mi) {
#pragma unroll
        for (int ng = 0; ng < 2; ++ng) {
            float v[2][4];
#pragma unroll
            for (int q = 0; q < 2; ++q) {
                const int ni = ng * 2 + q;
                v[q][0] = fmaxf(acc[mi][ni][0] + br[ni][0], 0.f);
                v[q][1] = fmaxf(acc[mi][ni][1] + br[ni][1], 0.f);
                v[q][2] = fmaxf(acc[mi][ni][2] + br[ni][0], 0.f);
                v[q][3] = fmaxf(acc[mi][ni][3] + br[ni][1], 0.f);
            }
            const int off = (mi * 16 + srow) * SA + colBase + ng * 16 + scol;
            stsm4(As + off, packh(v[0][0], v[0][1]), packh(v[0][2], v[0][3]),
                  packh(v[1][0], v[1][1]), packh(v[1][2], v[1][3]));
        }
    }
}

// gmem write: acc + bias + relu -> C [M,HD] as fp16
__device__ __forceinline__ void write_outh(
    const float (&acc)[2][4][4], const float (&br)[4][2],
    __half* __restrict__ C, int m0, int colBase, int cq, int rq, int M) {
#pragma unroll
    for (int mi = 0; mi < 2; ++mi)
#pragma unroll
        for (int ni = 0; ni < 4; ++ni) {
            const int col = colBase + ni * 8 + cq;
            const int r0 = m0 + mi * 16 + rq, r1 = r0 + 8;
            float v00 = fmaxf(acc[mi][ni][0] + br[ni][0], 0.f);
            float v01 = fmaxf(acc[mi][ni][1] + br[ni][1], 0.f);
            float v10 = fmaxf(acc[mi][ni][2] + br[ni][0], 0.f);
            float v11 = fmaxf(acc[mi][ni][3] + br[ni][1], 0.f);
            if (r0 < M) *(uint32_t*)(C + (size_t)r0 * HD + col) = packh(v00, v01);
            if (r1 < M) *(uint32_t*)(C + (size_t)r1 * HD + col) = packh(v10, v11);
        }
}

// smem: per quarter: two ping-pong As buffers (8704 B each) = 17408; x4
#define QSZ    17408
#define SMEM_F 69632

// cp.async a 32-row fp16 tile straight into ldsm layout (row*SA)
__device__ __forceinline__ void issue_cp_tileh(const __half* __restrict__ A,
                                               __half* Asdst, int tile, int M,
                                               int tiq) {
#pragma unroll
    for (int qq = 0; qq < 4; ++qq) {
        const int i = tiq + 128 * qq;         // 0..511
        const int r = i >> 4, c = i & 15;     // 16 x 16B chunks per 256B row
        const int grow = tile * 32 + r;
        __half* dst = Asdst + r * SA + c * 8;
        if (grow < M)
            cp16(dst, A + (size_t)grow * HD + c * 8);
        else
            *(uint4*)dst = make_uint4(0, 0, 0, 0);
    }
}

// ---------------- fused GIN layer: 4 independent quarter-pipelines ----------
// HEAD=false: out fp16 [M,HD]; HEAD=true: third GEMM vs Wo (hi+lo), out f32
template <bool HEAD>
__global__ __launch_bounds__(512, 1) void fused_gin(
    const __half* __restrict__ A,
    const uint4* __restrict__ W1F, const uint4* __restrict__ W2F,
    const uint4* __restrict__ WoFh, const uint4* __restrict__ WoFl,
    const float* __restrict__ b1, const float* __restrict__ b2,
    const float* __restrict__ b3,
    __half* __restrict__ C, float* __restrict__ Cf, int M, int nTiles) {
    extern __shared__ char smem[];
    const int tid = threadIdx.x, lane = tid & 31, wid = tid >> 5;
    const int q = wid >> 2, cc = wid & 3, tiq = tid & 127;

    __half* As0 = (__half*)(smem + q * QSZ);
    __half* As1 = As0 + 32 * SA;

    const int barid = 1 + q;
    const int colBase = cc * 32;
    const int lrow = lane & 15, lkoff = (lane >> 4) * 8;
    const int cq = (lane & 3) * 2, rq = lane >> 2;

    float b1r[4][2], b2r[4][2], b3r[2][2];
#pragma unroll
    for (int ni = 0; ni < 4; ++ni) {
        const int col = colBase + ni * 8 + cq;
        b1r[ni][0] = b1[col]; b1r[ni][1] = b1[col + 1];
        b2r[ni][0] = b2[col]; b2r[ni][1] = b2[col + 1];
    }
    if (HEAD) {
#pragma unroll
        for (int ni = 0; ni < 2; ++ni) {
            const int col = cc * 16 + ni * 8 + cq;
            b3r[ni][0] = b3[col]; b3r[ni][1] = b3[col + 1];
        }
    }

    int tile = blockIdx.x * 4 + q;
    int pb = 0;
    if (tile < nTiles) issue_cp_tileh(A, As0, tile, M, tiq);
    CP_COMMIT();

    for (; tile < nTiles; tile += gridDim.x * 4) {
        const int m0 = tile * 32;
        __half* Asb = pb ? As1 : As0;
        __half* Aso = pb ? As0 : As1;
        CP_WAIT0();
        BARQ(barid);   // this tile's A landed; previous iteration fully done

        const int nxt = tile + gridDim.x * 4;
        if (nxt < nTiles) issue_cp_tileh(A, Aso, nxt, M, tiq);
        CP_COMMIT();

        float acc[2][4][4];
        gemm_pass_frag(Asb, W1F, cc, lrow, lkoff, lane, acc);
        BARQ(barid);
        epi_to_smem(acc, b1r, Asb, colBase, lane);
        BARQ(barid);
        gemm_pass_frag(Asb, W2F, cc, lrow, lkoff, lane, acc);

        if (!HEAD) {
            write_outh(acc, b2r, C, m0, colBase, cq, rq, M);
        } else {
            BARQ(barid);
            epi_to_smem(acc, b2r, Asb, colBase, lane);
            BARQ(barid);
            float acc3[2][2][4];
#pragma unroll
            for (int mi = 0; mi < 2; ++mi)
#pragma unroll
                for (int ni = 0; ni < 2; ++ni)
#pragma unroll
                    for (int p = 0; p < 4; ++p) acc3[mi][ni][p] = 0.f;
#pragma unroll
            for (int ks = 0; ks < 8; ++ks) {
                const int k0 = ks * 16 + lkoff;
                uint32_t ah[2][4];
#pragma unroll
                for (int mi = 0; mi < 2; ++mi)
                    ldsm4(ah[mi], Asb + (mi * 16 + lrow) * SA + k0);
                const uint4 bh = WoFh[(cc * 8 + ks) * 32 + lane];
                const uint4 bl = WoFl[(cc * 8 + ks) * 32 + lane];
#pragma unroll
                for (int mi = 0; mi < 2; ++mi) {
                    mma_f16(acc3[mi][0], ah[mi], bh.x, bh.z);
                    mma_f16(acc3[mi][0], ah[mi], bl.x, bl.z);
                    mma_f16(acc3[mi][1], ah[mi], bh.y, bh.w);
                    mma_f16(acc3[mi][1], ah[mi], bl.y, bl.w);
                }
            }
#pragma unroll
            for (int mi = 0; mi < 2; ++mi)
#pragma unroll
                for (int ni = 0; ni < 2; ++ni) {
                    const int col = cc * 16 + ni * 8 + cq;
                    const int r0 = m0 + mi * 16 + rq, r1 = r0 + 8;
                    if (r0 < M)
                        *(float2*)(Cf + (size_t)r0 * OD + col) = make_float2(
                            acc3[mi][ni][0] + b3r[ni][0], acc3[mi][ni][1] + b3r[ni][1]);
                    if (r1 < M)
                        *(float2*)(Cf + (size_t)r1 * OD + col) = make_float2(
                            acc3[mi][ni][2] + b3r[ni][0], acc3[mi][ni][3] + b3r[ni][1]);
                }
        }
        pb ^= 1;
    }
}

// ---------------- fused node layer 1 + MLP (4 passes) ----------------------
__global__ __launch_bounds__(512, 1) void fused_gin_mlp(
    const __half* __restrict__ A,
    const uint4* __restrict__ WaF, const uint4* __restrict__ WbF,
    const uint4* __restrict__ WcF, const uint4* __restrict__ WdF,
    const float* __restrict__ b1, const float* __restrict__ b2,
    const float* __restrict__ b3, const float* __restrict__ b4,
    __half* __restrict__ C, int M, int nTiles) {
    extern __shared__ char smem[];
    const int tid = threadIdx.x, lane = tid & 31, wid = tid >> 5;
    const int q = wid >> 2, cc = wid & 3, tiq = tid & 127;

    __half* As0 = (__half*)(smem + q * QSZ);
    __half* As1 = As0 + 32 * SA;

    const int barid = 1 + q;
    const int colBase = cc * 32;
    const int lrow = lane & 15, lkoff = (lane >> 4) * 8;
    const int cq = (lane & 3) * 2, rq = lane >> 2;

    float b1r[4][2], b2r[4][2], b3r[4][2], b4r[4][2];
#pragma unroll
    for (int ni = 0; ni < 4; ++ni) {
        const int col = colBase + ni * 8 + cq;
        b1r[ni][0] = b1[col]; b1r[ni][1] = b1[col + 1];
        b2r[ni][0] = b2[col]; b2r[ni][1] = b2[col + 1];
        b3r[ni][0] = b3[col]; b3r[ni][1] = b3[col + 1];
        b4r[ni][0] = b4[col]; b4r[ni][1] = b4[col + 1];
    }

    int tile = blockIdx.x * 4 + q;
    int pb = 0;
    if (tile < nTiles) issue_cp_tileh(A, As0, tile, M, tiq);
    CP_COMMIT();

    for (; tile < nTiles; tile += gridDim.x * 4) {
        const int m0 = tile * 32;
        __half* Asb = pb ? As1 : As0;
        __half* Aso = pb ? As0 : As1;
        CP_WAIT0();
        BARQ(barid);

        const int nxt = tile + gridDim.x * 4;
        if (nxt < nTiles) issue_cp_tileh(A, Aso, nxt, M, tiq);
        CP_COMMIT();

        float acc[2][4][4];
        gemm_pass_frag(Asb, WaF, cc, lrow, lkoff, lane, acc);
        BARQ(barid);
        epi_to_smem(acc, b1r, Asb, colBase, lane);
        BARQ(barid);
        gemm_pass_frag(Asb, WbF, cc, lrow, lkoff, lane, acc);
        BARQ(barid);
        epi_to_smem(acc, b2r, Asb, colBase, lane);   // layer out (relu)
        BARQ(barid);
        gemm_pass_frag(Asb, WcF, cc, lrow, lkoff, lane, acc);
        BARQ(barid);
        epi_to_smem(acc, b3r, Asb, colBase, lane);   // mlp hidden (relu)
        BARQ(barid);
        gemm_pass_frag(Asb, WdF, cc, lrow, lkoff, lane, acc);
        // mlp out (no relu) -> fp16
#pragma unroll
        for (int mi = 0; mi < 2; ++mi)
#pragma unroll
            for (int ni = 0; ni < 4; ++ni) {
                const int col = colBase + ni * 8 + cq;
                const int r0 = m0 + mi * 16 + rq, r1 = r0 + 8;
                if (r0 < M)
                    *(uint32_t*)(C + (size_t)r0 * HD + col) =
                        packh(acc[mi][ni][0] + b4r[ni][0], acc[mi][ni][1] + b4r[ni][1]);
                if (r1 < M)
                    *(uint32_t*)(C + (size_t)r1 * HD + col) =
                        packh(acc[mi][ni][2] + b4r[ni][0], acc[mi][ni][3] + b4r[ni][1]);
            }
        pb ^= 1;
    }
}

// ---------------- weight prep ------------------------------------------------
struct PrepArgs {
    const float *W1[5], *b1[5], *g[5], *bb[5], *m[5], *v[5], *W2[5], *Wo;
    __half *W1h[5], *W2h[5];
    uint32_t *Wofh, *Wofl;
    float* bf[5];
};

__global__ void prep_weights(PrepArgs a) {
    const int blk = blockIdx.x, tid = threadIdx.x;
    if (blk < 320) {
        const int j = blk >> 6;
        const int idx = ((blk & 63) << 8) + tid;
        const int k = idx >> 7, n = idx & 127;
        float s = a.g[j][n] * rsqrtf(a.v[j][n] + 1e-5f);
        a.W1h[j][n * 128 + k] = __float2half(a.W1[j][idx] * s);
        if (idx < 128)
            a.bf[j][idx] = a.b1[j][idx] * s + a.bb[j][idx] - a.m[j][idx] * s;
    } else if (blk < 640) {
        const int j = (blk - 320) >> 6;
        const int idx = (((blk - 320) & 63) << 8) + tid;
        const int k = idx >> 7, n = idx & 127;
        a.W2h[j][n * 128 + k] = __float2half(a.W2[j][idx]);
    } else {
        const int idx = ((blk - 640) << 8) + tid;  // 0..4095 (Wo frags hi+lo)
        const int j = idx & 3, L = (idx >> 2) & 31;
        const int ks = (idx >> 7) & 7, cc = idx >> 10;
        const int n = cc * 16 + (j & 1) * 8 + (L >> 2);
        const int k = ks * 16 + ((j >> 1)) * 8 + (L & 3) * 2;
        float v0 = a.Wo[k * OD + n];
        float v1 = a.Wo[(k + 1) * OD + n];
        __half h0 = __float2half(v0), h1 = __float2half(v1);
        __half l0 = __float2half(v0 - __half2float(h0));
        __half l1 = __float2half(v1 - __half2float(h1));
        __half2 th = __halves2half2(h0, h1), tl = __halves2half2(l0, l1);
        a.Wofh[((cc * 8 + ks) * 32 + L) * 4 + j] = *(uint32_t*)&th;
        a.Wofl[((cc * 8 + ks) * 32 + L) * 4 + j] = *(uint32_t*)&tl;
    }
}

struct FragArgs {
    const __half* src[10];
    uint32_t* dst[10];
};
__global__ void frag_all(FragArgs a) {
    const int i = blockIdx.x * 256 + threadIdx.x;   // 0..81919
    const int m = i >> 13, e = i & 8191;
    const int j = e & 3, L = (e >> 2) & 31;
    const int ks = (e >> 7) & 7, g = e >> 10;
    const int n = g * 16 + (j & 1) * 8 + (L >> 2);
    const int k = ks * 16 + (j >> 1) * 8 + (L & 3) * 2;
    a.dst[m][e] = *(const uint32_t*)(a.src[m] + n * 128 + k);
}

// ---------------- CSR build ----------------------------------------------------
__global__ void count_deg(const int* __restrict__ dst, int E, int* __restrict__ deg) {
    int e = blockIdx.x * 256 + threadIdx.x;
    if (e < E) atomicAdd(&deg[dst[e]], 1);
}

__global__ void scan1(const int* __restrict__ deg, int* __restrict__ ex,
                      int* __restrict__ bsum, int n) {
    __shared__ int wsum[32];
    const int t = threadIdx.x;
    const int base = blockIdx.x * 4096 + t * 4;
    int v[4], s = 0;
#pragma unroll
    for (int i = 0; i < 4; ++i) {
        int idx = base + i;
        v[i] = idx < n ? deg[idx] : 0;
        s += v[i];
    }
    const int lane = t & 31, w = t >> 5;
    int ps = s;
#pragma unroll
    for (int o = 1; o < 32; o <<= 1) {
        int y = __shfl_up_sync(~0u, ps, o);
        if (lane >= o) ps += y;
    }
    if (lane == 31) wsum[w] = ps;
    __syncthreads();
    if (w == 0) {
        int x = wsum[lane];
#pragma unroll
        for (int o = 1; o < 32; o <<= 1) {
            int y = __shfl_up_sync(~0u, x, o);
            if (lane >= o) x += y;
        }
        wsum[lane] = x;
    }
    __syncthreads();
    const int warpoff = w ? wsum[w - 1] : 0;
    int run = warpoff + ps - s;
#pragma unroll
    for (int i = 0; i < 4; ++i) {
        int idx = base + i;
        if (idx < n) ex[idx] = run;
        run += v[i];
    }
    if (t == 0) bsum[blockIdx.x] = wsum[31];
}

__global__ void scan2(int* __restrict__ bsum, int nb) {
    __shared__ int sm_[1024];
    const int t = threadIdx.x;
    int v = (t < nb) ? bsum[t] : 0;
    sm_[t] = v;
    __syncthreads();
    for (int o = 1; o < 1024; o <<= 1) {
        int y = (t >= o) ? sm_[t - o] : 0;
        __syncthreads();
        sm_[t] += y;
        __syncthreads();
    }
    if (t < nb) bsum[t] = sm_[t] - v;
}

__global__ void scan3(const int* __restrict__ ex, const int* __restrict__ boff,
                      int* __restrict__ rp, int* __restrict__ cur, int n, int E) {
    int i = blockIdx.x * 1024 + threadIdx.x;
    if (i < n) {
        int vv = ex[i] + boff[i >> 12];
        rp[i] = vv;
        cur[i] = vv;
    } else if (i == n) {
        rp[n] = E;
    }
}

__global__ void fill_csr(const int* __restrict__ src, const int* __restrict__ dst,
                         int E, int* __restrict__ cur, int* __restrict__ adj) {
    int e = blockIdx.x * 256 + threadIdx.x;
    if (e < E) {
        int p = atomicAdd(&cur[dst[e]], 1);
        adj[p] = src[e];
    }
}

// ---------------- gather aggregation (fp16 rows, f32 accumulate) --------------
__device__ __forceinline__ void addrow_h(const __half* __restrict__ x, int row,
                                         int lane, float (&acc)[4]) {
    uint2 u = *(const uint2*)(x + (size_t)row * HD + lane * 4);
    float a0, a1, a2, a3;
    unpackh(u.x, a0, a1);
    unpackh(u.y, a2, a3);
    acc[0] += a0; acc[1] += a1; acc[2] += a2; acc[3] += a3;
}

// first layer: x f32, out fp16
__global__ void gather_agg_f(const float* __restrict__ x,
                             const int* __restrict__ rp,
                             const int* __restrict__ adj,
                             __half* __restrict__ agg, int n) {
    unsigned t = blockIdx.x * 256u + threadIdx.x;
    unsigned r = t >> 5, lane = t & 31u;
    if (r >= (unsigned)n) return;
    const int s = rp[r], e = rp[r + 1];
    float4 acc = ((const float4*)(x + (size_t)r * HD))[lane];
    const int cnt = e - s;
    int nb_l = ((int)lane < cnt) ? adj[s + lane] : 0;
    const int lim = cnt < 32 ? cnt : 32;
    for (int j = 0; j < lim; ++j) {
        const int nb = __shfl_sync(~0u, nb_l, j);
        float4 u = ((const float4*)(x + (size_t)nb * HD))[lane];
        acc.x += u.x; acc.y += u.y; acc.z += u.z; acc.w += u.w;
    }
    for (int j = s + 32; j < e; ++j) {
        const int nb = adj[j];
        float4 u = ((const float4*)(x + (size_t)nb * HD))[lane];
        acc.x += u.x; acc.y += u.y; acc.z += u.z; acc.w += u.w;
    }
    *(uint2*)(agg + (size_t)r * HD + lane * 4) =
        make_uint2(packh(acc.x, acc.y), packh(acc.z, acc.w));
}

// fp16 in, fp16 out
__global__ void gather_agg_h(const __half* __restrict__ x,
                             const int* __restrict__ rp,
                             const int* __restrict__ adj,
                             __half* __restrict__ agg, int n) {
    unsigned t = blockIdx.x * 256u + threadIdx.x;
    unsigned r = t >> 5, lane = t & 31u;
    if (r >= (unsigned)n) return;
    const int s = rp[r], e = rp[r + 1];
    float acc[4] = {0.f, 0.f, 0.f, 0.f};
    addrow_h(x, r, lane, acc);
    const int cnt = e - s;
    int nb_l = ((int)lane < cnt) ? adj[s + lane] : 0;
    const int lim = cnt < 32 ? cnt : 32;
    for (int j = 0; j < lim; ++j) {
        const int nb = __shfl_sync(~0u, nb_l, j);
        addrow_h(x, nb, lane, acc);
    }
    for (int j = s + 32; j < e; ++j) addrow_h(x, adj[j], lane, acc);
    *(uint2*)(agg + (size_t)r * HD + lane * 4) =
        make_uint2(packh(acc[0], acc[1]), packh(acc[2], acc[3]));
}

// fused pair lift + aggregation (fp16 y, L2-resident)
__global__ void pair_agg_h(const int* __restrict__ ep,
                           const __half* __restrict__ y,
                           const int* __restrict__ rp,
                           const int* __restrict__ adj,
                           __half* __restrict__ agg, int n) {
    unsigned t = blockIdx.x * 256u + threadIdx.x;
    unsigned r = t >> 5, lane = t & 31u;
    if (r >= (unsigned)n) return;
    const int s = rp[r], e = rp[r + 1];
    const int cnt = e - s;
    float acc[4] = {0.f, 0.f, 0.f, 0.f};
    addrow_h(y, ep[2 * r], lane, acc);
    addrow_h(y, ep[2 * r + 1], lane, acc);
    int p0_l = 0, p1_l = 0;
    if ((int)lane < cnt) {
        const int nb = adj[s + lane];
        p0_l = ep[2 * nb];
        p1_l = ep[2 * nb + 1];
    }
    const int lim = cnt < 32 ? cnt : 32;
    for (int j = 0; j < lim; ++j) {
        addrow_h(y, __shfl_sync(~0u, p0_l, j), lane, acc);
        addrow_h(y, __shfl_sync(~0u, p1_l, j), lane, acc);
    }
    for (int j = s + 32; j < e; ++j) {
        const int nb = adj[j];
        addrow_h(y, ep[2 * nb], lane, acc);
        addrow_h(y, ep[2 * nb + 1], lane, acc);
    }
    *(uint2*)(agg + (size_t)r * HD + lane * 4) =
        make_uint2(packh(acc[0], acc[1]), packh(acc[2], acc[3]));
}

// ----------------------------------------------------------------------------------
extern "C" void kernel_launch(void* const* d_in, const int* in_sizes, int n_in,
                              void* d_out, int out_size) {
    const int*   edge_index = (const int*)d_in[0];
    const float* x_orig     = (const float*)d_in[1];
    const int*   ei_orig    = (const int*)d_in[2];
    const int*   edge_pairs = (const int*)d_in[3];
    const float* init_W1 = (const float*)d_in[4];
    const float* init_b1 = (const float*)d_in[5];
    const float* init_g  = (const float*)d_in[6];
    const float* init_bb = (const float*)d_in[7];
    const float* init_m  = (const float*)d_in[8];
    const float* init_v  = (const float*)d_in[9];
    const float* init_W2 = (const float*)d_in[10];
    const float* init_b2 = (const float*)d_in[11];
    const float* gin_W1  = (const float*)d_in[12];
    const float* gin_b1  = (const float*)d_in[13];
    const float* gin_g   = (const float*)d_in[14];
    const float* gin_bb  = (const float*)d_in[15];
    const float* gin_m   = (const float*)d_in[16];
    const float* gin_v   = (const float*)d_in[17];
    const float* gin_W2  = (const float*)d_in[18];
    const float* gin_b2  = (const float*)d_in[19];
    const float* mlp_W1  = (const float*)d_in[20];
    const float* mlp_b1  = (const float*)d_in[21];
    const float* mlp_g   = (const float*)d_in[22];
    const float* mlp_bb  = (const float*)d_in[23];
    const float* mlp_m   = (const float*)d_in[24];
    const float* mlp_v   = (const float*)d_in[25];
    const float* mlp_W2  = (const float*)d_in[26];
    const float* mlp_b2  = (const float*)d_in[27];
    const float* out_W   = (const float*)d_in[28];
    const float* out_b   = (const float*)d_in[29];
    float* out = (float*)d_out;

    __half *hA, *hB, *hC, *hD, *heA, *heB, *heC;
    __half *W1h, *W2h;
    uint32_t *W1F, *W2F, *Wofh, *Wofl;
    float* bfb;
    int *deg, *ex, *bsum, *rpN, *adjN, *curN, *rpE, *adjE, *curE;
    cudaGetSymbolAddress((void**)&hA, g_hA);
    cudaGetSymbolAddress((void**)&hB, g_hB);
    cudaGetSymbolAddress((void**)&hC, g_hC);
    cudaGetSymbolAddress((void**)&hD, g_hD);
    cudaGetSymbolAddress((void**)&heA, g_heA);
    cudaGetSymbolAddress((void**)&heB, g_heB);
    cudaGetSymbolAddress((void**)&heC, g_heC);
    cudaGetSymbolAddress((void**)&bfb, g_bfb);
    cudaGetSymbolAddress((void**)&W1h, g_W1h);
    cudaGetSymbolAddress((void**)&W2h, g_W2h);
    cudaGetSymbolAddress((void**)&W1F, g_W1F);
    cudaGetSymbolAddress((void**)&W2F, g_W2F);
    cudaGetSymbolAddress((void**)&Wofh, g_Wofh);
    cudaGetSymbolAddress((void**)&Wofl, g_Wofl);
    cudaGetSymbolAddress((void**)&deg, g_deg);
    cudaGetSymbolAddress((void**)&ex, g_ex);
    cudaGetSymbolAddress((void**)&bsum, g_bsum);
    cudaGetSymbolAddress((void**)&rpN, g_rpN);
    cudaGetSymbolAddress((void**)&adjN, g_adjN);
    cudaGetSymbolAddress((void**)&curN, g_curN);
    cudaGetSymbolAddress((void**)&rpE, g_rpE);
    cudaGetSymbolAddress((void**)&adjE, g_adjE);
    cudaGetSymbolAddress((void**)&curE, g_curE);

    // ---- weight prep --------------------------------------------------------
    PrepArgs pa;
    const float* W1s[5]  = {init_W1, init_W1 + HD * HD, mlp_W1, gin_W1, gin_W1 + HD * HD};
    const float* b1s[5]  = {init_b1, init_b1 + HD, mlp_b1, gin_b1, gin_b1 + HD};
    const float* gs[5]   = {init_g, init_g + HD, mlp_g, gin_g, gin_g + HD};
    const float* bbs[5]  = {init_bb, init_bb + HD, mlp_bb, gin_bb, gin_bb + HD};
    const float* ms[5]   = {init_m, init_m + HD, mlp_m, gin_m, gin_m + HD};
    const float* vs[5]   = {init_v, init_v + HD, mlp_v, gin_v, gin_v + HD};
    const float* W2s[5]  = {init_W2, init_W2 + HD * HD, mlp_W2, gin_W2, gin_W2 + HD * HD};
    for (int j = 0; j < 5; ++j) {
        pa.W1[j] = W1s[j]; pa.b1[j] = b1s[j]; pa.g[j] = gs[j]; pa.bb[j] = bbs[j];
        pa.m[j] = ms[j]; pa.v[j] = vs[j]; pa.W2[j] = W2s[j];
        pa.W1h[j] = W1h + (size_t)j * HD * HD;
        pa.W2h[j] = W2h + (size_t)j * HD * HD;
        pa.bf[j] = bfb + j * HD;
    }
    pa.Wo = out_W; pa.Wofh = Wofh; pa.Wofl = Wofl;
    prep_weights<<<656, 256>>>(pa);

    FragArgs fa;
    for (int j = 0; j < 5; ++j) {
        fa.src[j]     = W1h + (size_t)j * HD * HD; fa.dst[j]     = W1F + (size_t)j * 8192;
        fa.src[5 + j] = W2h + (size_t)j * HD * HD; fa.dst[5 + j] = W2F + (size_t)j * 8192;
    }
    frag_all<<<320, 256>>>(fa);

    // ---- CSR build: node graph --------------------------------------------
    cudaMemsetAsync(deg, 0, NN * sizeof(int));
    count_deg<<<(EO + 255) / 256, 256>>>(ei_orig + EO, EO, deg);
    scan1<<<(NN + 4095) / 4096, 1024>>>(deg, ex, bsum, NN);
    scan2<<<1, 1024>>>(bsum, (NN + 4095) / 4096);
    scan3<<<(NN + 1024) / 1024 + 1, 1024>>>(ex, bsum, rpN, curN, NN, EO);
    fill_csr<<<(EO + 255) / 256, 256>>>(ei_orig, ei_orig + EO, EO, curN, adjN);

    // ---- CSR build: line graph --------------------------------------------
    cudaMemsetAsync(deg, 0, EO * sizeof(int));
    count_deg<<<(EL + 255) / 256, 256>>>(edge_index + EL, EL, deg);
    scan1<<<(EO + 4095) / 4096, 1024>>>(deg, ex, bsum, EO);
    scan2<<<1, 1024>>>(bsum, (EO + 4095) / 4096);
    scan3<<<(EO + 1024) / 1024 + 1, 1024>>>(ex, bsum, rpE, curE, EO, EL);
    fill_csr<<<(EL + 255) / 256, 256>>>(edge_index, edge_index + EL, EL, curE, adjE);

    // ---- main pipeline ------------------------------------------------------
    cudaFuncSetAttribute(fused_gin<false>,
                         cudaFuncAttributeMaxDynamicSharedMemorySize, SMEM_F);
    cudaFuncSetAttribute(fused_gin<true>,
                         cudaFuncAttributeMaxDynamicSharedMemorySize, SMEM_F);
    cudaFuncSetAttribute(fused_gin_mlp,
                         cudaFuncAttributeMaxDynamicSharedMemorySize, SMEM_F);

    const int GRID = 148;
    const int tilesN = (NN + 31) / 32;   // 3125
    const int tilesE = (EO + 31) / 32;   // 18750
    const int gaN = ((unsigned)NN * 32u + 255u) / 256u;
    const int gaE = ((unsigned)EO * 32u + 255u) / 256u;

    // node layer 0: agg(x_orig) -> hB (fp16); GEMM -> hA
    gather_agg_f<<<gaN, 256>>>(x_orig, rpN, adjN, hB, NN);
    fused_gin<false><<<GRID, 512, SMEM_F>>>(
        hB, (const uint4*)W1F, (const uint4*)W2F, nullptr, nullptr,
        bfb, init_b2, nullptr, hA, nullptr, NN, tilesN);

    // node layer 1 + MLP: agg(hA) -> hC; 4-pass GEMM -> hD
    gather_agg_h<<<gaN, 256>>>(hA, rpN, adjN, hC, NN);
    fused_gin_mlp<<<GRID, 512, SMEM_F>>>(
        hC,
        (const uint4*)(W1F + 8192), (const uint4*)(W2F + 8192),
        (const uint4*)(W1F + 2 * 8192), (const uint4*)(W2F + 2 * 8192),
        bfb + HD, init_b2 + HD, bfb + 2 * HD, mlp_b2, hD, NN, tilesN);

    // edge layer 0: fused pair-lift + agg (hD L2-resident) -> heB; GEMM -> heC
    pair_agg_h<<<gaE, 256>>>(edge_pairs, hD, rpE, adjE, heB, EO);
    fused_gin<false><<<GRID, 512, SMEM_F>>>(
        heB, (const uint4*)(W1F + 3 * 8192), (const uint4*)(W2F + 3 * 8192),
        nullptr, nullptr, bfb + 3 * HD, gin_b2, nullptr, heC, nullptr, EO, tilesE);

    // edge layer 1 + head: agg(heC) -> heA; GEMM+head -> out (f32)
    gather_agg_h<<<gaE, 256>>>(heC, rpE, adjE, heA, EO);
    fused_gin<true><<<GRID, 512, SMEM_F>>>(
        heA, (const uint4*)(W1F + 4 * 8192), (const uint4*)(W2F + 4 * 8192),
        (const uint4*)Wofh, (const uint4*)Wofl,
        bfb + 4 * HD, gin_b2 + HD, out_b, nullptr, out, EO, tilesE);
}